// round 1
// baseline (speedup 1.0000x reference)
#include <cuda_runtime.h>
#include <cuda_bf16.h>
#include <math.h>

#define BB 16
#define NN 512
#define DD 512
#define HH 8
#define DKK 64
#define MM (BB*NN)          // 8192 rows
#define SCALE 0.125f        // 64^-0.5
#define LN_EPS 1e-5f

// ---------------- scratch (device globals; no allocs allowed) ----------------
__device__ float g_h  [MM*DD];
__device__ float g_q  [MM*DD];
__device__ float g_k  [MM*DD];
__device__ float g_v  [MM*DD];
__device__ float g_ctx[MM*DD];
__device__ float g_h2 [MM*DD];

// ---------------- GEMM: C = A[M,K] @ W[K,Nc] + bias (+optional relu) ---------
// 128x128 tile, BK=16, 256 threads, 8x8 per thread.
#define GBM 128
#define GBN 128
#define GBK 16

__global__ __launch_bounds__(256) void gemm_bias_kernel(
    const float* __restrict__ A, const float* __restrict__ W,
    const float* __restrict__ bias, float* __restrict__ C,
    int M, int K, int Nc, int relu)
{
    __shared__ float As[GBK][GBM];
    __shared__ float Ws[GBK][GBN];
    const int tid = threadIdx.x;
    const int ty = tid >> 4;          // 0..15
    const int tx = tid & 15;          // 0..15
    const int rowBase = blockIdx.y * GBM;
    const int colBase = blockIdx.x * GBN;

    float acc[8][8];
#pragma unroll
    for (int i = 0; i < 8; i++)
#pragma unroll
        for (int j = 0; j < 8; j++) acc[i][j] = 0.f;

    for (int k0 = 0; k0 < K; k0 += GBK) {
#pragma unroll
        for (int s = 0; s < 2; s++) {
            int f = tid + s * 256;                 // float4 index, 512 total
            int ar = f >> 2, ak = (f & 3) << 2;    // A tile 128x16
            float4 av = *reinterpret_cast<const float4*>(
                &A[(size_t)(rowBase + ar) * K + k0 + ak]);
            As[ak + 0][ar] = av.x; As[ak + 1][ar] = av.y;
            As[ak + 2][ar] = av.z; As[ak + 3][ar] = av.w;
            int wk = f >> 5, wn = (f & 31) << 2;   // W tile 16x128
            float4 wv = *reinterpret_cast<const float4*>(
                &W[(size_t)(k0 + wk) * Nc + colBase + wn]);
            *reinterpret_cast<float4*>(&Ws[wk][wn]) = wv;
        }
        __syncthreads();
#pragma unroll
        for (int kk = 0; kk < GBK; kk++) {
            float a[8], w[8];
            float4 a0 = *reinterpret_cast<const float4*>(&As[kk][ty * 8]);
            float4 a1 = *reinterpret_cast<const float4*>(&As[kk][ty * 8 + 4]);
            float4 w0 = *reinterpret_cast<const float4*>(&Ws[kk][tx * 8]);
            float4 w1 = *reinterpret_cast<const float4*>(&Ws[kk][tx * 8 + 4]);
            a[0]=a0.x;a[1]=a0.y;a[2]=a0.z;a[3]=a0.w;a[4]=a1.x;a[5]=a1.y;a[6]=a1.z;a[7]=a1.w;
            w[0]=w0.x;w[1]=w0.y;w[2]=w0.z;w[3]=w0.w;w[4]=w1.x;w[5]=w1.y;w[6]=w1.z;w[7]=w1.w;
#pragma unroll
            for (int i = 0; i < 8; i++)
#pragma unroll
                for (int j = 0; j < 8; j++) acc[i][j] += a[i] * w[j];
        }
        __syncthreads();
    }

#pragma unroll
    for (int i = 0; i < 8; i++) {
        int row = rowBase + ty * 8 + i;
#pragma unroll
        for (int jg = 0; jg < 2; jg++) {
            int col = colBase + tx * 8 + jg * 4;
            float4 bv = *reinterpret_cast<const float4*>(&bias[col]);
            float4 o;
            o.x = acc[i][jg * 4 + 0] + bv.x;
            o.y = acc[i][jg * 4 + 1] + bv.y;
            o.z = acc[i][jg * 4 + 2] + bv.z;
            o.w = acc[i][jg * 4 + 3] + bv.w;
            if (relu) {
                o.x = fmaxf(o.x, 0.f); o.y = fmaxf(o.y, 0.f);
                o.z = fmaxf(o.z, 0.f); o.w = fmaxf(o.w, 0.f);
            }
            *reinterpret_cast<float4*>(&C[(size_t)row * Nc + col]) = o;
        }
    }
}

// ---------------- LayerNorm (in place), one block per row -------------------
__global__ __launch_bounds__(256) void ln_kernel(
    float* __restrict__ h, const float* __restrict__ g, const float* __restrict__ b)
{
    const int r = blockIdx.x;
    float* row = h + (size_t)r * DD;
    const int t = threadIdx.x;
    float v0 = row[t], v1 = row[t + 256];

    __shared__ float red[8];
    __shared__ float s_mu, s_rs;
    float s = v0 + v1;
#pragma unroll
    for (int o = 16; o; o >>= 1) s += __shfl_xor_sync(0xffffffffu, s, o);
    if ((t & 31) == 0) red[t >> 5] = s;
    __syncthreads();
    if (t == 0) {
        float tot = 0.f;
#pragma unroll
        for (int i = 0; i < 8; i++) tot += red[i];
        s_mu = tot * (1.f / DD);
    }
    __syncthreads();
    const float mu = s_mu;
    float d0 = v0 - mu, d1 = v1 - mu;
    float s2 = d0 * d0 + d1 * d1;
#pragma unroll
    for (int o = 16; o; o >>= 1) s2 += __shfl_xor_sync(0xffffffffu, s2, o);
    if ((t & 31) == 0) red[t >> 5] = s2;
    __syncthreads();
    if (t == 0) {
        float tot = 0.f;
#pragma unroll
        for (int i = 0; i < 8; i++) tot += red[i];
        s_rs = rsqrtf(tot * (1.f / DD) + LN_EPS);
    }
    __syncthreads();
    const float rs = s_rs;
    row[t]       = d0 * rs * g[t]       + b[t];
    row[t + 256] = d1 * rs * g[t + 256] + b[t + 256];
}

// ---------------- Attention: flash-style, 64 q-rows per block ---------------
// Mask semantics of the reference: masked scores become 0.0 (NOT -inf).
// grid = (N/64, B*H), block = 256. Dynamic smem.
#define ATT_SMEM_FLOATS (64*64 + 64*65 + 64*65 + 3*64)
#define ATT_SMEM_BYTES  (ATT_SMEM_FLOATS * 4)

__global__ __launch_bounds__(256) void attn_kernel(
    const float* __restrict__ q, const float* __restrict__ k,
    const float* __restrict__ v, const float* __restrict__ adj,
    const int* __restrict__ use_adj_p, float* __restrict__ ctx)
{
    extern __shared__ float sm[];
    float* Qs  = sm;                       // [64][64]
    float* KVs = Qs + 64 * 64;             // [64][65]  (K, then V)
    float* Ss  = KVs + 64 * 65;            // [64][65]
    float* m_s = Ss + 64 * 65;             // [64]
    float* l_s = m_s + 64;                 // [64]
    float* c_s = l_s + 64;                 // [64]

    const int tid = threadIdx.x;
    const int ty = tid >> 4, tx = tid & 15;
    const int bh = blockIdx.y;
    const int b = bh >> 3, hh = bh & 7;
    const int q0 = blockIdx.x * 64;
    const int use_adj = (*use_adj_p) != 0;

    // load Q tile (pre-scaled)
    const size_t qbase = ((size_t)b * NN + q0) * DD + hh * DKK;
#pragma unroll
    for (int s = 0; s < 4; s++) {
        int f = tid + s * 256;             // 1024 float4
        int r = f >> 4, dq = (f & 15) << 2;
        float4 t4 = *reinterpret_cast<const float4*>(&q[qbase + (size_t)r * DD + dq]);
        Qs[r * 64 + dq + 0] = t4.x * SCALE;
        Qs[r * 64 + dq + 1] = t4.y * SCALE;
        Qs[r * 64 + dq + 2] = t4.z * SCALE;
        Qs[r * 64 + dq + 3] = t4.w * SCALE;
    }
    if (tid < 64) { m_s[tid] = -1e30f; l_s[tid] = 0.f; }

    float oacc[4][4];
#pragma unroll
    for (int i = 0; i < 4; i++)
#pragma unroll
        for (int j = 0; j < 4; j++) oacc[i][j] = 0.f;

    for (int ck = 0; ck < NN / 64; ck++) {
        const int k0c = ck * 64;
        // ---- load K chunk into KVs[r][d] (pitch 65)
        const size_t kbase = ((size_t)b * NN + k0c) * DD + hh * DKK;
#pragma unroll
        for (int s = 0; s < 4; s++) {
            int f = tid + s * 256;
            int r = f >> 4, dq = (f & 15) << 2;
            float4 t4 = *reinterpret_cast<const float4*>(&k[kbase + (size_t)r * DD + dq]);
            KVs[r * 65 + dq + 0] = t4.x; KVs[r * 65 + dq + 1] = t4.y;
            KVs[r * 65 + dq + 2] = t4.z; KVs[r * 65 + dq + 3] = t4.w;
        }
        __syncthreads();

        // ---- S = Q @ K^T (each thread 4x4)
        float sacc[4][4];
#pragma unroll
        for (int i = 0; i < 4; i++)
#pragma unroll
            for (int j = 0; j < 4; j++) sacc[i][j] = 0.f;
#pragma unroll 8
        for (int d = 0; d < 64; d++) {
            float qa[4], kb[4];
#pragma unroll
            for (int i = 0; i < 4; i++) qa[i] = Qs[(ty * 4 + i) * 64 + d];
#pragma unroll
            for (int j = 0; j < 4; j++) kb[j] = KVs[(tx * 4 + j) * 65 + d];
#pragma unroll
            for (int i = 0; i < 4; i++)
#pragma unroll
                for (int j = 0; j < 4; j++) sacc[i][j] += qa[i] * kb[j];
        }
        // ---- mask (masked -> 0.0, reference semantics) + store to Ss
        if (use_adj) {
#pragma unroll
            for (int i = 0; i < 4; i++) {
                int qg = q0 + ty * 4 + i;
                float4 a4 = *reinterpret_cast<const float4*>(
                    &adj[((size_t)b * NN + qg) * NN + k0c + tx * 4]);
                sacc[i][0] = (a4.x > 0.f) ? sacc[i][0] : 0.f;
                sacc[i][1] = (a4.y > 0.f) ? sacc[i][1] : 0.f;
                sacc[i][2] = (a4.z > 0.f) ? sacc[i][2] : 0.f;
                sacc[i][3] = (a4.w > 0.f) ? sacc[i][3] : 0.f;
            }
        }
#pragma unroll
        for (int i = 0; i < 4; i++)
#pragma unroll
            for (int j = 0; j < 4; j++)
                Ss[(ty * 4 + i) * 65 + tx * 4 + j] = sacc[i][j];
        __syncthreads();   // Ks free from here

        // ---- load V chunk into KVs (overlaps with softmax below)
        const size_t vbase = ((size_t)b * NN + k0c) * DD + hh * DKK;
#pragma unroll
        for (int s = 0; s < 4; s++) {
            int f = tid + s * 256;
            int r = f >> 4, dq = (f & 15) << 2;
            float4 t4 = *reinterpret_cast<const float4*>(&v[vbase + (size_t)r * DD + dq]);
            KVs[r * 65 + dq + 0] = t4.x; KVs[r * 65 + dq + 1] = t4.y;
            KVs[r * 65 + dq + 2] = t4.z; KVs[r * 65 + dq + 3] = t4.w;
        }

        // ---- online softmax: 4 threads per row
        {
            const int r = tid >> 2, sub = tid & 3;
            float mo = m_s[r];
            float cm = -1e30f;
#pragma unroll
            for (int t = 0; t < 16; t++) cm = fmaxf(cm, Ss[r * 65 + sub + t * 4]);
            cm = fmaxf(cm, __shfl_xor_sync(0xffffffffu, cm, 1));
            cm = fmaxf(cm, __shfl_xor_sync(0xffffffffu, cm, 2));
            float mn = fmaxf(mo, cm);
            float cs = 0.f;
#pragma unroll
            for (int t = 0; t < 16; t++) {
                int c = sub + t * 4;
                float p = __expf(Ss[r * 65 + c] - mn);
                Ss[r * 65 + c] = p;
                cs += p;
            }
            cs += __shfl_xor_sync(0xffffffffu, cs, 1);
            cs += __shfl_xor_sync(0xffffffffu, cs, 2);
            if (sub == 0) {
                float sc = __expf(mo - mn);
                c_s[r] = sc;
                l_s[r] = l_s[r] * sc + cs;
                m_s[r] = mn;
            }
        }
        __syncthreads();

        // ---- rescale O, then O += P @ V
#pragma unroll
        for (int i = 0; i < 4; i++) {
            float sc = c_s[ty * 4 + i];
#pragma unroll
            for (int j = 0; j < 4; j++) oacc[i][j] *= sc;
        }
#pragma unroll 8
        for (int kk = 0; kk < 64; kk++) {
            float pa[4];
#pragma unroll
            for (int i = 0; i < 4; i++) pa[i] = Ss[(ty * 4 + i) * 65 + kk];
            float vb0 = KVs[kk * 65 + tx * 4 + 0];
            float vb1 = KVs[kk * 65 + tx * 4 + 1];
            float vb2 = KVs[kk * 65 + tx * 4 + 2];
            float vb3 = KVs[kk * 65 + tx * 4 + 3];
#pragma unroll
            for (int i = 0; i < 4; i++) {
                oacc[i][0] += pa[i] * vb0;
                oacc[i][1] += pa[i] * vb1;
                oacc[i][2] += pa[i] * vb2;
                oacc[i][3] += pa[i] * vb3;
            }
        }
        __syncthreads();
    }

    // ---- epilogue: normalize + write ctx
#pragma unroll
    for (int i = 0; i < 4; i++) {
        int r = ty * 4 + i;
        float inv = 1.f / l_s[r];
        float4 o;
        o.x = oacc[i][0] * inv; o.y = oacc[i][1] * inv;
        o.z = oacc[i][2] * inv; o.w = oacc[i][3] * inv;
        *reinterpret_cast<float4*>(
            &ctx[((size_t)b * NN + q0 + r) * DD + hh * DKK + tx * 4]) = o;
    }
}

// ---------------- gate + residual mix, one block per row --------------------
__global__ __launch_bounds__(256) void gate_kernel(
    const float* __restrict__ x, const float* __restrict__ h2,
    const float* __restrict__ gw, const float* __restrict__ gb,
    float* __restrict__ out)
{
    const int r = blockIdx.x;
    const size_t base = (size_t)r * DD;
    const int t = threadIdx.x;
    float x0 = x[base + t], x1 = x[base + t + 256];
    float h0 = h2[base + t], h1 = h2[base + t + 256];
    float s = x0 * gw[t] + x1 * gw[t + 256] + h0 * gw[512 + t] + h1 * gw[768 + t];

    __shared__ float red[8];
    __shared__ float s_c;
#pragma unroll
    for (int o = 16; o; o >>= 1) s += __shfl_xor_sync(0xffffffffu, s, o);
    if ((t & 31) == 0) red[t >> 5] = s;
    __syncthreads();
    if (t == 0) {
        float tot = 0.f;
#pragma unroll
        for (int i = 0; i < 8; i++) tot += red[i];
        s_c = 1.f / (1.f + expf(-(tot + gb[0])));
    }
    __syncthreads();
    const float c = s_c;
    out[base + t]       = c * x0 + (1.f - c) * h0;
    out[base + t + 256] = c * x1 + (1.f - c) * h1;
}

// ---------------- launch ----------------------------------------------------
extern "C" void kernel_launch(void* const* d_in, const int* in_sizes, int n_in,
                              void* d_out, int out_size)
{
    const float* x    = (const float*)d_in[0];
    const float* adj  = (const float*)d_in[1];
    const float* W_w  = (const float*)d_in[2];
    const float* W_b  = (const float*)d_in[3];
    const float* ln_g = (const float*)d_in[4];
    const float* ln_b = (const float*)d_in[5];
    const float* Wq   = (const float*)d_in[6];
    const float* bq   = (const float*)d_in[7];
    const float* Wk   = (const float*)d_in[8];
    const float* bk   = (const float*)d_in[9];
    const float* Wv   = (const float*)d_in[10];
    const float* bv   = (const float*)d_in[11];
    const float* Wo   = (const float*)d_in[12];
    const float* bo   = (const float*)d_in[13];
    const float* gw   = (const float*)d_in[14];
    const float* gb   = (const float*)d_in[15];
    const int*   uadj = (const int*)d_in[16];
    float* out = (float*)d_out;

    float *h, *q, *k, *v, *ctx, *h2;
    cudaGetSymbolAddress((void**)&h,   g_h);
    cudaGetSymbolAddress((void**)&q,   g_q);
    cudaGetSymbolAddress((void**)&k,   g_k);
    cudaGetSymbolAddress((void**)&v,   g_v);
    cudaGetSymbolAddress((void**)&ctx, g_ctx);
    cudaGetSymbolAddress((void**)&h2,  g_h2);

    cudaFuncSetAttribute(attn_kernel,
                         cudaFuncAttributeMaxDynamicSharedMemorySize, ATT_SMEM_BYTES);

    dim3 gB(DD / GBN, MM / GBM);   // (4, 64)
    gemm_bias_kernel<<<gB, 256>>>(x, W_w, W_b, h, MM, DD, DD, 0);
    ln_kernel<<<MM, 256>>>(h, ln_g, ln_b);
    gemm_bias_kernel<<<gB, 256>>>(h, Wq, bq, q, MM, DD, DD, 0);
    gemm_bias_kernel<<<gB, 256>>>(h, Wk, bk, k, MM, DD, DD, 0);
    gemm_bias_kernel<<<gB, 256>>>(h, Wv, bv, v, MM, DD, DD, 0);
    attn_kernel<<<dim3(NN / 64, BB * HH), 256, ATT_SMEM_BYTES>>>(q, k, v, adj, uadj, ctx);
    gemm_bias_kernel<<<gB, 256>>>(ctx, Wo, bo, h2, MM, DD, DD, 1);
    gate_kernel<<<MM, 256>>>(x, h2, gw, gb, out);
}

// round 3
// speedup vs baseline: 1.4041x; 1.4041x over previous
#include <cuda_runtime.h>
#include <cuda_bf16.h>
#include <cstdint>
#include <math.h>

#define BB 16
#define NN 512
#define DD 512
#define HH 8
#define DKK 64
#define MM (BB*NN)          // 8192 rows
#define SCALE 0.125f
#define LN_EPS 1e-5f

// ---------------- scratch (device globals; no allocs allowed) ----------------
__device__ float g_h [MM*DD];
__device__ float g_q [MM*DD];
__device__ float g_k [MM*DD];
__device__ float g_v [MM*DD];
__device__ float g_h2[MM*DD];
__device__ __nv_bfloat16 g_xh[MM*DD], g_xl[MM*DD];   // x split
__device__ __nv_bfloat16 g_hh[MM*DD], g_hl[MM*DD];   // LN(h) split
__device__ __nv_bfloat16 g_ch[MM*DD], g_cl[MM*DD];   // ctx split
__device__ __nv_bfloat16 g_wth[5*DD*DD], g_wtl[5*DD*DD];  // transposed weights split

__device__ __forceinline__ uint32_t smem_u32(const void* p) {
    uint32_t a;
    asm("{ .reg .u64 t; cvta.to.shared.u64 t, %1; cvt.u32.u64 %0, t; }"
        : "=r"(a) : "l"(p));
    return a;
}

// =================== mma.sync bf16-split GEMM ===============================
// C[8192,512] = A @ Wt^T + bias (opt relu).
// A bf16 hi/lo [M,K] row-major; W transposed bf16 hi/lo [N,K] (K-major).
// CTA tile 128(M) x 64(N), 4 warps (warp tile 64x32), K chunks of 32,
// cp.async double buffer, ldmatrix fragment loads, pitch 40 bf16 (80B).
#define PITCHB 80                    // bytes per smem row
#define OFF_AL 10240                 // 128*80
#define OFF_BH 20480
#define OFF_BL 25600                 // 20480 + 64*80
#define BUFSZ  30720
#define GEMM_SMEM (2*BUFSZ)          // 61440

#define MMA_OP(acc, A, B) asm volatile(                                        \
    "mma.sync.aligned.m16n8k16.row.col.f32.bf16.bf16.f32 "                     \
    "{%0,%1,%2,%3}, {%4,%5,%6,%7}, {%8,%9}, {%0,%1,%2,%3};"                    \
    : "+f"((acc)[0]), "+f"((acc)[1]), "+f"((acc)[2]), "+f"((acc)[3])           \
    : "r"((A)[0]), "r"((A)[1]), "r"((A)[2]), "r"((A)[3]),                      \
      "r"((B)[0]), "r"((B)[1]))

#define LDSM4(r0, r1, r2, r3, ad) asm volatile(                                \
    "ldmatrix.sync.aligned.m8n8.x4.shared.b16 {%0,%1,%2,%3}, [%4];"            \
    : "=r"(r0), "=r"(r1), "=r"(r2), "=r"(r3) : "r"(ad))

__global__ __launch_bounds__(128) void mma_gemm(
    const __nv_bfloat16* __restrict__ Ah, const __nv_bfloat16* __restrict__ Al,
    const __nv_bfloat16* __restrict__ Bh, const __nv_bfloat16* __restrict__ Bl,
    const float* __restrict__ bias, float* __restrict__ C, int relu)
{
    extern __shared__ char smx[];
    const uint32_t sbase = smem_u32(smx);
    const int tid = threadIdx.x, wid = tid >> 5, lane = tid & 31;
    const int rowBase = blockIdx.y * 128, nBase = blockIdx.x * 64;
    const int warpM = wid & 1, warpN = wid >> 1;    // 2 x 2

    float acc[4][4][4];
#pragma unroll
    for (int i = 0; i < 4; i++)
#pragma unroll
        for (int j = 0; j < 4; j++)
#pragma unroll
            for (int e = 0; e < 4; e++) acc[i][j][e] = 0.f;

    // ---- async chunk loader: 1536 x 16B segments
    auto issue_load = [&](int c, int buf) {
        const int kc = c * 32;
#pragma unroll
        for (int s = 0; s < 12; s++) {
            int sid = tid + s * 128;      // 0..1535
            const __nv_bfloat16* g;
            int t, r, off;
            if (sid < 512)       { g = Ah; t = sid;        off = 0; }
            else if (sid < 1024) { g = Al; t = sid - 512;  off = OFF_AL; }
            else if (sid < 1280) { g = Bh; t = sid - 1024; off = OFF_BH; }
            else                 { g = Bl; t = sid - 1280; off = OFF_BL; }
            r = t >> 2;
            int seg = t & 3;
            int grow = (off < OFF_BH) ? (rowBase + r) : (nBase + r);
            uint32_t da = sbase + buf * BUFSZ + off + r * PITCHB + seg * 16;
            const char* gp = (const char*)(g + (size_t)grow * 512 + kc) + seg * 16;
            asm volatile("cp.async.cg.shared.global [%0], [%1], 16;"
                         :: "r"(da), "l"(gp) : "memory");
        }
        asm volatile("cp.async.commit_group;" ::: "memory");
    };

    issue_load(0, 0);
    for (int c = 0; c < 16; c++) {
        const int buf = c & 1;
        if (c < 15) issue_load(c + 1, buf ^ 1);
        if (c < 15) asm volatile("cp.async.wait_group 1;" ::: "memory");
        else        asm volatile("cp.async.wait_group 0;" ::: "memory");
        __syncthreads();

        const uint32_t bufb = sbase + buf * BUFSZ;
        const int rq = lane & 7, grp = lane >> 3;
        const int mrow = ((grp & 1) << 3) + rq;
#pragma unroll
        for (int ks = 0; ks < 2; ks++) {
            const int kof2 = (ks * 16 + ((grp >> 1) << 3)) * 2;   // byte offset
            uint32_t ah[4][4], bh_[4][2];
            // A hi fragments
#pragma unroll
            for (int i = 0; i < 4; i++) {
                uint32_t ad = bufb + (uint32_t)(warpM * 64 + i * 16 + mrow) * PITCHB + kof2;
                LDSM4(ah[i][0], ah[i][1], ah[i][2], ah[i][3], ad);
            }
            // B hi fragments (x4 covers two n8 tiles)
#pragma unroll
            for (int jj = 0; jj < 2; jj++) {
                uint32_t ad = bufb + OFF_BH +
                    (uint32_t)(warpN * 32 + jj * 16 + ((grp & 1) << 3) + rq) * PITCHB + kof2;
                uint32_t r0, r1, r2, r3;
                LDSM4(r0, r1, r2, r3, ad);
                bh_[2 * jj][0] = r0; bh_[2 * jj + 1][0] = r1;
                bh_[2 * jj][1] = r2; bh_[2 * jj + 1][1] = r3;
            }
#pragma unroll
            for (int i = 0; i < 4; i++)
#pragma unroll
                for (int j = 0; j < 4; j++) MMA_OP(acc[i][j], ah[i], bh_[j]);

            // A lo * B hi
            {
                uint32_t al_[4];
#pragma unroll
                for (int i = 0; i < 4; i++) {
                    uint32_t ad = bufb + OFF_AL +
                        (uint32_t)(warpM * 64 + i * 16 + mrow) * PITCHB + kof2;
                    LDSM4(al_[0], al_[1], al_[2], al_[3], ad);
#pragma unroll
                    for (int j = 0; j < 4; j++) MMA_OP(acc[i][j], al_, bh_[j]);
                }
            }
            // A hi * B lo
            {
                uint32_t bl_[4][2];
#pragma unroll
                for (int jj = 0; jj < 2; jj++) {
                    uint32_t ad = bufb + OFF_BL +
                        (uint32_t)(warpN * 32 + jj * 16 + ((grp & 1) << 3) + rq) * PITCHB + kof2;
                    uint32_t r0, r1, r2, r3;
                    LDSM4(r0, r1, r2, r3, ad);
                    bl_[2 * jj][0] = r0; bl_[2 * jj + 1][0] = r1;
                    bl_[2 * jj][1] = r2; bl_[2 * jj + 1][1] = r3;
                }
#pragma unroll
                for (int i = 0; i < 4; i++)
#pragma unroll
                    for (int j = 0; j < 4; j++) MMA_OP(acc[i][j], ah[i], bl_[j]);
            }
        }
        __syncthreads();
    }

    // ---- epilogue
#pragma unroll
    for (int i = 0; i < 4; i++) {
#pragma unroll
        for (int j = 0; j < 4; j++) {
            int gr = rowBase + warpM * 64 + i * 16 + (lane >> 2);
            int gc = nBase + warpN * 32 + j * 8 + (lane & 3) * 2;
            float2 b2 = *(const float2*)&bias[gc];
            float v0 = acc[i][j][0] + b2.x, v1 = acc[i][j][1] + b2.y;
            float v2 = acc[i][j][2] + b2.x, v3 = acc[i][j][3] + b2.y;
            if (relu) {
                v0 = fmaxf(v0, 0.f); v1 = fmaxf(v1, 0.f);
                v2 = fmaxf(v2, 0.f); v3 = fmaxf(v3, 0.f);
            }
            float2 o0; o0.x = v0; o0.y = v1;
            float2 o1; o1.x = v2; o1.y = v3;
            *(float2*)&C[(size_t)gr * DD + gc]       = o0;
            *(float2*)&C[(size_t)(gr + 8) * DD + gc] = o1;
        }
    }
}

// ---------------- fp32 -> (hi,lo) bf16 split --------------------------------
__global__ __launch_bounds__(256) void conv_split(
    const float4* __restrict__ in, __nv_bfloat162* __restrict__ hi,
    __nv_bfloat162* __restrict__ lo, int n4)
{
    int i = blockIdx.x * 256 + threadIdx.x;
    if (i >= n4) return;
    float4 v = in[i];
    __nv_bfloat16 h0 = __float2bfloat16(v.x), h1 = __float2bfloat16(v.y);
    __nv_bfloat16 h2 = __float2bfloat16(v.z), h3 = __float2bfloat16(v.w);
    __nv_bfloat162 a, b, c, d;
    a.x = h0; a.y = h1; b.x = h2; b.y = h3;
    c.x = __float2bfloat16(v.x - __bfloat162float(h0));
    c.y = __float2bfloat16(v.y - __bfloat162float(h1));
    d.x = __float2bfloat16(v.z - __bfloat162float(h2));
    d.y = __float2bfloat16(v.w - __bfloat162float(h3));
    hi[2 * i] = a; hi[2 * i + 1] = b;
    lo[2 * i] = c; lo[2 * i + 1] = d;
}

// ---------------- weight transpose + split: W[K,N] -> Wt[N,K] hi/lo ---------
__global__ __launch_bounds__(256) void wtrans(
    const float* __restrict__ W, __nv_bfloat16* __restrict__ th,
    __nv_bfloat16* __restrict__ tl)
{
    __shared__ float t[32][33];
    const int k0 = blockIdx.y * 32, n0 = blockIdx.x * 32;
    const int tx = threadIdx.x & 31, ty = threadIdx.x >> 5;   // 32 x 8
#pragma unroll
    for (int i = 0; i < 32; i += 8)
        t[ty + i][tx] = W[(size_t)(k0 + ty + i) * DD + n0 + tx];
    __syncthreads();
#pragma unroll
    for (int i = 0; i < 32; i += 8) {
        float v = t[tx][ty + i];                  // = W[k0+tx][n0+ty+i]
        __nv_bfloat16 h = __float2bfloat16(v);
        __nv_bfloat16 l = __float2bfloat16(v - __bfloat162float(h));
        size_t o = (size_t)(n0 + ty + i) * DD + k0 + tx;
        th[o] = h; tl[o] = l;
    }
}

// ---------------- LayerNorm -> bf16 hi/lo -----------------------------------
__global__ __launch_bounds__(256) void ln2_kernel(
    const float* __restrict__ h, const float* __restrict__ g, const float* __restrict__ b,
    __nv_bfloat16* __restrict__ hh, __nv_bfloat16* __restrict__ hl)
{
    const int r = blockIdx.x;
    const float* row = h + (size_t)r * DD;
    const int t = threadIdx.x;
    float v0 = row[t], v1 = row[t + 256];

    __shared__ float red[8];
    __shared__ float s_mu, s_rs;
    float s = v0 + v1;
#pragma unroll
    for (int o = 16; o; o >>= 1) s += __shfl_xor_sync(0xffffffffu, s, o);
    if ((t & 31) == 0) red[t >> 5] = s;
    __syncthreads();
    if (t == 0) {
        float tot = 0.f;
#pragma unroll
        for (int i = 0; i < 8; i++) tot += red[i];
        s_mu = tot * (1.f / DD);
    }
    __syncthreads();
    const float mu = s_mu;
    float d0 = v0 - mu, d1 = v1 - mu;
    float s2 = d0 * d0 + d1 * d1;
#pragma unroll
    for (int o = 16; o; o >>= 1) s2 += __shfl_xor_sync(0xffffffffu, s2, o);
    if ((t & 31) == 0) red[t >> 5] = s2;
    __syncthreads();
    if (t == 0) {
        float tot = 0.f;
#pragma unroll
        for (int i = 0; i < 8; i++) tot += red[i];
        s_rs = rsqrtf(tot * (1.f / DD) + LN_EPS);
    }
    __syncthreads();
    const float rs = s_rs;
    float y0 = d0 * rs * g[t] + b[t];
    float y1 = d1 * rs * g[t + 256] + b[t + 256];
    size_t base = (size_t)r * DD;
    __nv_bfloat16 a0 = __float2bfloat16(y0);
    __nv_bfloat16 a1 = __float2bfloat16(y1);
    hh[base + t] = a0;       hl[base + t] = __float2bfloat16(y0 - __bfloat162float(a0));
    hh[base + t + 256] = a1; hl[base + t + 256] = __float2bfloat16(y1 - __bfloat162float(a1));
}

// ---------------- Attention (fp32 SIMT), epilogue writes bf16 hi/lo ---------
#define ATT_SMEM_FLOATS (64*64 + 64*65 + 64*65 + 3*64)
#define ATT_SMEM_BYTES  (ATT_SMEM_FLOATS * 4)

__global__ __launch_bounds__(256) void attn_kernel(
    const float* __restrict__ q, const float* __restrict__ k,
    const float* __restrict__ v, const float* __restrict__ adj,
    const int* __restrict__ use_adj_p,
    __nv_bfloat16* __restrict__ ch, __nv_bfloat16* __restrict__ cl)
{
    extern __shared__ float sm[];
    float* Qs  = sm;
    float* KVs = Qs + 64 * 64;
    float* Ss  = KVs + 64 * 65;
    float* m_s = Ss + 64 * 65;
    float* l_s = m_s + 64;
    float* c_s = l_s + 64;

    const int tid = threadIdx.x;
    const int ty = tid >> 4, tx = tid & 15;
    const int bh = blockIdx.y;
    const int b = bh >> 3, hd = bh & 7;
    const int q0 = blockIdx.x * 64;
    const int use_adj = (*use_adj_p) != 0;

    const size_t qbase = ((size_t)b * NN + q0) * DD + hd * DKK;
#pragma unroll
    for (int s = 0; s < 4; s++) {
        int f = tid + s * 256;
        int r = f >> 4, dq = (f & 15) << 2;
        float4 t4 = *reinterpret_cast<const float4*>(&q[qbase + (size_t)r * DD + dq]);
        Qs[r * 64 + dq + 0] = t4.x * SCALE;
        Qs[r * 64 + dq + 1] = t4.y * SCALE;
        Qs[r * 64 + dq + 2] = t4.z * SCALE;
        Qs[r * 64 + dq + 3] = t4.w * SCALE;
    }
    if (tid < 64) { m_s[tid] = -1e30f; l_s[tid] = 0.f; }

    float oacc[4][4];
#pragma unroll
    for (int i = 0; i < 4; i++)
#pragma unroll
        for (int j = 0; j < 4; j++) oacc[i][j] = 0.f;

    for (int ck = 0; ck < NN / 64; ck++) {
        const int k0c = ck * 64;
        const size_t kbase = ((size_t)b * NN + k0c) * DD + hd * DKK;
#pragma unroll
        for (int s = 0; s < 4; s++) {
            int f = tid + s * 256;
            int r = f >> 4, dq = (f & 15) << 2;
            float4 t4 = *reinterpret_cast<const float4*>(&k[kbase + (size_t)r * DD + dq]);
            KVs[r * 65 + dq + 0] = t4.x; KVs[r * 65 + dq + 1] = t4.y;
            KVs[r * 65 + dq + 2] = t4.z; KVs[r * 65 + dq + 3] = t4.w;
        }
        __syncthreads();

        float sacc[4][4];
#pragma unroll
        for (int i = 0; i < 4; i++)
#pragma unroll
            for (int j = 0; j < 4; j++) sacc[i][j] = 0.f;
#pragma unroll 8
        for (int d = 0; d < 64; d++) {
            float qa[4], kb[4];
#pragma unroll
            for (int i = 0; i < 4; i++) qa[i] = Qs[(ty * 4 + i) * 64 + d];
#pragma unroll
            for (int j = 0; j < 4; j++) kb[j] = KVs[(tx * 4 + j) * 65 + d];
#pragma unroll
            for (int i = 0; i < 4; i++)
#pragma unroll
                for (int j = 0; j < 4; j++) sacc[i][j] += qa[i] * kb[j];
        }
        if (use_adj) {
#pragma unroll
            for (int i = 0; i < 4; i++) {
                int qg = q0 + ty * 4 + i;
                float4 a4 = *reinterpret_cast<const float4*>(
                    &adj[((size_t)b * NN + qg) * NN + k0c + tx * 4]);
                sacc[i][0] = (a4.x > 0.f) ? sacc[i][0] : 0.f;
                sacc[i][1] = (a4.y > 0.f) ? sacc[i][1] : 0.f;
                sacc[i][2] = (a4.z > 0.f) ? sacc[i][2] : 0.f;
                sacc[i][3] = (a4.w > 0.f) ? sacc[i][3] : 0.f;
            }
        }
#pragma unroll
        for (int i = 0; i < 4; i++)
#pragma unroll
            for (int j = 0; j < 4; j++)
                Ss[(ty * 4 + i) * 65 + tx * 4 + j] = sacc[i][j];
        __syncthreads();

        const size_t vbase = ((size_t)b * NN + k0c) * DD + hd * DKK;
#pragma unroll
        for (int s = 0; s < 4; s++) {
            int f = tid + s * 256;
            int r = f >> 4, dq = (f & 15) << 2;
            float4 t4 = *reinterpret_cast<const float4*>(&v[vbase + (size_t)r * DD + dq]);
            KVs[r * 65 + dq + 0] = t4.x; KVs[r * 65 + dq + 1] = t4.y;
            KVs[r * 65 + dq + 2] = t4.z; KVs[r * 65 + dq + 3] = t4.w;
        }

        {
            const int r = tid >> 2, sub = tid & 3;
            float mo = m_s[r];
            float cm = -1e30f;
#pragma unroll
            for (int t = 0; t < 16; t++) cm = fmaxf(cm, Ss[r * 65 + sub + t * 4]);
            cm = fmaxf(cm, __shfl_xor_sync(0xffffffffu, cm, 1));
            cm = fmaxf(cm, __shfl_xor_sync(0xffffffffu, cm, 2));
            float mn = fmaxf(mo, cm);
            float cs = 0.f;
#pragma unroll
            for (int t = 0; t < 16; t++) {
                int c = sub + t * 4;
                float p = __expf(Ss[r * 65 + c] - mn);
                Ss[r * 65 + c] = p;
                cs += p;
            }
            cs += __shfl_xor_sync(0xffffffffu, cs, 1);
            cs += __shfl_xor_sync(0xffffffffu, cs, 2);
            if (sub == 0) {
                float sc = __expf(mo - mn);
                c_s[r] = sc;
                l_s[r] = l_s[r] * sc + cs;
                m_s[r] = mn;
            }
        }
        __syncthreads();

#pragma unroll
        for (int i = 0; i < 4; i++) {
            float sc = c_s[ty * 4 + i];
#pragma unroll
            for (int j = 0; j < 4; j++) oacc[i][j] *= sc;
        }
#pragma unroll 8
        for (int kk = 0; kk < 64; kk++) {
            float pa[4];
#pragma unroll
            for (int i = 0; i < 4; i++) pa[i] = Ss[(ty * 4 + i) * 65 + kk];
            float vb0 = KVs[kk * 65 + tx * 4 + 0];
            float vb1 = KVs[kk * 65 + tx * 4 + 1];
            float vb2 = KVs[kk * 65 + tx * 4 + 2];
            float vb3 = KVs[kk * 65 + tx * 4 + 3];
#pragma unroll
            for (int i = 0; i < 4; i++) {
                oacc[i][0] += pa[i] * vb0;
                oacc[i][1] += pa[i] * vb1;
                oacc[i][2] += pa[i] * vb2;
                oacc[i][3] += pa[i] * vb3;
            }
        }
        __syncthreads();
    }

#pragma unroll
    for (int i = 0; i < 4; i++) {
        int r = ty * 4 + i;
        float inv = 1.f / l_s[r];
        float vv[4];
        vv[0] = oacc[i][0] * inv; vv[1] = oacc[i][1] * inv;
        vv[2] = oacc[i][2] * inv; vv[3] = oacc[i][3] * inv;
        size_t base = ((size_t)b * NN + q0 + r) * DD + hd * DKK + tx * 4;
        __nv_bfloat162 hp0, hp1, lp0, lp1;
        __nv_bfloat16 t0 = __float2bfloat16(vv[0]);
        __nv_bfloat16 t1 = __float2bfloat16(vv[1]);
        __nv_bfloat16 t2 = __float2bfloat16(vv[2]);
        __nv_bfloat16 t3 = __float2bfloat16(vv[3]);
        hp0.x = t0; hp0.y = t1; hp1.x = t2; hp1.y = t3;
        lp0.x = __float2bfloat16(vv[0] - __bfloat162float(t0));
        lp0.y = __float2bfloat16(vv[1] - __bfloat162float(t1));
        lp1.x = __float2bfloat16(vv[2] - __bfloat162float(t2));
        lp1.y = __float2bfloat16(vv[3] - __bfloat162float(t3));
        *(__nv_bfloat162*)&ch[base]     = hp0;
        *(__nv_bfloat162*)&ch[base + 2] = hp1;
        *(__nv_bfloat162*)&cl[base]     = lp0;
        *(__nv_bfloat162*)&cl[base + 2] = lp1;
    }
}

// ---------------- gate + residual mix ---------------------------------------
__global__ __launch_bounds__(256) void gate_kernel(
    const float* __restrict__ x, const float* __restrict__ h2,
    const float* __restrict__ gw, const float* __restrict__ gb,
    float* __restrict__ out)
{
    const int r = blockIdx.x;
    const size_t base = (size_t)r * DD;
    const int t = threadIdx.x;
    float x0 = x[base + t], x1 = x[base + t + 256];
    float h0 = h2[base + t], h1 = h2[base + t + 256];
    float s = x0 * gw[t] + x1 * gw[t + 256] + h0 * gw[512 + t] + h1 * gw[768 + t];

    __shared__ float red[8];
    __shared__ float s_c;
#pragma unroll
    for (int o = 16; o; o >>= 1) s += __shfl_xor_sync(0xffffffffu, s, o);
    if ((t & 31) == 0) red[t >> 5] = s;
    __syncthreads();
    if (t == 0) {
        float tot = 0.f;
#pragma unroll
        for (int i = 0; i < 8; i++) tot += red[i];
        s_c = 1.f / (1.f + expf(-(tot + gb[0])));
    }
    __syncthreads();
    const float c = s_c;
    out[base + t]       = c * x0 + (1.f - c) * h0;
    out[base + t + 256] = c * x1 + (1.f - c) * h1;
}

// ---------------- launch ----------------------------------------------------
extern "C" void kernel_launch(void* const* d_in, const int* in_sizes, int n_in,
                              void* d_out, int out_size)
{
    const float* x    = (const float*)d_in[0];
    const float* adj  = (const float*)d_in[1];
    const float* W_w  = (const float*)d_in[2];
    const float* W_b  = (const float*)d_in[3];
    const float* ln_g = (const float*)d_in[4];
    const float* ln_b = (const float*)d_in[5];
    const float* Wq   = (const float*)d_in[6];
    const float* bq   = (const float*)d_in[7];
    const float* Wk   = (const float*)d_in[8];
    const float* bk   = (const float*)d_in[9];
    const float* Wv   = (const float*)d_in[10];
    const float* bv   = (const float*)d_in[11];
    const float* Wo   = (const float*)d_in[12];
    const float* bo   = (const float*)d_in[13];
    const float* gw   = (const float*)d_in[14];
    const float* gb   = (const float*)d_in[15];
    const int*   uadj = (const int*)d_in[16];
    float* out = (float*)d_out;

    float *h, *q, *k, *v, *h2;
    __nv_bfloat16 *xh, *xl, *hh, *hl, *ch, *cl, *wth, *wtl;
    cudaGetSymbolAddress((void**)&h,  g_h);
    cudaGetSymbolAddress((void**)&q,  g_q);
    cudaGetSymbolAddress((void**)&k,  g_k);
    cudaGetSymbolAddress((void**)&v,  g_v);
    cudaGetSymbolAddress((void**)&h2, g_h2);
    cudaGetSymbolAddress((void**)&xh, g_xh);
    cudaGetSymbolAddress((void**)&xl, g_xl);
    cudaGetSymbolAddress((void**)&hh, g_hh);
    cudaGetSymbolAddress((void**)&hl, g_hl);
    cudaGetSymbolAddress((void**)&ch, g_ch);
    cudaGetSymbolAddress((void**)&cl, g_cl);
    cudaGetSymbolAddress((void**)&wth, g_wth);
    cudaGetSymbolAddress((void**)&wtl, g_wtl);

    cudaFuncSetAttribute(mma_gemm,
                         cudaFuncAttributeMaxDynamicSharedMemorySize, GEMM_SMEM);
    cudaFuncSetAttribute(attn_kernel,
                         cudaFuncAttributeMaxDynamicSharedMemorySize, ATT_SMEM_BYTES);

    const int n4 = MM * DD / 4;
    conv_split<<<(n4 + 255) / 256, 256>>>((const float4*)x,
                                          (__nv_bfloat162*)xh, (__nv_bfloat162*)xl, n4);
    dim3 gT(16, 16);
    wtrans<<<gT, 256>>>(W_w, wth + 0 * DD * DD, wtl + 0 * DD * DD);
    wtrans<<<gT, 256>>>(Wq,  wth + 1 * DD * DD, wtl + 1 * DD * DD);
    wtrans<<<gT, 256>>>(Wk,  wth + 2 * DD * DD, wtl + 2 * DD * DD);
    wtrans<<<gT, 256>>>(Wv,  wth + 3 * DD * DD, wtl + 3 * DD * DD);
    wtrans<<<gT, 256>>>(Wo,  wth + 4 * DD * DD, wtl + 4 * DD * DD);

    dim3 gG(DD / 64, MM / 128);   // (8, 64) = 512 CTAs
    mma_gemm<<<gG, 128, GEMM_SMEM>>>(xh, xl, wth + 0 * DD * DD, wtl + 0 * DD * DD, W_b, h, 0);
    ln2_kernel<<<MM, 256>>>(h, ln_g, ln_b, hh, hl);
    mma_gemm<<<gG, 128, GEMM_SMEM>>>(hh, hl, wth + 1 * DD * DD, wtl + 1 * DD * DD, bq, q, 0);
    mma_gemm<<<gG, 128, GEMM_SMEM>>>(hh, hl, wth + 2 * DD * DD, wtl + 2 * DD * DD, bk, k, 0);
    mma_gemm<<<gG, 128, GEMM_SMEM>>>(hh, hl, wth + 3 * DD * DD, wtl + 3 * DD * DD, bv, v, 0);
    attn_kernel<<<dim3(NN / 64, BB * HH), 256, ATT_SMEM_BYTES>>>(q, k, v, adj, uadj, ch, cl);
    mma_gemm<<<gG, 128, GEMM_SMEM>>>(ch, cl, wth + 4 * DD * DD, wtl + 4 * DD * DD, bo, h2, 1);
    gate_kernel<<<MM, 256>>>(x, h2, gw, gb, out);
}

// round 4
// speedup vs baseline: 1.7735x; 1.2631x over previous
#include <cuda_runtime.h>
#include <cuda_bf16.h>
#include <cstdint>
#include <math.h>

#define BB 16
#define NN 512
#define DD 512
#define HH 8
#define DKK 64
#define MM (BB*NN)          // 8192 rows
#define SCALE 0.125f
#define LN_EPS 1e-5f

// ---------------- scratch (device globals; no allocs allowed) ----------------
__device__ float g_h [MM*DD];
__device__ float g_h2[MM*DD];
__device__ __nv_bfloat16 g_xh[MM*DD], g_xl[MM*DD];   // x split
__device__ __nv_bfloat16 g_hh[MM*DD], g_hl[MM*DD];   // LN(h) split
__device__ __nv_bfloat16 g_qh[MM*DD], g_ql[MM*DD];   // q split
__device__ __nv_bfloat16 g_kh[MM*DD], g_kl[MM*DD];   // k split
__device__ __nv_bfloat16 g_vh[MM*DD], g_vl[MM*DD];   // v split
__device__ __nv_bfloat16 g_ch[MM*DD], g_cl[MM*DD];   // ctx split
__device__ __nv_bfloat16 g_wth[5*DD*DD], g_wtl[5*DD*DD];  // transposed weights split

__device__ __forceinline__ uint32_t smem_u32(const void* p) {
    uint32_t a;
    asm("{ .reg .u64 t; cvta.to.shared.u64 t, %1; cvt.u32.u64 %0, t; }"
        : "=r"(a) : "l"(p));
    return a;
}

// fast exp on FMA pipe: 2^r degree-6 + exponent bit-stuff, rel err ~2e-5
__device__ __forceinline__ float fexp(float x) {
    x = fmaxf(x, -80.f);
    float y = x * 1.4426950408889634f;
    int   i = __float2int_rd(y);
    float r = y - __int2float_rn(i);
    float q = 1.5403530e-4f;
    q = q * r + 1.3333558e-3f;
    q = q * r + 9.6181291e-3f;
    q = q * r + 5.5504109e-2f;
    q = q * r + 2.4022651e-1f;
    q = q * r + 6.9314718e-1f;
    q = q * r + 1.0f;
    return __int_as_float(__float_as_int(q) + (i << 23));
}

#define MMA_OP(acc, A, B) asm volatile(                                        \
    "mma.sync.aligned.m16n8k16.row.col.f32.bf16.bf16.f32 "                     \
    "{%0,%1,%2,%3}, {%4,%5,%6,%7}, {%8,%9}, {%0,%1,%2,%3};"                    \
    : "+f"((acc)[0]), "+f"((acc)[1]), "+f"((acc)[2]), "+f"((acc)[3])           \
    : "r"((A)[0]), "r"((A)[1]), "r"((A)[2]), "r"((A)[3]),                      \
      "r"((B)[0]), "r"((B)[1]))

#define LDSM4(r0, r1, r2, r3, ad) asm volatile(                                \
    "ldmatrix.sync.aligned.m8n8.x4.shared.b16 {%0,%1,%2,%3}, [%4];"            \
    : "=r"(r0), "=r"(r1), "=r"(r2), "=r"(r3) : "r"(ad))

__device__ __forceinline__ uint32_t pk_bf2(float lo, float hi) {
    uint32_t u;
    asm("cvt.rn.bf16x2.f32 %0, %1, %2;" : "=r"(u) : "f"(hi), "f"(lo));
    return u;
}

// =================== mma.sync bf16-split GEMM ===============================
// mode 0: fp32 out (+opt relu). mode 1: bf16 hi/lo split out.
#define PITCHB 80
#define OFF_AL 10240
#define OFF_BH 20480
#define OFF_BL 25600
#define BUFSZ  30720
#define GEMM_SMEM (2*BUFSZ)

__global__ __launch_bounds__(128) void mma_gemm(
    const __nv_bfloat16* __restrict__ Ah, const __nv_bfloat16* __restrict__ Al,
    const __nv_bfloat16* __restrict__ Bh, const __nv_bfloat16* __restrict__ Bl,
    const float* __restrict__ bias, float* __restrict__ C,
    __nv_bfloat16* __restrict__ Ch, __nv_bfloat16* __restrict__ Cl,
    int relu, int mode)
{
    extern __shared__ char smx[];
    const uint32_t sbase = smem_u32(smx);
    const int tid = threadIdx.x, wid = tid >> 5, lane = tid & 31;
    const int rowBase = blockIdx.y * 128, nBase = blockIdx.x * 64;
    const int warpM = wid & 1, warpN = wid >> 1;

    float acc[4][4][4];
#pragma unroll
    for (int i = 0; i < 4; i++)
#pragma unroll
        for (int j = 0; j < 4; j++)
#pragma unroll
            for (int e = 0; e < 4; e++) acc[i][j][e] = 0.f;

    auto issue_load = [&](int c, int buf) {
        const int kc = c * 32;
#pragma unroll
        for (int s = 0; s < 12; s++) {
            int sid = tid + s * 128;
            const __nv_bfloat16* g;
            int t, r, off;
            if (sid < 512)       { g = Ah; t = sid;        off = 0; }
            else if (sid < 1024) { g = Al; t = sid - 512;  off = OFF_AL; }
            else if (sid < 1280) { g = Bh; t = sid - 1024; off = OFF_BH; }
            else                 { g = Bl; t = sid - 1280; off = OFF_BL; }
            r = t >> 2;
            int seg = t & 3;
            int grow = (off < OFF_BH) ? (rowBase + r) : (nBase + r);
            uint32_t da = sbase + buf * BUFSZ + off + r * PITCHB + seg * 16;
            const char* gp = (const char*)(g + (size_t)grow * 512 + kc) + seg * 16;
            asm volatile("cp.async.cg.shared.global [%0], [%1], 16;"
                         :: "r"(da), "l"(gp) : "memory");
        }
        asm volatile("cp.async.commit_group;" ::: "memory");
    };

    issue_load(0, 0);
    for (int c = 0; c < 16; c++) {
        const int buf = c & 1;
        if (c < 15) issue_load(c + 1, buf ^ 1);
        if (c < 15) asm volatile("cp.async.wait_group 1;" ::: "memory");
        else        asm volatile("cp.async.wait_group 0;" ::: "memory");
        __syncthreads();

        const uint32_t bufb = sbase + buf * BUFSZ;
        const int rq = lane & 7, grp = lane >> 3;
        const int mrow = ((grp & 1) << 3) + rq;
#pragma unroll
        for (int ks = 0; ks < 2; ks++) {
            const int kof2 = (ks * 16 + ((grp >> 1) << 3)) * 2;
            uint32_t ah[4][4], bh_[4][2];
#pragma unroll
            for (int i = 0; i < 4; i++) {
                uint32_t ad = bufb + (uint32_t)(warpM * 64 + i * 16 + mrow) * PITCHB + kof2;
                LDSM4(ah[i][0], ah[i][1], ah[i][2], ah[i][3], ad);
            }
#pragma unroll
            for (int jj = 0; jj < 2; jj++) {
                uint32_t ad = bufb + OFF_BH +
                    (uint32_t)(warpN * 32 + jj * 16 + ((grp & 1) << 3) + rq) * PITCHB + kof2;
                uint32_t r0, r1, r2, r3;
                LDSM4(r0, r1, r2, r3, ad);
                bh_[2 * jj][0] = r0; bh_[2 * jj + 1][0] = r1;
                bh_[2 * jj][1] = r2; bh_[2 * jj + 1][1] = r3;
            }
#pragma unroll
            for (int i = 0; i < 4; i++)
#pragma unroll
                for (int j = 0; j < 4; j++) MMA_OP(acc[i][j], ah[i], bh_[j]);
            {
                uint32_t al_[4];
#pragma unroll
                for (int i = 0; i < 4; i++) {
                    uint32_t ad = bufb + OFF_AL +
                        (uint32_t)(warpM * 64 + i * 16 + mrow) * PITCHB + kof2;
                    LDSM4(al_[0], al_[1], al_[2], al_[3], ad);
#pragma unroll
                    for (int j = 0; j < 4; j++) MMA_OP(acc[i][j], al_, bh_[j]);
                }
            }
            {
                uint32_t bl_[4][2];
#pragma unroll
                for (int jj = 0; jj < 2; jj++) {
                    uint32_t ad = bufb + OFF_BL +
                        (uint32_t)(warpN * 32 + jj * 16 + ((grp & 1) << 3) + rq) * PITCHB + kof2;
                    uint32_t r0, r1, r2, r3;
                    LDSM4(r0, r1, r2, r3, ad);
                    bl_[2 * jj][0] = r0; bl_[2 * jj + 1][0] = r1;
                    bl_[2 * jj][1] = r2; bl_[2 * jj + 1][1] = r3;
                }
#pragma unroll
                for (int i = 0; i < 4; i++)
#pragma unroll
                    for (int j = 0; j < 4; j++) MMA_OP(acc[i][j], ah[i], bl_[j]);
            }
        }
        __syncthreads();
    }

#pragma unroll
    for (int i = 0; i < 4; i++) {
#pragma unroll
        for (int j = 0; j < 4; j++) {
            int gr = rowBase + warpM * 64 + i * 16 + (lane >> 2);
            int gc = nBase + warpN * 32 + j * 8 + (lane & 3) * 2;
            float2 b2 = *(const float2*)&bias[gc];
            float v0 = acc[i][j][0] + b2.x, v1 = acc[i][j][1] + b2.y;
            float v2 = acc[i][j][2] + b2.x, v3 = acc[i][j][3] + b2.y;
            if (mode == 0) {
                if (relu) {
                    v0 = fmaxf(v0, 0.f); v1 = fmaxf(v1, 0.f);
                    v2 = fmaxf(v2, 0.f); v3 = fmaxf(v3, 0.f);
                }
                float2 o0; o0.x = v0; o0.y = v1;
                float2 o1; o1.x = v2; o1.y = v3;
                *(float2*)&C[(size_t)gr * DD + gc]       = o0;
                *(float2*)&C[(size_t)(gr + 8) * DD + gc] = o1;
            } else {
                float h0 = __bfloat162float(__float2bfloat16(v0));
                float h1 = __bfloat162float(__float2bfloat16(v1));
                float h2 = __bfloat162float(__float2bfloat16(v2));
                float h3 = __bfloat162float(__float2bfloat16(v3));
                *(uint32_t*)&Ch[(size_t)gr * DD + gc]       = pk_bf2(h0, h1);
                *(uint32_t*)&Ch[(size_t)(gr + 8) * DD + gc] = pk_bf2(h2, h3);
                *(uint32_t*)&Cl[(size_t)gr * DD + gc]       = pk_bf2(v0 - h0, v1 - h1);
                *(uint32_t*)&Cl[(size_t)(gr + 8) * DD + gc] = pk_bf2(v2 - h2, v3 - h3);
            }
        }
    }
}

// =================== tensor-core flash attention ============================
// CTA: 64 q-rows x one (b,h); 4 warps x 16 q-rows; key chunks of 64.
#define AP    144                 // smem pitch bytes (64 bf16 + pad)
#define OQH   0
#define OQL   (64*AP)             // 9216
#define OKH   (2*64*AP)
#define OKL   (3*64*AP)
#define OVH   (4*64*AP)           // Vt hi (d-major)
#define OVL   (5*64*AP)
#define OADJ  (6*64*AP)           // 55296; u8 [64q][64k]
#define ATT_SMEM (OADJ + 64*64)   // 59392

__global__ __launch_bounds__(128) void attn_mma(
    const __nv_bfloat16* __restrict__ qh, const __nv_bfloat16* __restrict__ ql,
    const __nv_bfloat16* __restrict__ kh, const __nv_bfloat16* __restrict__ kl,
    const __nv_bfloat16* __restrict__ vh, const __nv_bfloat16* __restrict__ vl,
    const float* __restrict__ adj, const int* __restrict__ use_adj_p,
    __nv_bfloat16* __restrict__ ch, __nv_bfloat16* __restrict__ cl)
{
    extern __shared__ char smx[];
    const uint32_t sbase = smem_u32(smx);
    const int tid = threadIdx.x, warp = tid >> 5, lane = tid & 31;
    const int bh = blockIdx.y;
    const int b = bh >> 3, hd = bh & 7;
    const int q0 = blockIdx.x * 64;
    const int use_adj = (*use_adj_p) != 0;

    const int rq = lane & 7, grp = lane >> 3;
    const int mrow = ((grp & 1) << 3) + rq;     // A-frag row pattern
    const int kg16 = (grp >> 1) << 4;           // k byte offset within 16-step
    const int lane2 = lane & 3, r0 = lane >> 2;

    // ---- load Q tile (hi+lo) once
#pragma unroll
    for (int s = 0; s < 4; s++) {
        int idx = tid + s * 128;                // 0..511
        int r = idx >> 3, seg = idx & 7;
        size_t gb = ((size_t)(b * NN + q0 + r)) * DD + hd * DKK + seg * 8;
        *(uint4*)(smx + OQH + r * AP + seg * 16) = *(const uint4*)(qh + gb);
        *(uint4*)(smx + OQL + r * AP + seg * 16) = *(const uint4*)(ql + gb);
    }

    float m0 = -1e30f, m1 = -1e30f, l0 = 0.f, l1 = 0.f;
    float ca[8][4];
#pragma unroll
    for (int j = 0; j < 8; j++)
#pragma unroll
        for (int e = 0; e < 4; e++) ca[j][e] = 0.f;

    for (int cchunk = 0; cchunk < 8; cchunk++) {
        const int k0c = cchunk * 64;
        __syncthreads();   // previous iteration's ldsm done before overwrite

        // ---- K chunk (hi+lo), row-major keys x 64d
#pragma unroll
        for (int s = 0; s < 4; s++) {
            int idx = tid + s * 128;
            int r = idx >> 3, seg = idx & 7;
            size_t gb = ((size_t)(b * NN + k0c + r)) * DD + hd * DKK + seg * 8;
            *(uint4*)(smx + OKH + r * AP + seg * 16) = *(const uint4*)(kh + gb);
            *(uint4*)(smx + OKL + r * AP + seg * 16) = *(const uint4*)(kl + gb);
        }
        // ---- V chunk transposed: Vt[d][key], packed 2 keys per u32
#pragma unroll
        for (int s = 0; s < 4; s++) {
            int idx = tid + s * 128;            // 0..511
            int kp = idx & 31, dq = idx >> 5;   // key pair, d quad
            size_t g0 = ((size_t)(b * NN + k0c + 2 * kp)) * DD + hd * DKK + dq * 4;
            size_t g1 = g0 + DD;
            uint2 a  = *(const uint2*)(vh + g0);
            uint2 b2 = *(const uint2*)(vh + g1);
            char* vt = smx + OVH + kp * 4;
            *(uint32_t*)(vt + (dq * 4 + 0) * AP) = __byte_perm(a.x, b2.x, 0x5410);
            *(uint32_t*)(vt + (dq * 4 + 1) * AP) = __byte_perm(a.x, b2.x, 0x7632);
            *(uint32_t*)(vt + (dq * 4 + 2) * AP) = __byte_perm(a.y, b2.y, 0x5410);
            *(uint32_t*)(vt + (dq * 4 + 3) * AP) = __byte_perm(a.y, b2.y, 0x7632);
            a  = *(const uint2*)(vl + g0);
            b2 = *(const uint2*)(vl + g1);
            vt = smx + OVL + kp * 4;
            *(uint32_t*)(vt + (dq * 4 + 0) * AP) = __byte_perm(a.x, b2.x, 0x5410);
            *(uint32_t*)(vt + (dq * 4 + 1) * AP) = __byte_perm(a.x, b2.x, 0x7632);
            *(uint32_t*)(vt + (dq * 4 + 2) * AP) = __byte_perm(a.y, b2.y, 0x5410);
            *(uint32_t*)(vt + (dq * 4 + 3) * AP) = __byte_perm(a.y, b2.y, 0x7632);
        }
        // ---- adj chunk -> u8
#pragma unroll
        for (int s = 0; s < 8; s++) {
            int idx = tid + s * 128;            // 0..1023
            int r = idx >> 4, fs = idx & 15;
            uint32_t pack;
            if (use_adj) {
                float4 av = *(const float4*)(adj + ((size_t)b * NN + q0 + r) * NN + k0c + fs * 4);
                pack = (av.x > 0.f ? 1u : 0u) | (av.y > 0.f ? 1u : 0u) << 8 |
                       (av.z > 0.f ? 1u : 0u) << 16 | (av.w > 0.f ? 1u : 0u) << 24;
            } else pack = 0x01010101u;
            *(uint32_t*)(smx + OADJ + r * 64 + fs * 4) = pack;
        }
        __syncthreads();

        // ---- S = Q K^T (3-term split), per warp 16q x 64k
        float sa[8][4];
#pragma unroll
        for (int j = 0; j < 8; j++)
#pragma unroll
            for (int e = 0; e < 4; e++) sa[j][e] = 0.f;

#pragma unroll
        for (int ks = 0; ks < 4; ks++) {
            const int kof = ks * 32 + kg16;
            uint32_t aH[4], aL[4];
            uint32_t ad = sbase + OQH + (uint32_t)(warp * 16 + mrow) * AP + kof;
            LDSM4(aH[0], aH[1], aH[2], aH[3], ad);
            ad = sbase + OQL + (uint32_t)(warp * 16 + mrow) * AP + kof;
            LDSM4(aL[0], aL[1], aL[2], aL[3], ad);
#pragma unroll
            for (int jj = 0; jj < 4; jj++) {
                uint32_t bH[2][2], bL[2][2], t0, t1, t2, t3;
                uint32_t bd = sbase + OKH + (uint32_t)(jj * 16 + mrow) * AP + kof;
                LDSM4(t0, t1, t2, t3, bd);
                bH[0][0] = t0; bH[1][0] = t1; bH[0][1] = t2; bH[1][1] = t3;
                bd = sbase + OKL + (uint32_t)(jj * 16 + mrow) * AP + kof;
                LDSM4(t0, t1, t2, t3, bd);
                bL[0][0] = t0; bL[1][0] = t1; bL[0][1] = t2; bL[1][1] = t3;
                MMA_OP(sa[2 * jj],     aH, bH[0]); MMA_OP(sa[2 * jj + 1], aH, bH[1]);
                MMA_OP(sa[2 * jj],     aL, bH[0]); MMA_OP(sa[2 * jj + 1], aL, bH[1]);
                MMA_OP(sa[2 * jj],     aH, bL[0]); MMA_OP(sa[2 * jj + 1], aH, bL[1]);
            }
        }

        // ---- mask + scale (masked -> 0.0 reference semantics)
#pragma unroll
        for (int j = 0; j < 8; j++) {
            int colb = j * 8 + lane2 * 2;
            uint32_t m01 = *(const unsigned short*)(smx + OADJ + (warp * 16 + r0) * 64 + colb);
            uint32_t m23 = *(const unsigned short*)(smx + OADJ + (warp * 16 + r0 + 8) * 64 + colb);
            sa[j][0] = (m01 & 0xFFu)  ? sa[j][0] * SCALE : 0.f;
            sa[j][1] = (m01 & 0xFF00u) ? sa[j][1] * SCALE : 0.f;
            sa[j][2] = (m23 & 0xFFu)  ? sa[j][2] * SCALE : 0.f;
            sa[j][3] = (m23 & 0xFF00u) ? sa[j][3] * SCALE : 0.f;
        }

        // ---- online softmax
        float cm0 = -1e30f, cm1 = -1e30f;
#pragma unroll
        for (int j = 0; j < 8; j++) {
            cm0 = fmaxf(cm0, fmaxf(sa[j][0], sa[j][1]));
            cm1 = fmaxf(cm1, fmaxf(sa[j][2], sa[j][3]));
        }
        cm0 = fmaxf(cm0, __shfl_xor_sync(0xffffffffu, cm0, 1));
        cm0 = fmaxf(cm0, __shfl_xor_sync(0xffffffffu, cm0, 2));
        cm1 = fmaxf(cm1, __shfl_xor_sync(0xffffffffu, cm1, 1));
        cm1 = fmaxf(cm1, __shfl_xor_sync(0xffffffffu, cm1, 2));
        float mn0 = fmaxf(m0, cm0), mn1 = fmaxf(m1, cm1);
        float sc0 = fexp(m0 - mn0), sc1 = fexp(m1 - mn1);
        float cs0 = 0.f, cs1 = 0.f;
#pragma unroll
        for (int j = 0; j < 8; j++) {
            sa[j][0] = fexp(sa[j][0] - mn0);
            sa[j][1] = fexp(sa[j][1] - mn0);
            sa[j][2] = fexp(sa[j][2] - mn1);
            sa[j][3] = fexp(sa[j][3] - mn1);
            cs0 += sa[j][0] + sa[j][1];
            cs1 += sa[j][2] + sa[j][3];
        }
        cs0 += __shfl_xor_sync(0xffffffffu, cs0, 1);
        cs0 += __shfl_xor_sync(0xffffffffu, cs0, 2);
        cs1 += __shfl_xor_sync(0xffffffffu, cs1, 1);
        cs1 += __shfl_xor_sync(0xffffffffu, cs1, 2);
        l0 = l0 * sc0 + cs0; m0 = mn0;
        l1 = l1 * sc1 + cs1; m1 = mn1;
#pragma unroll
        for (int j = 0; j < 8; j++) {
            ca[j][0] *= sc0; ca[j][1] *= sc0;
            ca[j][2] *= sc1; ca[j][3] *= sc1;
        }

        // ---- ctx += P @ V (3-term split); A-frags from S accums
#pragma unroll
        for (int ks = 0; ks < 4; ks++) {
            uint32_t aH[4], aL[4];
            {
                float p0 = sa[2 * ks][0], p1 = sa[2 * ks][1];
                float p2 = sa[2 * ks][2], p3 = sa[2 * ks][3];
                float p4 = sa[2 * ks + 1][0], p5 = sa[2 * ks + 1][1];
                float p6 = sa[2 * ks + 1][2], p7 = sa[2 * ks + 1][3];
                float h0 = __bfloat162float(__float2bfloat16(p0));
                float h1 = __bfloat162float(__float2bfloat16(p1));
                float h2 = __bfloat162float(__float2bfloat16(p2));
                float h3 = __bfloat162float(__float2bfloat16(p3));
                float h4 = __bfloat162float(__float2bfloat16(p4));
                float h5 = __bfloat162float(__float2bfloat16(p5));
                float h6 = __bfloat162float(__float2bfloat16(p6));
                float h7 = __bfloat162float(__float2bfloat16(p7));
                aH[0] = pk_bf2(h0, h1); aH[1] = pk_bf2(h2, h3);
                aH[2] = pk_bf2(h4, h5); aH[3] = pk_bf2(h6, h7);
                aL[0] = pk_bf2(p0 - h0, p1 - h1); aL[1] = pk_bf2(p2 - h2, p3 - h3);
                aL[2] = pk_bf2(p4 - h4, p5 - h5); aL[3] = pk_bf2(p6 - h6, p7 - h7);
            }
            const int kof = ks * 32 + kg16;
#pragma unroll
            for (int jj = 0; jj < 4; jj++) {
                uint32_t bH[2][2], bL[2][2], t0, t1, t2, t3;
                uint32_t bd = sbase + OVH + (uint32_t)(jj * 16 + mrow) * AP + kof;
                LDSM4(t0, t1, t2, t3, bd);
                bH[0][0] = t0; bH[1][0] = t1; bH[0][1] = t2; bH[1][1] = t3;
                bd = sbase + OVL + (uint32_t)(jj * 16 + mrow) * AP + kof;
                LDSM4(t0, t1, t2, t3, bd);
                bL[0][0] = t0; bL[1][0] = t1; bL[0][1] = t2; bL[1][1] = t3;
                MMA_OP(ca[2 * jj],     aH, bH[0]); MMA_OP(ca[2 * jj + 1], aH, bH[1]);
                MMA_OP(ca[2 * jj],     aL, bH[0]); MMA_OP(ca[2 * jj + 1], aL, bH[1]);
                MMA_OP(ca[2 * jj],     aH, bL[0]); MMA_OP(ca[2 * jj + 1], aH, bL[1]);
            }
        }
    }

    // ---- epilogue: normalize, split, store
    const float inv0 = 1.f / l0, inv1 = 1.f / l1;
    const int qr0 = q0 + warp * 16 + r0;
#pragma unroll
    for (int j = 0; j < 8; j++) {
        int d = j * 8 + lane2 * 2;
        size_t b0 = ((size_t)(b * NN + qr0)) * DD + hd * DKK + d;
        size_t b1 = b0 + 8 * DD;
        float v0 = ca[j][0] * inv0, v1 = ca[j][1] * inv0;
        float v2 = ca[j][2] * inv1, v3 = ca[j][3] * inv1;
        float h0 = __bfloat162float(__float2bfloat16(v0));
        float h1 = __bfloat162float(__float2bfloat16(v1));
        float h2 = __bfloat162float(__float2bfloat16(v2));
        float h3 = __bfloat162float(__float2bfloat16(v3));
        *(uint32_t*)&ch[b0] = pk_bf2(h0, h1);
        *(uint32_t*)&ch[b1] = pk_bf2(h2, h3);
        *(uint32_t*)&cl[b0] = pk_bf2(v0 - h0, v1 - h1);
        *(uint32_t*)&cl[b1] = pk_bf2(v2 - h2, v3 - h3);
    }
}

// ---------------- fp32 -> (hi,lo) bf16 split --------------------------------
__global__ __launch_bounds__(256) void conv_split(
    const float4* __restrict__ in, __nv_bfloat162* __restrict__ hi,
    __nv_bfloat162* __restrict__ lo, int n4)
{
    int i = blockIdx.x * 256 + threadIdx.x;
    if (i >= n4) return;
    float4 v = in[i];
    __nv_bfloat16 h0 = __float2bfloat16(v.x), h1 = __float2bfloat16(v.y);
    __nv_bfloat16 h2 = __float2bfloat16(v.z), h3 = __float2bfloat16(v.w);
    __nv_bfloat162 a, b, c, d;
    a.x = h0; a.y = h1; b.x = h2; b.y = h3;
    c.x = __float2bfloat16(v.x - __bfloat162float(h0));
    c.y = __float2bfloat16(v.y - __bfloat162float(h1));
    d.x = __float2bfloat16(v.z - __bfloat162float(h2));
    d.y = __float2bfloat16(v.w - __bfloat162float(h3));
    hi[2 * i] = a; hi[2 * i + 1] = b;
    lo[2 * i] = c; lo[2 * i + 1] = d;
}

// ---------------- weight transpose + split ----------------------------------
__global__ __launch_bounds__(256) void wtrans(
    const float* __restrict__ W, __nv_bfloat16* __restrict__ th,
    __nv_bfloat16* __restrict__ tl)
{
    __shared__ float t[32][33];
    const int k0 = blockIdx.y * 32, n0 = blockIdx.x * 32;
    const int tx = threadIdx.x & 31, ty = threadIdx.x >> 5;
#pragma unroll
    for (int i = 0; i < 32; i += 8)
        t[ty + i][tx] = W[(size_t)(k0 + ty + i) * DD + n0 + tx];
    __syncthreads();
#pragma unroll
    for (int i = 0; i < 32; i += 8) {
        float v = t[tx][ty + i];
        __nv_bfloat16 h = __float2bfloat16(v);
        __nv_bfloat16 l = __float2bfloat16(v - __bfloat162float(h));
        size_t o = (size_t)(n0 + ty + i) * DD + k0 + tx;
        th[o] = h; tl[o] = l;
    }
}

// ---------------- LayerNorm -> bf16 hi/lo -----------------------------------
__global__ __launch_bounds__(256) void ln2_kernel(
    const float* __restrict__ h, const float* __restrict__ g, const float* __restrict__ b,
    __nv_bfloat16* __restrict__ hh, __nv_bfloat16* __restrict__ hl)
{
    const int r = blockIdx.x;
    const float* row = h + (size_t)r * DD;
    const int t = threadIdx.x;
    float v0 = row[t], v1 = row[t + 256];

    __shared__ float red[8];
    __shared__ float s_mu, s_rs;
    float s = v0 + v1;
#pragma unroll
    for (int o = 16; o; o >>= 1) s += __shfl_xor_sync(0xffffffffu, s, o);
    if ((t & 31) == 0) red[t >> 5] = s;
    __syncthreads();
    if (t == 0) {
        float tot = 0.f;
#pragma unroll
        for (int i = 0; i < 8; i++) tot += red[i];
        s_mu = tot * (1.f / DD);
    }
    __syncthreads();
    const float mu = s_mu;
    float d0 = v0 - mu, d1 = v1 - mu;
    float s2 = d0 * d0 + d1 * d1;
#pragma unroll
    for (int o = 16; o; o >>= 1) s2 += __shfl_xor_sync(0xffffffffu, s2, o);
    if ((t & 31) == 0) red[t >> 5] = s2;
    __syncthreads();
    if (t == 0) {
        float tot = 0.f;
#pragma unroll
        for (int i = 0; i < 8; i++) tot += red[i];
        s_rs = rsqrtf(tot * (1.f / DD) + LN_EPS);
    }
    __syncthreads();
    const float rs = s_rs;
    float y0 = d0 * rs * g[t] + b[t];
    float y1 = d1 * rs * g[t + 256] + b[t + 256];
    size_t base = (size_t)r * DD;
    __nv_bfloat16 a0 = __float2bfloat16(y0);
    __nv_bfloat16 a1 = __float2bfloat16(y1);
    hh[base + t] = a0;       hl[base + t] = __float2bfloat16(y0 - __bfloat162float(a0));
    hh[base + t + 256] = a1; hl[base + t + 256] = __float2bfloat16(y1 - __bfloat162float(a1));
}

// ---------------- gate + residual mix ---------------------------------------
__global__ __launch_bounds__(256) void gate_kernel(
    const float* __restrict__ x, const float* __restrict__ h2,
    const float* __restrict__ gw, const float* __restrict__ gb,
    float* __restrict__ out)
{
    const int r = blockIdx.x;
    const size_t base = (size_t)r * DD;
    const int t = threadIdx.x;
    float x0 = x[base + t], x1 = x[base + t + 256];
    float h0 = h2[base + t], h1 = h2[base + t + 256];
    float s = x0 * gw[t] + x1 * gw[t + 256] + h0 * gw[512 + t] + h1 * gw[768 + t];

    __shared__ float red[8];
    __shared__ float s_c;
#pragma unroll
    for (int o = 16; o; o >>= 1) s += __shfl_xor_sync(0xffffffffu, s, o);
    if ((t & 31) == 0) red[t >> 5] = s;
    __syncthreads();
    if (t == 0) {
        float tot = 0.f;
#pragma unroll
        for (int i = 0; i < 8; i++) tot += red[i];
        s_c = 1.f / (1.f + expf(-(tot + gb[0])));
    }
    __syncthreads();
    const float c = s_c;
    out[base + t]       = c * x0 + (1.f - c) * h0;
    out[base + t + 256] = c * x1 + (1.f - c) * h1;
}

// ---------------- launch ----------------------------------------------------
extern "C" void kernel_launch(void* const* d_in, const int* in_sizes, int n_in,
                              void* d_out, int out_size)
{
    const float* x    = (const float*)d_in[0];
    const float* adj  = (const float*)d_in[1];
    const float* W_w  = (const float*)d_in[2];
    const float* W_b  = (const float*)d_in[3];
    const float* ln_g = (const float*)d_in[4];
    const float* ln_b = (const float*)d_in[5];
    const float* Wq   = (const float*)d_in[6];
    const float* bq   = (const float*)d_in[7];
    const float* Wk   = (const float*)d_in[8];
    const float* bk   = (const float*)d_in[9];
    const float* Wv   = (const float*)d_in[10];
    const float* bv   = (const float*)d_in[11];
    const float* Wo   = (const float*)d_in[12];
    const float* bo   = (const float*)d_in[13];
    const float* gw   = (const float*)d_in[14];
    const float* gb   = (const float*)d_in[15];
    const int*   uadj = (const int*)d_in[16];
    float* out = (float*)d_out;

    float *h, *h2;
    __nv_bfloat16 *xh, *xl, *hh, *hl, *qh, *ql, *kh, *kl, *vh, *vl, *ch, *cl, *wth, *wtl;
    cudaGetSymbolAddress((void**)&h,  g_h);
    cudaGetSymbolAddress((void**)&h2, g_h2);
    cudaGetSymbolAddress((void**)&xh, g_xh);
    cudaGetSymbolAddress((void**)&xl, g_xl);
    cudaGetSymbolAddress((void**)&hh, g_hh);
    cudaGetSymbolAddress((void**)&hl, g_hl);
    cudaGetSymbolAddress((void**)&qh, g_qh);
    cudaGetSymbolAddress((void**)&ql, g_ql);
    cudaGetSymbolAddress((void**)&kh, g_kh);
    cudaGetSymbolAddress((void**)&kl, g_kl);
    cudaGetSymbolAddress((void**)&vh, g_vh);
    cudaGetSymbolAddress((void**)&vl, g_vl);
    cudaGetSymbolAddress((void**)&ch, g_ch);
    cudaGetSymbolAddress((void**)&cl, g_cl);
    cudaGetSymbolAddress((void**)&wth, g_wth);
    cudaGetSymbolAddress((void**)&wtl, g_wtl);

    cudaFuncSetAttribute(mma_gemm,
                         cudaFuncAttributeMaxDynamicSharedMemorySize, GEMM_SMEM);
    cudaFuncSetAttribute(attn_mma,
                         cudaFuncAttributeMaxDynamicSharedMemorySize, ATT_SMEM);

    const int n4 = MM * DD / 4;
    conv_split<<<(n4 + 255) / 256, 256>>>((const float4*)x,
                                          (__nv_bfloat162*)xh, (__nv_bfloat162*)xl, n4);
    dim3 gT(16, 16);
    wtrans<<<gT, 256>>>(W_w, wth + 0 * DD * DD, wtl + 0 * DD * DD);
    wtrans<<<gT, 256>>>(Wq,  wth + 1 * DD * DD, wtl + 1 * DD * DD);
    wtrans<<<gT, 256>>>(Wk,  wth + 2 * DD * DD, wtl + 2 * DD * DD);
    wtrans<<<gT, 256>>>(Wv,  wth + 3 * DD * DD, wtl + 3 * DD * DD);
    wtrans<<<gT, 256>>>(Wo,  wth + 4 * DD * DD, wtl + 4 * DD * DD);

    dim3 gG(DD / 64, MM / 128);   // (8, 64)
    mma_gemm<<<gG, 128, GEMM_SMEM>>>(xh, xl, wth + 0 * DD * DD, wtl + 0 * DD * DD,
                                     W_b, h, nullptr, nullptr, 0, 0);
    ln2_kernel<<<MM, 256>>>(h, ln_g, ln_b, hh, hl);
    mma_gemm<<<gG, 128, GEMM_SMEM>>>(hh, hl, wth + 1 * DD * DD, wtl + 1 * DD * DD,
                                     bq, nullptr, qh, ql, 0, 1);
    mma_gemm<<<gG, 128, GEMM_SMEM>>>(hh, hl, wth + 2 * DD * DD, wtl + 2 * DD * DD,
                                     bk, nullptr, kh, kl, 0, 1);
    mma_gemm<<<gG, 128, GEMM_SMEM>>>(hh, hl, wth + 3 * DD * DD, wtl + 3 * DD * DD,
                                     bv, nullptr, vh, vl, 0, 1);
    attn_mma<<<dim3(NN / 64, BB * HH), 128, ATT_SMEM>>>(qh, ql, kh, kl, vh, vl,
                                                        adj, uadj, ch, cl);
    mma_gemm<<<gG, 128, GEMM_SMEM>>>(ch, cl, wth + 4 * DD * DD, wtl + 4 * DD * DD,
                                     bo, h2, nullptr, nullptr, 1, 0);
    gate_kernel<<<MM, 256>>>(x, h2, gw, gb, out);
}

// round 6
// speedup vs baseline: 1.9074x; 1.0755x over previous
#include <cuda_runtime.h>
#include <cuda_bf16.h>
#include <cstdint>
#include <math.h>

#define BB 16
#define NN 512
#define DD 512
#define HH 8
#define DKK 64
#define MM (BB*NN)          // 8192 rows
#define SCALE 0.125f
#define LN_EPS 1e-5f

// ---------------- scratch (device globals; no allocs allowed) ----------------
__device__ float g_h [MM*DD];
__device__ float g_h2[MM*DD];
__device__ float g_bqkv[3*DD];
__device__ __nv_bfloat16 g_xh[MM*DD], g_xl[MM*DD];
__device__ __nv_bfloat16 g_hh[MM*DD], g_hl[MM*DD];
__device__ __nv_bfloat16 g_qh[MM*DD], g_ql[MM*DD];
__device__ __nv_bfloat16 g_kh[MM*DD], g_kl[MM*DD];
__device__ __nv_bfloat16 g_vh[MM*DD], g_vl[MM*DD];
__device__ __nv_bfloat16 g_ch[MM*DD], g_cl[MM*DD];
__device__ __nv_bfloat16 g_wth[5*DD*DD], g_wtl[5*DD*DD];

__device__ __forceinline__ uint32_t smem_u32(const void* p) {
    uint32_t a;
    asm("{ .reg .u64 t; cvta.to.shared.u64 t, %1; cvt.u32.u64 %0, t; }"
        : "=r"(a) : "l"(p));
    return a;
}

// fast exp on FMA pipe
__device__ __forceinline__ float fexp(float x) {
    x = fmaxf(x, -80.f);
    float y = x * 1.4426950408889634f;
    int   i = __float2int_rd(y);
    float r = y - __int2float_rn(i);
    float q = 1.5403530e-4f;
    q = q * r + 1.3333558e-3f;
    q = q * r + 9.6181291e-3f;
    q = q * r + 5.5504109e-2f;
    q = q * r + 2.4022651e-1f;
    q = q * r + 6.9314718e-1f;
    q = q * r + 1.0f;
    return __int_as_float(__float_as_int(q) + (i << 23));
}

#define MMA_OP(acc, A, B) asm volatile(                                        \
    "mma.sync.aligned.m16n8k16.row.col.f32.bf16.bf16.f32 "                     \
    "{%0,%1,%2,%3}, {%4,%5,%6,%7}, {%8,%9}, {%0,%1,%2,%3};"                    \
    : "+f"((acc)[0]), "+f"((acc)[1]), "+f"((acc)[2]), "+f"((acc)[3])           \
    : "r"((A)[0]), "r"((A)[1]), "r"((A)[2]), "r"((A)[3]),                      \
      "r"((B)[0]), "r"((B)[1]))

#define LDSM4(r0, r1, r2, r3, ad) asm volatile(                                \
    "ldmatrix.sync.aligned.m8n8.x4.shared.b16 {%0,%1,%2,%3}, [%4];"            \
    : "=r"(r0), "=r"(r1), "=r"(r2), "=r"(r3) : "r"(ad))

__device__ __forceinline__ uint32_t pk_bf2(float lo, float hi) {
    uint32_t u;
    asm("cvt.rn.bf16x2.f32 %0, %1, %2;" : "=r"(u) : "f"(hi), "f"(lo));
    return u;
}

// =================== mma.sync bf16-split GEMM ===============================
// CTA 128(M) x 128(N), 256 threads (2x4 warps, warp tile 64x32), K chunks 32.
// mode 0: fp32 out (+opt relu). mode 1: bf16 hi/lo split out (QKV select).
#define PITCHB 80
#define OFF_AL 10240
#define OFF_BH 20480
#define OFF_BL 30720
#define BUFSZ  40960
#define GEMM_SMEM (2*BUFSZ)          // 81920

__global__ __launch_bounds__(256, 2) void mma_gemm(
    const __nv_bfloat16* __restrict__ Ah, const __nv_bfloat16* __restrict__ Al,
    const __nv_bfloat16* __restrict__ Bh, const __nv_bfloat16* __restrict__ Bl,
    const float* __restrict__ bias, float* __restrict__ C,
    __nv_bfloat16* __restrict__ Q0h, __nv_bfloat16* __restrict__ Q0l,
    __nv_bfloat16* __restrict__ Q1h, __nv_bfloat16* __restrict__ Q1l,
    __nv_bfloat16* __restrict__ Q2h, __nv_bfloat16* __restrict__ Q2l,
    int relu, int mode)
{
    extern __shared__ char smx[];
    const uint32_t sbase = smem_u32(smx);
    const int tid = threadIdx.x, wid = tid >> 5, lane = tid & 31;
    const int rowBase = blockIdx.y * 128, nBase = blockIdx.x * 128;
    const int warpM = wid & 1, warpN = wid >> 1;     // 2 x 4

    float acc[4][4][4];
#pragma unroll
    for (int i = 0; i < 4; i++)
#pragma unroll
        for (int j = 0; j < 4; j++)
#pragma unroll
            for (int e = 0; e < 4; e++) acc[i][j][e] = 0.f;

    auto issue_load = [&](int c, int buf) {
        const int kc = c * 32;
#pragma unroll
        for (int s = 0; s < 8; s++) {
            int sid = tid + s * 256;       // 0..2047
            const __nv_bfloat16* g;
            int off;
            if (sid < 512)       { g = Ah; off = 0; }
            else if (sid < 1024) { g = Al; off = OFF_AL; }
            else if (sid < 1536) { g = Bh; off = OFF_BH; }
            else                 { g = Bl; off = OFF_BL; }
            int t = sid & 511;
            int r = t >> 2, seg = t & 3;
            int grow = (off < OFF_BH) ? (rowBase + r) : (nBase + r);
            uint32_t da = sbase + buf * BUFSZ + off + r * PITCHB + seg * 16;
            const char* gp = (const char*)(g + (size_t)grow * 512 + kc) + seg * 16;
            asm volatile("cp.async.cg.shared.global [%0], [%1], 16;"
                         :: "r"(da), "l"(gp) : "memory");
        }
        asm volatile("cp.async.commit_group;" ::: "memory");
    };

    issue_load(0, 0);
    for (int c = 0; c < 16; c++) {
        const int buf = c & 1;
        if (c < 15) issue_load(c + 1, buf ^ 1);
        if (c < 15) asm volatile("cp.async.wait_group 1;" ::: "memory");
        else        asm volatile("cp.async.wait_group 0;" ::: "memory");
        __syncthreads();

        const uint32_t bufb = sbase + buf * BUFSZ;
        const int rq = lane & 7, grp = lane >> 3;
        const int mrow = ((grp & 1) << 3) + rq;
#pragma unroll
        for (int ks = 0; ks < 2; ks++) {
            const int kof2 = (ks * 16 + ((grp >> 1) << 3)) * 2;
            uint32_t ah[4][4], bh_[4][2];
#pragma unroll
            for (int i = 0; i < 4; i++) {
                uint32_t ad = bufb + (uint32_t)(warpM * 64 + i * 16 + mrow) * PITCHB + kof2;
                LDSM4(ah[i][0], ah[i][1], ah[i][2], ah[i][3], ad);
            }
#pragma unroll
            for (int jj = 0; jj < 2; jj++) {
                uint32_t ad = bufb + OFF_BH +
                    (uint32_t)(warpN * 32 + jj * 16 + ((grp & 1) << 3) + rq) * PITCHB + kof2;
                uint32_t r0, r1, r2, r3;
                LDSM4(r0, r1, r2, r3, ad);
                bh_[2 * jj][0] = r0; bh_[2 * jj + 1][0] = r1;
                bh_[2 * jj][1] = r2; bh_[2 * jj + 1][1] = r3;
            }
#pragma unroll
            for (int i = 0; i < 4; i++)
#pragma unroll
                for (int j = 0; j < 4; j++) MMA_OP(acc[i][j], ah[i], bh_[j]);
            {
                uint32_t al_[4];
#pragma unroll
                for (int i = 0; i < 4; i++) {
                    uint32_t ad = bufb + OFF_AL +
                        (uint32_t)(warpM * 64 + i * 16 + mrow) * PITCHB + kof2;
                    LDSM4(al_[0], al_[1], al_[2], al_[3], ad);
#pragma unroll
                    for (int j = 0; j < 4; j++) MMA_OP(acc[i][j], al_, bh_[j]);
                }
            }
            {
                uint32_t bl_[4][2];
#pragma unroll
                for (int jj = 0; jj < 2; jj++) {
                    uint32_t ad = bufb + OFF_BL +
                        (uint32_t)(warpN * 32 + jj * 16 + ((grp & 1) << 3) + rq) * PITCHB + kof2;
                    uint32_t r0, r1, r2, r3;
                    LDSM4(r0, r1, r2, r3, ad);
                    bl_[2 * jj][0] = r0; bl_[2 * jj + 1][0] = r1;
                    bl_[2 * jj][1] = r2; bl_[2 * jj + 1][1] = r3;
                }
#pragma unroll
                for (int i = 0; i < 4; i++)
#pragma unroll
                    for (int j = 0; j < 4; j++) MMA_OP(acc[i][j], ah[i], bl_[j]);
            }
        }
        __syncthreads();
    }

    // ---- epilogue
    const int third = nBase >> 9;
    const int ncol0 = nBase & 511;
    __nv_bfloat16* Ch = (third == 0) ? Q0h : (third == 1) ? Q1h : Q2h;
    __nv_bfloat16* Cl = (third == 0) ? Q0l : (third == 1) ? Q1l : Q2l;
#pragma unroll
    for (int i = 0; i < 4; i++) {
#pragma unroll
        for (int j = 0; j < 4; j++) {
            int gr = rowBase + warpM * 64 + i * 16 + (lane >> 2);
            int cw = warpN * 32 + j * 8 + (lane & 3) * 2;
            int gc = ncol0 + cw;
            float2 b2 = *(const float2*)&bias[nBase + cw];
            float v0 = acc[i][j][0] + b2.x, v1 = acc[i][j][1] + b2.y;
            float v2 = acc[i][j][2] + b2.x, v3 = acc[i][j][3] + b2.y;
            if (mode == 0) {
                if (relu) {
                    v0 = fmaxf(v0, 0.f); v1 = fmaxf(v1, 0.f);
                    v2 = fmaxf(v2, 0.f); v3 = fmaxf(v3, 0.f);
                }
                float2 o0; o0.x = v0; o0.y = v1;
                float2 o1; o1.x = v2; o1.y = v3;
                *(float2*)&C[(size_t)gr * DD + gc]       = o0;
                *(float2*)&C[(size_t)(gr + 8) * DD + gc] = o1;
            } else {
                float h0 = __bfloat162float(__float2bfloat16(v0));
                float h1 = __bfloat162float(__float2bfloat16(v1));
                float h2 = __bfloat162float(__float2bfloat16(v2));
                float h3 = __bfloat162float(__float2bfloat16(v3));
                *(uint32_t*)&Ch[(size_t)gr * DD + gc]       = pk_bf2(h0, h1);
                *(uint32_t*)&Ch[(size_t)(gr + 8) * DD + gc] = pk_bf2(h2, h3);
                *(uint32_t*)&Cl[(size_t)gr * DD + gc]       = pk_bf2(v0 - h0, v1 - h1);
                *(uint32_t*)&Cl[(size_t)(gr + 8) * DD + gc] = pk_bf2(v2 - h2, v3 - h3);
            }
        }
    }
}

// =================== tensor-core flash attention (cp.async pipelined) =======
#define AP    144
#define OQH   0
#define OQL   9216
#define OK0   18432              // K buffers (hi at +0, lo at +9216), 2x18432
#define OVR0  55296              // V raw buffers, 2x18432
#define OVT   92160              // V transposed (hi +0, lo +9216)
#define ATT_SMEM 110592

__global__ __launch_bounds__(128) void attn_mma(
    const __nv_bfloat16* __restrict__ qh, const __nv_bfloat16* __restrict__ ql,
    const __nv_bfloat16* __restrict__ kh, const __nv_bfloat16* __restrict__ kl,
    const __nv_bfloat16* __restrict__ vh, const __nv_bfloat16* __restrict__ vl,
    const float* __restrict__ adj, const int* __restrict__ use_adj_p,
    __nv_bfloat16* __restrict__ ch, __nv_bfloat16* __restrict__ cl)
{
    extern __shared__ char smx[];
    const uint32_t sbase = smem_u32(smx);
    const int tid = threadIdx.x, warp = tid >> 5, lane = tid & 31;
    const int bh = blockIdx.y;
    const int b = bh >> 3, hd = bh & 7;
    const int q0 = blockIdx.x * 64;
    const int use_adj = (*use_adj_p) != 0;

    const int rq = lane & 7, grp = lane >> 3;
    const int mrow = ((grp & 1) << 3) + rq;
    const int kg16 = (grp >> 1) << 4;
    const int lane2 = lane & 3, r0 = lane >> 2;

    // ---- Q tile (hi+lo) once
#pragma unroll
    for (int s = 0; s < 4; s++) {
        int idx = tid + s * 128;
        int r = idx >> 3, seg = idx & 7;
        size_t gb = ((size_t)(b * NN + q0 + r)) * DD + hd * DKK + seg * 8;
        *(uint4*)(smx + OQH + r * AP + seg * 16) = *(const uint4*)(qh + gb);
        *(uint4*)(smx + OQL + r * AP + seg * 16) = *(const uint4*)(ql + gb);
    }

    auto issue_kv = [&](int cc, int buf) {
        const int k0c = cc * 64;
        const uint32_t okb = sbase + OK0  + buf * 18432;
        const uint32_t ovb = sbase + OVR0 + buf * 18432;
#pragma unroll
        for (int s = 0; s < 16; s++) {
            int idx = tid + s * 128;          // 0..2047
            int which = idx >> 9;
            int t = idx & 511;
            int r = t >> 3, seg = t & 7;
            const __nv_bfloat16* g = (which == 0) ? kh : (which == 1) ? kl
                                   : (which == 2) ? vh : vl;
            uint32_t base = (which == 0) ? okb : (which == 1) ? okb + 9216
                          : (which == 2) ? ovb : ovb + 9216;
            const char* gp = (const char*)(g + ((size_t)(b * NN + k0c + r)) * DD + hd * DKK) + seg * 16;
            asm volatile("cp.async.cg.shared.global [%0], [%1], 16;"
                         :: "r"(base + r * AP + seg * 16), "l"(gp) : "memory");
        }
        asm volatile("cp.async.commit_group;" ::: "memory");
    };

    float m0 = -1e30f, m1 = -1e30f, l0 = 0.f, l1 = 0.f;
    float ca[8][4];
#pragma unroll
    for (int j = 0; j < 8; j++)
#pragma unroll
        for (int e = 0; e < 4; e++) ca[j][e] = 0.f;

    issue_kv(0, 0);
    for (int cchunk = 0; cchunk < 8; cchunk++) {
        const int buf = cchunk & 1;
        const int k0c = cchunk * 64;
        if (cchunk < 7) issue_kv(cchunk + 1, buf ^ 1);
        if (cchunk < 7) asm volatile("cp.async.wait_group 1;" ::: "memory");
        else            asm volatile("cp.async.wait_group 0;" ::: "memory");
        __syncthreads();

        // ---- adj mask bits via direct LDG (overlaps with transpose + MMAs)
        uint32_t mk0 = 0xFFFFFFFFu, mk1 = 0xFFFFFFFFu;
        if (use_adj) {
            mk0 = 0; mk1 = 0;
            const float* ab = adj + ((size_t)b * NN + q0 + warp * 16 + r0) * NN + k0c + lane2 * 2;
#pragma unroll
            for (int j = 0; j < 8; j++) {
                float2 a0 = *(const float2*)(ab + j * 8);
                float2 a1 = *(const float2*)(ab + 8 * NN + j * 8);
                mk0 |= (a0.x > 0.f ? 1u : 0u) << (2 * j) | (a0.y > 0.f ? 1u : 0u) << (2 * j + 1);
                mk1 |= (a1.x > 0.f ? 1u : 0u) << (2 * j) | (a1.y > 0.f ? 1u : 0u) << (2 * j + 1);
            }
        }

        // ---- transpose V raw -> Vt (smem->smem, byte_perm pack)
        {
            const char* vrh = smx + OVR0 + buf * 18432;
            const char* vrl = vrh + 9216;
#pragma unroll
            for (int s = 0; s < 4; s++) {
                int idx = tid + s * 128;
                int kp = idx & 31, dq = idx >> 5;
                uint2 a  = *(const uint2*)(vrh + (2 * kp) * AP + dq * 8);
                uint2 b2 = *(const uint2*)(vrh + (2 * kp + 1) * AP + dq * 8);
                char* vt = smx + OVT + kp * 4;
                *(uint32_t*)(vt + (dq * 4 + 0) * AP) = __byte_perm(a.x, b2.x, 0x5410);
                *(uint32_t*)(vt + (dq * 4 + 1) * AP) = __byte_perm(a.x, b2.x, 0x7632);
                *(uint32_t*)(vt + (dq * 4 + 2) * AP) = __byte_perm(a.y, b2.y, 0x5410);
                *(uint32_t*)(vt + (dq * 4 + 3) * AP) = __byte_perm(a.y, b2.y, 0x7632);
                a  = *(const uint2*)(vrl + (2 * kp) * AP + dq * 8);
                b2 = *(const uint2*)(vrl + (2 * kp + 1) * AP + dq * 8);
                vt = smx + OVT + 9216 + kp * 4;
                *(uint32_t*)(vt + (dq * 4 + 0) * AP) = __byte_perm(a.x, b2.x, 0x5410);
                *(uint32_t*)(vt + (dq * 4 + 1) * AP) = __byte_perm(a.x, b2.x, 0x7632);
                *(uint32_t*)(vt + (dq * 4 + 2) * AP) = __byte_perm(a.y, b2.y, 0x5410);
                *(uint32_t*)(vt + (dq * 4 + 3) * AP) = __byte_perm(a.y, b2.y, 0x7632);
            }
        }
        __syncthreads();

        // ---- S = Q K^T (3-term split)
        const uint32_t okh = sbase + OK0 + buf * 18432;
        const uint32_t okl = okh + 9216;
        float sa[8][4];
#pragma unroll
        for (int j = 0; j < 8; j++)
#pragma unroll
            for (int e = 0; e < 4; e++) sa[j][e] = 0.f;

#pragma unroll
        for (int ks = 0; ks < 4; ks++) {
            const int kof = ks * 32 + kg16;
            uint32_t aH[4], aL[4];
            uint32_t ad = sbase + OQH + (uint32_t)(warp * 16 + mrow) * AP + kof;
            LDSM4(aH[0], aH[1], aH[2], aH[3], ad);
            ad = sbase + OQL + (uint32_t)(warp * 16 + mrow) * AP + kof;
            LDSM4(aL[0], aL[1], aL[2], aL[3], ad);
#pragma unroll
            for (int jj = 0; jj < 4; jj++) {
                uint32_t bH[2][2], bL[2][2], t0, t1, t2, t3;
                uint32_t bd = okh + (uint32_t)(jj * 16 + mrow) * AP + kof;
                LDSM4(t0, t1, t2, t3, bd);
                bH[0][0] = t0; bH[1][0] = t1; bH[0][1] = t2; bH[1][1] = t3;
                bd = okl + (uint32_t)(jj * 16 + mrow) * AP + kof;
                LDSM4(t0, t1, t2, t3, bd);
                bL[0][0] = t0; bL[1][0] = t1; bL[0][1] = t2; bL[1][1] = t3;
                MMA_OP(sa[2 * jj],     aH, bH[0]); MMA_OP(sa[2 * jj + 1], aH, bH[1]);
                MMA_OP(sa[2 * jj],     aL, bH[0]); MMA_OP(sa[2 * jj + 1], aL, bH[1]);
                MMA_OP(sa[2 * jj],     aH, bL[0]); MMA_OP(sa[2 * jj + 1], aH, bL[1]);
            }
        }

        // ---- mask + scale (masked -> 0.0)
#pragma unroll
        for (int j = 0; j < 8; j++) {
            sa[j][0] = (mk0 >> (2 * j)     & 1u) ? sa[j][0] * SCALE : 0.f;
            sa[j][1] = (mk0 >> (2 * j + 1) & 1u) ? sa[j][1] * SCALE : 0.f;
            sa[j][2] = (mk1 >> (2 * j)     & 1u) ? sa[j][2] * SCALE : 0.f;
            sa[j][3] = (mk1 >> (2 * j + 1) & 1u) ? sa[j][3] * SCALE : 0.f;
        }

        // ---- online softmax
        float cm0 = -1e30f, cm1 = -1e30f;
#pragma unroll
        for (int j = 0; j < 8; j++) {
            cm0 = fmaxf(cm0, fmaxf(sa[j][0], sa[j][1]));
            cm1 = fmaxf(cm1, fmaxf(sa[j][2], sa[j][3]));
        }
        cm0 = fmaxf(cm0, __shfl_xor_sync(0xffffffffu, cm0, 1));
        cm0 = fmaxf(cm0, __shfl_xor_sync(0xffffffffu, cm0, 2));
        cm1 = fmaxf(cm1, __shfl_xor_sync(0xffffffffu, cm1, 1));
        cm1 = fmaxf(cm1, __shfl_xor_sync(0xffffffffu, cm1, 2));
        float mn0 = fmaxf(m0, cm0), mn1 = fmaxf(m1, cm1);
        float sc0 = fexp(m0 - mn0), sc1 = fexp(m1 - mn1);
        float cs0 = 0.f, cs1 = 0.f;
#pragma unroll
        for (int j = 0; j < 8; j++) {
            sa[j][0] = fexp(sa[j][0] - mn0);
            sa[j][1] = fexp(sa[j][1] - mn0);
            sa[j][2] = fexp(sa[j][2] - mn1);
            sa[j][3] = fexp(sa[j][3] - mn1);
            cs0 += sa[j][0] + sa[j][1];
            cs1 += sa[j][2] + sa[j][3];
        }
        cs0 += __shfl_xor_sync(0xffffffffu, cs0, 1);
        cs0 += __shfl_xor_sync(0xffffffffu, cs0, 2);
        cs1 += __shfl_xor_sync(0xffffffffu, cs1, 1);
        cs1 += __shfl_xor_sync(0xffffffffu, cs1, 2);
        l0 = l0 * sc0 + cs0; m0 = mn0;
        l1 = l1 * sc1 + cs1; m1 = mn1;
#pragma unroll
        for (int j = 0; j < 8; j++) {
            ca[j][0] *= sc0; ca[j][1] *= sc0;
            ca[j][2] *= sc1; ca[j][3] *= sc1;
        }

        // ---- ctx += P @ V
#pragma unroll
        for (int ks = 0; ks < 4; ks++) {
            uint32_t aH[4], aL[4];
            {
                float p0 = sa[2 * ks][0], p1 = sa[2 * ks][1];
                float p2 = sa[2 * ks][2], p3 = sa[2 * ks][3];
                float p4 = sa[2 * ks + 1][0], p5 = sa[2 * ks + 1][1];
                float p6 = sa[2 * ks + 1][2], p7 = sa[2 * ks + 1][3];
                float h0 = __bfloat162float(__float2bfloat16(p0));
                float h1 = __bfloat162float(__float2bfloat16(p1));
                float h2 = __bfloat162float(__float2bfloat16(p2));
                float h3 = __bfloat162float(__float2bfloat16(p3));
                float h4 = __bfloat162float(__float2bfloat16(p4));
                float h5 = __bfloat162float(__float2bfloat16(p5));
                float h6 = __bfloat162float(__float2bfloat16(p6));
                float h7 = __bfloat162float(__float2bfloat16(p7));
                aH[0] = pk_bf2(h0, h1); aH[1] = pk_bf2(h2, h3);
                aH[2] = pk_bf2(h4, h5); aH[3] = pk_bf2(h6, h7);
                aL[0] = pk_bf2(p0 - h0, p1 - h1); aL[1] = pk_bf2(p2 - h2, p3 - h3);
                aL[2] = pk_bf2(p4 - h4, p5 - h5); aL[3] = pk_bf2(p6 - h6, p7 - h7);
            }
            const int kof = ks * 32 + kg16;
#pragma unroll
            for (int jj = 0; jj < 4; jj++) {
                uint32_t bH[2][2], bL[2][2], t0, t1, t2, t3;
                uint32_t bd = sbase + OVT + (uint32_t)(jj * 16 + mrow) * AP + kof;
                LDSM4(t0, t1, t2, t3, bd);
                bH[0][0] = t0; bH[1][0] = t1; bH[0][1] = t2; bH[1][1] = t3;
                bd = sbase + OVT + 9216 + (uint32_t)(jj * 16 + mrow) * AP + kof;
                LDSM4(t0, t1, t2, t3, bd);
                bL[0][0] = t0; bL[1][0] = t1; bL[0][1] = t2; bL[1][1] = t3;
                MMA_OP(ca[2 * jj],     aH, bH[0]); MMA_OP(ca[2 * jj + 1], aH, bH[1]);
                MMA_OP(ca[2 * jj],     aL, bH[0]); MMA_OP(ca[2 * jj + 1], aL, bH[1]);
                MMA_OP(ca[2 * jj],     aH, bL[0]); MMA_OP(ca[2 * jj + 1], aH, bL[1]);
            }
        }
    }

    // ---- epilogue
    const float inv0 = 1.f / l0, inv1 = 1.f / l1;
    const int qr0 = q0 + warp * 16 + r0;
#pragma unroll
    for (int j = 0; j < 8; j++) {
        int d = j * 8 + lane2 * 2;
        size_t b0 = ((size_t)(b * NN + qr0)) * DD + hd * DKK + d;
        size_t b1 = b0 + 8 * DD;
        float v0 = ca[j][0] * inv0, v1 = ca[j][1] * inv0;
        float v2 = ca[j][2] * inv1, v3 = ca[j][3] * inv1;
        float h0 = __bfloat162float(__float2bfloat16(v0));
        float h1 = __bfloat162float(__float2bfloat16(v1));
        float h2 = __bfloat162float(__float2bfloat16(v2));
        float h3 = __bfloat162float(__float2bfloat16(v3));
        *(uint32_t*)&ch[b0] = pk_bf2(h0, h1);
        *(uint32_t*)&ch[b1] = pk_bf2(h2, h3);
        *(uint32_t*)&cl[b0] = pk_bf2(v0 - h0, v1 - h1);
        *(uint32_t*)&cl[b1] = pk_bf2(v2 - h2, v3 - h3);
    }
}

// ---------------- helpers ----------------------------------------------------
__global__ __launch_bounds__(256) void conv_split(
    const float4* __restrict__ in, __nv_bfloat162* __restrict__ hi,
    __nv_bfloat162* __restrict__ lo, int n4)
{
    int i = blockIdx.x * 256 + threadIdx.x;
    if (i >= n4) return;
    float4 v = in[i];
    __nv_bfloat16 h0 = __float2bfloat16(v.x), h1 = __float2bfloat16(v.y);
    __nv_bfloat16 h2 = __float2bfloat16(v.z), h3 = __float2bfloat16(v.w);
    __nv_bfloat162 a, b, c, d;
    a.x = h0; a.y = h1; b.x = h2; b.y = h3;
    c.x = __float2bfloat16(v.x - __bfloat162float(h0));
    c.y = __float2bfloat16(v.y - __bfloat162float(h1));
    d.x = __float2bfloat16(v.z - __bfloat162float(h2));
    d.y = __float2bfloat16(v.w - __bfloat162float(h3));
    hi[2 * i] = a; hi[2 * i + 1] = b;
    lo[2 * i] = c; lo[2 * i + 1] = d;
}

__global__ __launch_bounds__(256) void wtrans(
    const float* __restrict__ W, __nv_bfloat16* __restrict__ th,
    __nv_bfloat16* __restrict__ tl)
{
    __shared__ float t[32][33];
    const int k0 = blockIdx.y * 32, n0 = blockIdx.x * 32;
    const int tx = threadIdx.x & 31, ty = threadIdx.x >> 5;
#pragma unroll
    for (int i = 0; i < 32; i += 8)
        t[ty + i][tx] = W[(size_t)(k0 + ty + i) * DD + n0 + tx];
    __syncthreads();
#pragma unroll
    for (int i = 0; i < 32; i += 8) {
        float v = t[tx][ty + i];
        __nv_bfloat16 h = __float2bfloat16(v);
        __nv_bfloat16 l = __float2bfloat16(v - __bfloat162float(h));
        size_t o = (size_t)(n0 + ty + i) * DD + k0 + tx;
        th[o] = h; tl[o] = l;
    }
}

__global__ __launch_bounds__(256) void pack_bias(
    const float* __restrict__ bq, const float* __restrict__ bk,
    const float* __restrict__ bv, float* __restrict__ o)
{
    int t = blockIdx.x * 256 + threadIdx.x;
    if (t < 512)       o[t] = bq[t];
    else if (t < 1024) o[t] = bk[t - 512];
    else if (t < 1536) o[t] = bv[t - 1024];
}

__global__ __launch_bounds__(256) void ln2_kernel(
    const float* __restrict__ h, const float* __restrict__ g, const float* __restrict__ b,
    __nv_bfloat16* __restrict__ hh, __nv_bfloat16* __restrict__ hl)
{
    const int r = blockIdx.x;
    const float* row = h + (size_t)r * DD;
    const int t = threadIdx.x;
    float v0 = row[t], v1 = row[t + 256];

    __shared__ float red[8];
    __shared__ float s_mu, s_rs;
    float s = v0 + v1;
#pragma unroll
    for (int o = 16; o; o >>= 1) s += __shfl_xor_sync(0xffffffffu, s, o);
    if ((t & 31) == 0) red[t >> 5] = s;
    __syncthreads();
    if (t == 0) {
        float tot = 0.f;
#pragma unroll
        for (int i = 0; i < 8; i++) tot += red[i];
        s_mu = tot * (1.f / DD);
    }
    __syncthreads();
    const float mu = s_mu;
    float d0 = v0 - mu, d1 = v1 - mu;
    float s2 = d0 * d0 + d1 * d1;
#pragma unroll
    for (int o = 16; o; o >>= 1) s2 += __shfl_xor_sync(0xffffffffu, s2, o);
    if ((t & 31) == 0) red[t >> 5] = s2;
    __syncthreads();
    if (t == 0) {
        float tot = 0.f;
#pragma unroll
        for (int i = 0; i < 8; i++) tot += red[i];
        s_rs = rsqrtf(tot * (1.f / DD) + LN_EPS);
    }
    __syncthreads();
    const float rs = s_rs;
    float y0 = d0 * rs * g[t] + b[t];
    float y1 = d1 * rs * g[t + 256] + b[t + 256];
    size_t base = (size_t)r * DD;
    __nv_bfloat16 a0 = __float2bfloat16(y0);
    __nv_bfloat16 a1 = __float2bfloat16(y1);
    hh[base + t] = a0;       hl[base + t] = __float2bfloat16(y0 - __bfloat162float(a0));
    hh[base + t + 256] = a1; hl[base + t + 256] = __float2bfloat16(y1 - __bfloat162float(a1));
}

__global__ __launch_bounds__(256) void gate_kernel(
    const float* __restrict__ x, const float* __restrict__ h2,
    const float* __restrict__ gw, const float* __restrict__ gb,
    float* __restrict__ out)
{
    const int r = blockIdx.x;
    const size_t base = (size_t)r * DD;
    const int t = threadIdx.x;
    float x0 = x[base + t], x1 = x[base + t + 256];
    float h0 = h2[base + t], h1 = h2[base + t + 256];
    float s = x0 * gw[t] + x1 * gw[t + 256] + h0 * gw[512 + t] + h1 * gw[768 + t];

    __shared__ float red[8];
    __shared__ float s_c;
#pragma unroll
    for (int o = 16; o; o >>= 1) s += __shfl_xor_sync(0xffffffffu, s, o);
    if ((t & 31) == 0) red[t >> 5] = s;
    __syncthreads();
    if (t == 0) {
        float tot = 0.f;
#pragma unroll
        for (int i = 0; i < 8; i++) tot += red[i];
        s_c = 1.f / (1.f + expf(-(tot + gb[0])));
    }
    __syncthreads();
    const float c = s_c;
    out[base + t]       = c * x0 + (1.f - c) * h0;
    out[base + t + 256] = c * x1 + (1.f - c) * h1;
}

// ---------------- launch ----------------------------------------------------
extern "C" void kernel_launch(void* const* d_in, const int* in_sizes, int n_in,
                              void* d_out, int out_size)
{
    const float* x    = (const float*)d_in[0];
    const float* adj  = (const float*)d_in[1];
    const float* W_w  = (const float*)d_in[2];
    const float* W_b  = (const float*)d_in[3];
    const float* ln_g = (const float*)d_in[4];
    const float* ln_b = (const float*)d_in[5];
    const float* Wq   = (const float*)d_in[6];
    const float* bq   = (const float*)d_in[7];
    const float* Wk   = (const float*)d_in[8];
    const float* bk   = (const float*)d_in[9];
    const float* Wv   = (const float*)d_in[10];
    const float* bv   = (const float*)d_in[11];
    const float* Wo   = (const float*)d_in[12];
    const float* bo   = (const float*)d_in[13];
    const float* gw   = (const float*)d_in[14];
    const float* gb   = (const float*)d_in[15];
    const int*   uadj = (const int*)d_in[16];
    float* out = (float*)d_out;

    float *h, *h2, *bqkv;
    __nv_bfloat16 *xh, *xl, *hh, *hl, *qh, *ql, *kh, *kl, *vh, *vl, *ch, *cl, *wth, *wtl;
    cudaGetSymbolAddress((void**)&h,  g_h);
    cudaGetSymbolAddress((void**)&h2, g_h2);
    cudaGetSymbolAddress((void**)&bqkv, g_bqkv);
    cudaGetSymbolAddress((void**)&xh, g_xh);
    cudaGetSymbolAddress((void**)&xl, g_xl);
    cudaGetSymbolAddress((void**)&hh, g_hh);
    cudaGetSymbolAddress((void**)&hl, g_hl);
    cudaGetSymbolAddress((void**)&qh, g_qh);
    cudaGetSymbolAddress((void**)&ql, g_ql);
    cudaGetSymbolAddress((void**)&kh, g_kh);
    cudaGetSymbolAddress((void**)&kl, g_kl);
    cudaGetSymbolAddress((void**)&vh, g_vh);
    cudaGetSymbolAddress((void**)&vl, g_vl);
    cudaGetSymbolAddress((void**)&ch, g_ch);
    cudaGetSymbolAddress((void**)&cl, g_cl);
    cudaGetSymbolAddress((void**)&wth, g_wth);
    cudaGetSymbolAddress((void**)&wtl, g_wtl);

    cudaFuncSetAttribute(mma_gemm,
                         cudaFuncAttributeMaxDynamicSharedMemorySize, GEMM_SMEM);
    cudaFuncSetAttribute(attn_mma,
                         cudaFuncAttributeMaxDynamicSharedMemorySize, ATT_SMEM);

    const int n4 = MM * DD / 4;
    dim3 gT(16, 16);
    // launch order chosen so ncu (-s 5 -c 1) captures the first big GEMM (#6)
    conv_split<<<(n4 + 255) / 256, 256>>>((const float4*)x,
                                          (__nv_bfloat162*)xh, (__nv_bfloat162*)xl, n4);  // 1
    wtrans<<<gT, 256>>>(W_w, wth + 0 * DD * DD, wtl + 0 * DD * DD);                        // 2
    wtrans<<<gT, 256>>>(Wq,  wth + 1 * DD * DD, wtl + 1 * DD * DD);                        // 3
    wtrans<<<gT, 256>>>(Wk,  wth + 2 * DD * DD, wtl + 2 * DD * DD);                        // 4
    wtrans<<<gT, 256>>>(Wv,  wth + 3 * DD * DD, wtl + 3 * DD * DD);                        // 5

    mma_gemm<<<dim3(4, 64), 256, GEMM_SMEM>>>(xh, xl,                                      // 6
        wth + 0 * DD * DD, wtl + 0 * DD * DD, W_b, h,
        nullptr, nullptr, nullptr, nullptr, nullptr, nullptr, 0, 0);
    ln2_kernel<<<MM, 256>>>(h, ln_g, ln_b, hh, hl);                                        // 7
    pack_bias<<<6, 256>>>(bq, bk, bv, bqkv);                                               // 8
    mma_gemm<<<dim3(12, 64), 256, GEMM_SMEM>>>(hh, hl,                                     // 9: fused QKV
        wth + 1 * DD * DD, wtl + 1 * DD * DD, bqkv, nullptr,
        qh, ql, kh, kl, vh, vl, 0, 1);
    attn_mma<<<dim3(NN / 64, BB * HH), 128, ATT_SMEM>>>(qh, ql, kh, kl, vh, vl,            // 10
                                                        adj, uadj, ch, cl);
    wtrans<<<gT, 256>>>(Wo,  wth + 4 * DD * DD, wtl + 4 * DD * DD);                        // 11
    mma_gemm<<<dim3(4, 64), 256, GEMM_SMEM>>>(ch, cl,                                      // 12
        wth + 4 * DD * DD, wtl + 4 * DD * DD, bo, h2,
        nullptr, nullptr, nullptr, nullptr, nullptr, nullptr, 1, 0);
    gate_kernel<<<MM, 256>>>(x, h2, gw, gb, out);                                          // 13
}

// round 11
// speedup vs baseline: 2.0274x; 1.0629x over previous
#include <cuda_runtime.h>
#include <cuda_bf16.h>
#include <cstdint>
#include <math.h>

#define BB 16
#define NN 512
#define DD 512
#define HH 8
#define DKK 64
#define MM (BB*NN)          // 8192 rows
#define SCALE 0.125f
#define LN_EPS 1e-5f

// ---------------- scratch (device globals; no allocs allowed) ----------------
__device__ float g_h [MM*DD];
__device__ float g_h2[MM*DD];
__device__ float g_bqkv[3*DD];
__device__ __nv_bfloat16 g_xh[MM*DD], g_xl[MM*DD];
__device__ __nv_bfloat16 g_hh[MM*DD], g_hl[MM*DD];
__device__ __nv_bfloat16 g_qh[MM*DD], g_ql[MM*DD];
__device__ __nv_bfloat16 g_kh[MM*DD], g_kl[MM*DD];
__device__ __nv_bfloat16 g_vth[MM*DD], g_vtl[MM*DD];   // V transposed [b*8+h][64][512]
__device__ __nv_bfloat16 g_ch[MM*DD], g_cl[MM*DD];
__device__ __nv_bfloat16 g_wth[5*DD*DD], g_wtl[5*DD*DD];

__device__ __forceinline__ uint32_t smem_u32(const void* p) {
    uint32_t a;
    asm("{ .reg .u64 t; cvta.to.shared.u64 t, %1; cvt.u32.u64 %0, t; }"
        : "=r"(a) : "l"(p));
    return a;
}

// fast exp on FMA pipe
__device__ __forceinline__ float fexp(float x) {
    x = fmaxf(x, -80.f);
    float y = x * 1.4426950408889634f;
    int   i = __float2int_rd(y);
    float r = y - __int2float_rn(i);
    float q = 1.5403530e-4f;
    q = q * r + 1.3333558e-3f;
    q = q * r + 9.6181291e-3f;
    q = q * r + 5.5504109e-2f;
    q = q * r + 2.4022651e-1f;
    q = q * r + 6.9314718e-1f;
    q = q * r + 1.0f;
    return __int_as_float(__float_as_int(q) + (i << 23));
}

#define MMA_OP(acc, A, B) asm volatile(                                        \
    "mma.sync.aligned.m16n8k16.row.col.f32.bf16.bf16.f32 "                     \
    "{%0,%1,%2,%3}, {%4,%5,%6,%7}, {%8,%9}, {%0,%1,%2,%3};"                    \
    : "+f"((acc)[0]), "+f"((acc)[1]), "+f"((acc)[2]), "+f"((acc)[3])           \
    : "r"((A)[0]), "r"((A)[1]), "r"((A)[2]), "r"((A)[3]),                      \
      "r"((B)[0]), "r"((B)[1]))

#define LDSM4(r0, r1, r2, r3, ad) asm volatile(                                \
    "ldmatrix.sync.aligned.m8n8.x4.shared.b16 {%0,%1,%2,%3}, [%4];"            \
    : "=r"(r0), "=r"(r1), "=r"(r2), "=r"(r3) : "r"(ad))

__device__ __forceinline__ uint32_t pk_bf2(float lo, float hi) {
    uint32_t u;
    asm("cvt.rn.bf16x2.f32 %0, %1, %2;" : "=r"(u) : "f"(hi), "f"(lo));
    return u;
}

// =================== mma.sync bf16-split GEMM ===============================
// CTA 128(M) x 128(N), 256 threads (2x4 warps, warp tile 64x32), K chunks 32.
// mode 0: fp32 out (+opt relu). mode 1: QKV split out (V stored transposed).
#define PITCHB 80
#define OFF_AL 10240
#define OFF_BH 20480
#define OFF_BL 30720
#define BUFSZ  40960
#define GEMM_SMEM (2*BUFSZ)          // 81920

__global__ __launch_bounds__(256, 2) void mma_gemm(
    const __nv_bfloat16* __restrict__ Ah, const __nv_bfloat16* __restrict__ Al,
    const __nv_bfloat16* __restrict__ Bh, const __nv_bfloat16* __restrict__ Bl,
    const float* __restrict__ bias, float* __restrict__ C,
    __nv_bfloat16* __restrict__ Q0h, __nv_bfloat16* __restrict__ Q0l,
    __nv_bfloat16* __restrict__ Q1h, __nv_bfloat16* __restrict__ Q1l,
    __nv_bfloat16* __restrict__ Q2h, __nv_bfloat16* __restrict__ Q2l,
    int relu, int mode)
{
    extern __shared__ char smx[];
    const uint32_t sbase = smem_u32(smx);
    const int tid = threadIdx.x, wid = tid >> 5, lane = tid & 31;
    const int rowBase = blockIdx.y * 128, nBase = blockIdx.x * 128;
    const int warpM = wid & 1, warpN = wid >> 1;     // 2 x 4

    float acc[4][4][4];
#pragma unroll
    for (int i = 0; i < 4; i++)
#pragma unroll
        for (int j = 0; j < 4; j++)
#pragma unroll
            for (int e = 0; e < 4; e++) acc[i][j][e] = 0.f;

    auto issue_load = [&](int c, int buf) {
        const int kc = c * 32;
#pragma unroll
        for (int s = 0; s < 8; s++) {
            int sid = tid + s * 256;       // 0..2047
            const __nv_bfloat16* g;
            int off;
            if (sid < 512)       { g = Ah; off = 0; }
            else if (sid < 1024) { g = Al; off = OFF_AL; }
            else if (sid < 1536) { g = Bh; off = OFF_BH; }
            else                 { g = Bl; off = OFF_BL; }
            int t = sid & 511;
            int r = t >> 2, seg = t & 3;
            int grow = (off < OFF_BH) ? (rowBase + r) : (nBase + r);
            uint32_t da = sbase + buf * BUFSZ + off + r * PITCHB + seg * 16;
            const char* gp = (const char*)(g + (size_t)grow * 512 + kc) + seg * 16;
            asm volatile("cp.async.cg.shared.global [%0], [%1], 16;"
                         :: "r"(da), "l"(gp) : "memory");
        }
        asm volatile("cp.async.commit_group;" ::: "memory");
    };

    issue_load(0, 0);
    for (int c = 0; c < 16; c++) {
        const int buf = c & 1;
        if (c < 15) issue_load(c + 1, buf ^ 1);
        if (c < 15) asm volatile("cp.async.wait_group 1;" ::: "memory");
        else        asm volatile("cp.async.wait_group 0;" ::: "memory");
        __syncthreads();

        const uint32_t bufb = sbase + buf * BUFSZ;
        const int rq = lane & 7, grp = lane >> 3;
        const int mrow = ((grp & 1) << 3) + rq;
#pragma unroll
        for (int ks = 0; ks < 2; ks++) {
            const int kof2 = (ks * 16 + ((grp >> 1) << 3)) * 2;
            uint32_t ah[4][4], bh_[4][2];
#pragma unroll
            for (int i = 0; i < 4; i++) {
                uint32_t ad = bufb + (uint32_t)(warpM * 64 + i * 16 + mrow) * PITCHB + kof2;
                LDSM4(ah[i][0], ah[i][1], ah[i][2], ah[i][3], ad);
            }
#pragma unroll
            for (int jj = 0; jj < 2; jj++) {
                uint32_t ad = bufb + OFF_BH +
                    (uint32_t)(warpN * 32 + jj * 16 + ((grp & 1) << 3) + rq) * PITCHB + kof2;
                uint32_t r0, r1, r2, r3;
                LDSM4(r0, r1, r2, r3, ad);
                bh_[2 * jj][0] = r0; bh_[2 * jj + 1][0] = r1;
                bh_[2 * jj][1] = r2; bh_[2 * jj + 1][1] = r3;
            }
#pragma unroll
            for (int i = 0; i < 4; i++)
#pragma unroll
                for (int j = 0; j < 4; j++) MMA_OP(acc[i][j], ah[i], bh_[j]);
            {
                uint32_t al_[4];
#pragma unroll
                for (int i = 0; i < 4; i++) {
                    uint32_t ad = bufb + OFF_AL +
                        (uint32_t)(warpM * 64 + i * 16 + mrow) * PITCHB + kof2;
                    LDSM4(al_[0], al_[1], al_[2], al_[3], ad);
#pragma unroll
                    for (int j = 0; j < 4; j++) MMA_OP(acc[i][j], al_, bh_[j]);
                }
            }
            {
                uint32_t bl_[4][2];
#pragma unroll
                for (int jj = 0; jj < 2; jj++) {
                    uint32_t ad = bufb + OFF_BL +
                        (uint32_t)(warpN * 32 + jj * 16 + ((grp & 1) << 3) + rq) * PITCHB + kof2;
                    uint32_t r0, r1, r2, r3;
                    LDSM4(r0, r1, r2, r3, ad);
                    bl_[2 * jj][0] = r0; bl_[2 * jj + 1][0] = r1;
                    bl_[2 * jj][1] = r2; bl_[2 * jj + 1][1] = r3;
                }
#pragma unroll
                for (int i = 0; i < 4; i++)
#pragma unroll
                    for (int j = 0; j < 4; j++) MMA_OP(acc[i][j], ah[i], bl_[j]);
            }
        }
        __syncthreads();
    }

    // ---- epilogue
    const int third = nBase >> 9;
    const int ncol0 = nBase & 511;
#pragma unroll
    for (int i = 0; i < 4; i++) {
#pragma unroll
        for (int j = 0; j < 4; j++) {
            int gr = rowBase + warpM * 64 + i * 16 + (lane >> 2);
            int cw = warpN * 32 + j * 8 + (lane & 3) * 2;
            int gc = ncol0 + cw;
            float2 b2 = *(const float2*)&bias[nBase + cw];
            float v0 = acc[i][j][0] + b2.x, v1 = acc[i][j][1] + b2.y;
            float v2 = acc[i][j][2] + b2.x, v3 = acc[i][j][3] + b2.y;
            if (mode == 0) {
                if (relu) {
                    v0 = fmaxf(v0, 0.f); v1 = fmaxf(v1, 0.f);
                    v2 = fmaxf(v2, 0.f); v3 = fmaxf(v3, 0.f);
                }
                float2 o0; o0.x = v0; o0.y = v1;
                float2 o1; o1.x = v2; o1.y = v3;
                *(float2*)&C[(size_t)gr * DD + gc]       = o0;
                *(float2*)&C[(size_t)(gr + 8) * DD + gc] = o1;
            } else if (third < 2) {
                __nv_bfloat16* Ch = (third == 0) ? Q0h : Q1h;
                __nv_bfloat16* Cl = (third == 0) ? Q0l : Q1l;
                float h0 = __bfloat162float(__float2bfloat16(v0));
                float h1 = __bfloat162float(__float2bfloat16(v1));
                float h2 = __bfloat162float(__float2bfloat16(v2));
                float h3 = __bfloat162float(__float2bfloat16(v3));
                *(uint32_t*)&Ch[(size_t)gr * DD + gc]       = pk_bf2(h0, h1);
                *(uint32_t*)&Ch[(size_t)(gr + 8) * DD + gc] = pk_bf2(h2, h3);
                *(uint32_t*)&Cl[(size_t)gr * DD + gc]       = pk_bf2(v0 - h0, v1 - h1);
                *(uint32_t*)&Cl[(size_t)(gr + 8) * DD + gc] = pk_bf2(v2 - h2, v3 - h3);
            } else {
                // V: store transposed Vt[b*8+h][d][n]  (d = head dim, n = token)
                int nr = gr & 511, bb = gr >> 9;
                int hh2 = gc >> 6, d0 = gc & 63;
                size_t rb = ((size_t)(bb * 8 + hh2) * 64 + d0) * 512;
                __nv_bfloat16 t0 = __float2bfloat16(v0);
                __nv_bfloat16 t1 = __float2bfloat16(v1);
                __nv_bfloat16 t2 = __float2bfloat16(v2);
                __nv_bfloat16 t3 = __float2bfloat16(v3);
                Q2h[rb + nr]           = t0;     // (d0,   nr)
                Q2h[rb + 512 + nr]     = t1;     // (d0+1, nr)
                Q2h[rb + nr + 8]       = t2;     // (d0,   nr+8)
                Q2h[rb + 512 + nr + 8] = t3;
                Q2l[rb + nr]           = __float2bfloat16(v0 - __bfloat162float(t0));
                Q2l[rb + 512 + nr]     = __float2bfloat16(v1 - __bfloat162float(t1));
                Q2l[rb + nr + 8]       = __float2bfloat16(v2 - __bfloat162float(t2));
                Q2l[rb + 512 + nr + 8] = __float2bfloat16(v3 - __bfloat162float(t3));
            }
        }
    }
}

// =================== tensor-core flash attention ============================
// K and Vt both cp.async double-buffered; Vt comes pre-transposed from the
// QKV GEMM epilogue, so no in-kernel transpose and only 1 sync per chunk.
#define AP    144
#define OQH   0
#define OQL   9216
#define OK0   18432              // 2 bufs x (hi 9216 + lo 9216)
#define OVT0  55296              // 2 bufs x (hi 9216 + lo 9216)
#define ATT_SMEM 92160

__global__ __launch_bounds__(128) void attn_mma(
    const __nv_bfloat16* __restrict__ qh, const __nv_bfloat16* __restrict__ ql,
    const __nv_bfloat16* __restrict__ kh, const __nv_bfloat16* __restrict__ kl,
    const __nv_bfloat16* __restrict__ vth, const __nv_bfloat16* __restrict__ vtl,
    const float* __restrict__ adj, const int* __restrict__ use_adj_p,
    __nv_bfloat16* __restrict__ ch, __nv_bfloat16* __restrict__ cl)
{
    extern __shared__ char smx[];
    const uint32_t sbase = smem_u32(smx);
    const int tid = threadIdx.x, warp = tid >> 5, lane = tid & 31;
    const int bh = blockIdx.y;
    const int b = bh >> 3, hd = bh & 7;
    const int q0 = blockIdx.x * 64;
    const int use_adj = (*use_adj_p) != 0;

    const int rq = lane & 7, grp = lane >> 3;
    const int mrow = ((grp & 1) << 3) + rq;
    const int kg16 = (grp >> 1) << 4;
    const int lane2 = lane & 3, r0 = lane >> 2;

    // ---- Q tile (hi+lo) once
#pragma unroll
    for (int s = 0; s < 4; s++) {
        int idx = tid + s * 128;
        int r = idx >> 3, seg = idx & 7;
        size_t gb = ((size_t)(b * NN + q0 + r)) * DD + hd * DKK + seg * 8;
        *(uint4*)(smx + OQH + r * AP + seg * 16) = *(const uint4*)(qh + gb);
        *(uint4*)(smx + OQL + r * AP + seg * 16) = *(const uint4*)(ql + gb);
    }

    auto issue_kv = [&](int cc, int buf) {
        const int k0c = cc * 64;
        const uint32_t okb = sbase + OK0  + buf * 18432;
        const uint32_t ovb = sbase + OVT0 + buf * 18432;
#pragma unroll
        for (int s = 0; s < 16; s++) {
            int idx = tid + s * 128;          // 0..2047
            int which = idx >> 9;
            int t = idx & 511;
            int r = t >> 3, seg = t & 7;
            const char* gp;
            uint32_t dst;
            if (which < 2) {                  // K rows = keys
                const __nv_bfloat16* g = which ? kl : kh;
                gp = (const char*)(g + ((size_t)(b * NN + k0c + r)) * DD + hd * DKK) + seg * 16;
                dst = okb + which * 9216 + r * AP + seg * 16;
            } else {                          // Vt rows = d, contiguous keys
                const __nv_bfloat16* g = (which == 2) ? vth : vtl;
                gp = (const char*)(g + ((size_t)bh * 64 + r) * 512 + k0c) + seg * 16;
                dst = ovb + (which - 2) * 9216 + r * AP + seg * 16;
            }
            asm volatile("cp.async.cg.shared.global [%0], [%1], 16;"
                         :: "r"(dst), "l"(gp) : "memory");
        }
        asm volatile("cp.async.commit_group;" ::: "memory");
    };

    float m0 = -1e30f, m1 = -1e30f, l0 = 0.f, l1 = 0.f;
    float ca[8][4];
#pragma unroll
    for (int j = 0; j < 8; j++)
#pragma unroll
        for (int e = 0; e < 4; e++) ca[j][e] = 0.f;

    issue_kv(0, 0);
    for (int cchunk = 0; cchunk < 8; cchunk++) {
        const int buf = cchunk & 1;
        const int k0c = cchunk * 64;
        asm volatile("cp.async.wait_group 0;" ::: "memory");
        __syncthreads();
        // prefetch next chunk into other buffer (safe: its readers synced above)
        if (cchunk < 7) issue_kv(cchunk + 1, buf ^ 1);

        // ---- adj mask bits via direct LDG (hidden under S MMAs)
        uint32_t mk0 = 0xFFFFFFFFu, mk1 = 0xFFFFFFFFu;
        if (use_adj) {
            mk0 = 0; mk1 = 0;
            const float* ab = adj + ((size_t)b * NN + q0 + warp * 16 + r0) * NN + k0c + lane2 * 2;
#pragma unroll
            for (int j = 0; j < 8; j++) {
                float2 a0 = *(const float2*)(ab + j * 8);
                float2 a1 = *(const float2*)(ab + 8 * NN + j * 8);
                mk0 |= (a0.x > 0.f ? 1u : 0u) << (2 * j) | (a0.y > 0.f ? 1u : 0u) << (2 * j + 1);
                mk1 |= (a1.x > 0.f ? 1u : 0u) << (2 * j) | (a1.y > 0.f ? 1u : 0u) << (2 * j + 1);
            }
        }

        // ---- S = Q K^T (3-term split)
        const uint32_t okh = sbase + OK0 + buf * 18432;
        const uint32_t okl = okh + 9216;
        float sa[8][4];
#pragma unroll
        for (int j = 0; j < 8; j++)
#pragma unroll
            for (int e = 0; e < 4; e++) sa[j][e] = 0.f;

#pragma unroll
        for (int ks = 0; ks < 4; ks++) {
            const int kof = ks * 32 + kg16;
            uint32_t aH[4], aL[4];
            uint32_t ad = sbase + OQH + (uint32_t)(warp * 16 + mrow) * AP + kof;
            LDSM4(aH[0], aH[1], aH[2], aH[3], ad);
            ad = sbase + OQL + (uint32_t)(warp * 16 + mrow) * AP + kof;
            LDSM4(aL[0], aL[1], aL[2], aL[3], ad);
#pragma unroll
            for (int jj = 0; jj < 4; jj++) {
                uint32_t bH[2][2], bL[2][2], t0, t1, t2, t3;
                uint32_t bd = okh + (uint32_t)(jj * 16 + mrow) * AP + kof;
                LDSM4(t0, t1, t2, t3, bd);
                bH[0][0] = t0; bH[1][0] = t1; bH[0][1] = t2; bH[1][1] = t3;
                bd = okl + (uint32_t)(jj * 16 + mrow) * AP + kof;
                LDSM4(t0, t1, t2, t3, bd);
                bL[0][0] = t0; bL[1][0] = t1; bL[0][1] = t2; bL[1][1] = t3;
                MMA_OP(sa[2 * jj],     aH, bH[0]); MMA_OP(sa[2 * jj + 1], aH, bH[1]);
                MMA_OP(sa[2 * jj],     aL, bH[0]); MMA_OP(sa[2 * jj + 1], aL, bH[1]);
                MMA_OP(sa[2 * jj],     aH, bL[0]); MMA_OP(sa[2 * jj + 1], aH, bL[1]);
            }
        }

        // ---- mask + scale (masked -> 0.0)
#pragma unroll
        for (int j = 0; j < 8; j++) {
            sa[j][0] = (mk0 >> (2 * j)     & 1u) ? sa[j][0] * SCALE : 0.f;
            sa[j][1] = (mk0 >> (2 * j + 1) & 1u) ? sa[j][1] * SCALE : 0.f;
            sa[j][2] = (mk1 >> (2 * j)     & 1u) ? sa[j][2] * SCALE : 0.f;
            sa[j][3] = (mk1 >> (2 * j + 1) & 1u) ? sa[j][3] * SCALE : 0.f;
        }

        // ---- online softmax
        float cm0 = -1e30f, cm1 = -1e30f;
#pragma unroll
        for (int j = 0; j < 8; j++) {
            cm0 = fmaxf(cm0, fmaxf(sa[j][0], sa[j][1]));
            cm1 = fmaxf(cm1, fmaxf(sa[j][2], sa[j][3]));
        }
        cm0 = fmaxf(cm0, __shfl_xor_sync(0xffffffffu, cm0, 1));
        cm0 = fmaxf(cm0, __shfl_xor_sync(0xffffffffu, cm0, 2));
        cm1 = fmaxf(cm1, __shfl_xor_sync(0xffffffffu, cm1, 1));
        cm1 = fmaxf(cm1, __shfl_xor_sync(0xffffffffu, cm1, 2));
        float mn0 = fmaxf(m0, cm0), mn1 = fmaxf(m1, cm1);
        float sc0 = fexp(m0 - mn0), sc1 = fexp(m1 - mn1);
        float cs0 = 0.f, cs1 = 0.f;
#pragma unroll
        for (int j = 0; j < 8; j++) {
            sa[j][0] = fexp(sa[j][0] - mn0);
            sa[j][1] = fexp(sa[j][1] - mn0);
            sa[j][2] = fexp(sa[j][2] - mn1);
            sa[j][3] = fexp(sa[j][3] - mn1);
            cs0 += sa[j][0] + sa[j][1];
            cs1 += sa[j][2] + sa[j][3];
        }
        cs0 += __shfl_xor_sync(0xffffffffu, cs0, 1);
        cs0 += __shfl_xor_sync(0xffffffffu, cs0, 2);
        cs1 += __shfl_xor_sync(0xffffffffu, cs1, 1);
        cs1 += __shfl_xor_sync(0xffffffffu, cs1, 2);
        l0 = l0 * sc0 + cs0; m0 = mn0;
        l1 = l1 * sc1 + cs1; m1 = mn1;
#pragma unroll
        for (int j = 0; j < 8; j++) {
            ca[j][0] *= sc0; ca[j][1] *= sc0;
            ca[j][2] *= sc1; ca[j][3] *= sc1;
        }

        // ---- ctx += P @ V  (Vt already [d][key] in smem)
        const uint32_t ovh = sbase + OVT0 + buf * 18432;
        const uint32_t ovl = ovh + 9216;
#pragma unroll
        for (int ks = 0; ks < 4; ks++) {
            uint32_t aH[4], aL[4];
            {
                float p0 = sa[2 * ks][0], p1 = sa[2 * ks][1];
                float p2 = sa[2 * ks][2], p3 = sa[2 * ks][3];
                float p4 = sa[2 * ks + 1][0], p5 = sa[2 * ks + 1][1];
                float p6 = sa[2 * ks + 1][2], p7 = sa[2 * ks + 1][3];
                float h0 = __bfloat162float(__float2bfloat16(p0));
                float h1 = __bfloat162float(__float2bfloat16(p1));
                float h2 = __bfloat162float(__float2bfloat16(p2));
                float h3 = __bfloat162float(__float2bfloat16(p3));
                float h4 = __bfloat162float(__float2bfloat16(p4));
                float h5 = __bfloat162float(__float2bfloat16(p5));
                float h6 = __bfloat162float(__float2bfloat16(p6));
                float h7 = __bfloat162float(__float2bfloat16(p7));
                aH[0] = pk_bf2(h0, h1); aH[1] = pk_bf2(h2, h3);
                aH[2] = pk_bf2(h4, h5); aH[3] = pk_bf2(h6, h7);
                aL[0] = pk_bf2(p0 - h0, p1 - h1); aL[1] = pk_bf2(p2 - h2, p3 - h3);
                aL[2] = pk_bf2(p4 - h4, p5 - h5); aL[3] = pk_bf2(p6 - h6, p7 - h7);
            }
            const int kof = ks * 32 + kg16;
#pragma unroll
            for (int jj = 0; jj < 4; jj++) {
                uint32_t bH[2][2], bL[2][2], t0, t1, t2, t3;
                uint32_t bd = ovh + (uint32_t)(jj * 16 + mrow) * AP + kof;
                LDSM4(t0, t1, t2, t3, bd);
                bH[0][0] = t0; bH[1][0] = t1; bH[0][1] = t2; bH[1][1] = t3;
                bd = ovl + (uint32_t)(jj * 16 + mrow) * AP + kof;
                LDSM4(t0, t1, t2, t3, bd);
                bL[0][0] = t0; bL[1][0] = t1; bL[0][1] = t2; bL[1][1] = t3;
                MMA_OP(ca[2 * jj],     aH, bH[0]); MMA_OP(ca[2 * jj + 1], aH, bH[1]);
                MMA_OP(ca[2 * jj],     aL, bH[0]); MMA_OP(ca[2 * jj + 1], aL, bH[1]);
                MMA_OP(ca[2 * jj],     aH, bL[0]); MMA_OP(ca[2 * jj + 1], aH, bL[1]);
            }
        }
    }

    // ---- epilogue
    const float inv0 = 1.f / l0, inv1 = 1.f / l1;
    const int qr0 = q0 + warp * 16 + r0;
#pragma unroll
    for (int j = 0; j < 8; j++) {
        int d = j * 8 + lane2 * 2;
        size_t b0 = ((size_t)(b * NN + qr0)) * DD + hd * DKK + d;
        size_t b1 = b0 + 8 * DD;
        float v0 = ca[j][0] * inv0, v1 = ca[j][1] * inv0;
        float v2 = ca[j][2] * inv1, v3 = ca[j][3] * inv1;
        float h0 = __bfloat162float(__float2bfloat16(v0));
        float h1 = __bfloat162float(__float2bfloat16(v1));
        float h2 = __bfloat162float(__float2bfloat16(v2));
        float h3 = __bfloat162float(__float2bfloat16(v3));
        *(uint32_t*)&ch[b0] = pk_bf2(h0, h1);
        *(uint32_t*)&ch[b1] = pk_bf2(h2, h3);
        *(uint32_t*)&cl[b0] = pk_bf2(v0 - h0, v1 - h1);
        *(uint32_t*)&cl[b1] = pk_bf2(v2 - h2, v3 - h3);
    }
}

// ---------------- helpers ----------------------------------------------------
__global__ __launch_bounds__(256) void conv_split(
    const float4* __restrict__ in, __nv_bfloat162* __restrict__ hi,
    __nv_bfloat162* __restrict__ lo, int n4)
{
    int i = blockIdx.x * 256 + threadIdx.x;
    if (i >= n4) return;
    float4 v = in[i];
    __nv_bfloat16 h0 = __float2bfloat16(v.x), h1 = __float2bfloat16(v.y);
    __nv_bfloat16 h2 = __float2bfloat16(v.z), h3 = __float2bfloat16(v.w);
    __nv_bfloat162 a, b, c, d;
    a.x = h0; a.y = h1; b.x = h2; b.y = h3;
    c.x = __float2bfloat16(v.x - __bfloat162float(h0));
    c.y = __float2bfloat16(v.y - __bfloat162float(h1));
    d.x = __float2bfloat16(v.z - __bfloat162float(h2));
    d.y = __float2bfloat16(v.w - __bfloat162float(h3));
    hi[2 * i] = a; hi[2 * i + 1] = b;
    lo[2 * i] = c; lo[2 * i + 1] = d;
}

// all 5 weight transposes in one launch (blockIdx.z selects the weight)
__global__ __launch_bounds__(256) void wtrans_all(
    const float* __restrict__ W0, const float* __restrict__ W1,
    const float* __restrict__ W2, const float* __restrict__ W3,
    const float* __restrict__ W4,
    __nv_bfloat16* __restrict__ th, __nv_bfloat16* __restrict__ tl)
{
    const int z = blockIdx.z;
    const float* W = (z == 0) ? W0 : (z == 1) ? W1 : (z == 2) ? W2 : (z == 3) ? W3 : W4;
    th += (size_t)z * DD * DD;
    tl += (size_t)z * DD * DD;

    __shared__ float t[32][33];
    const int k0 = blockIdx.y * 32, n0 = blockIdx.x * 32;
    const int tx = threadIdx.x & 31, ty = threadIdx.x >> 5;
#pragma unroll
    for (int i = 0; i < 32; i += 8)
        t[ty + i][tx] = W[(size_t)(k0 + ty + i) * DD + n0 + tx];
    __syncthreads();
#pragma unroll
    for (int i = 0; i < 32; i += 8) {
        float v = t[tx][ty + i];
        __nv_bfloat16 h = __float2bfloat16(v);
        __nv_bfloat16 l = __float2bfloat16(v - __bfloat162float(h));
        size_t o = (size_t)(n0 + ty + i) * DD + k0 + tx;
        th[o] = h; tl[o] = l;
    }
}

__global__ __launch_bounds__(256) void pack_bias(
    const float* __restrict__ bq, const float* __restrict__ bk,
    const float* __restrict__ bv, float* __restrict__ o)
{
    int t = blockIdx.x * 256 + threadIdx.x;
    if (t < 512)       o[t] = bq[t];
    else if (t < 1024) o[t] = bk[t - 512];
    else if (t < 1536) o[t] = bv[t - 1024];
}

__global__ __launch_bounds__(256) void ln2_kernel(
    const float* __restrict__ h, const float* __restrict__ g, const float* __restrict__ b,
    __nv_bfloat16* __restrict__ hh, __nv_bfloat16* __restrict__ hl)
{
    const int r = blockIdx.x;
    const float* row = h + (size_t)r * DD;
    const int t = threadIdx.x;
    float v0 = row[t], v1 = row[t + 256];

    __shared__ float red[8];
    __shared__ float s_mu, s_rs;
    float s = v0 + v1;
#pragma unroll
    for (int o = 16; o; o >>= 1) s += __shfl_xor_sync(0xffffffffu, s, o);
    if ((t & 31) == 0) red[t >> 5] = s;
    __syncthreads();
    if (t == 0) {
        float tot = 0.f;
#pragma unroll
        for (int i = 0; i < 8; i++) tot += red[i];
        s_mu = tot * (1.f / DD);
    }
    __syncthreads();
    const float mu = s_mu;
    float d0 = v0 - mu, d1 = v1 - mu;
    float s2 = d0 * d0 + d1 * d1;
#pragma unroll
    for (int o = 16; o; o >>= 1) s2 += __shfl_xor_sync(0xffffffffu, s2, o);
    if ((t & 31) == 0) red[t >> 5] = s2;
    __syncthreads();
    if (t == 0) {
        float tot = 0.f;
#pragma unroll
        for (int i = 0; i < 8; i++) tot += red[i];
        s_rs = rsqrtf(tot * (1.f / DD) + LN_EPS);
    }
    __syncthreads();
    const float rs = s_rs;
    float y0 = d0 * rs * g[t] + b[t];
    float y1 = d1 * rs * g[t + 256] + b[t + 256];
    size_t base = (size_t)r * DD;
    __nv_bfloat16 a0 = __float2bfloat16(y0);
    __nv_bfloat16 a1 = __float2bfloat16(y1);
    hh[base + t] = a0;       hl[base + t] = __float2bfloat16(y0 - __bfloat162float(a0));
    hh[base + t + 256] = a1; hl[base + t + 256] = __float2bfloat16(y1 - __bfloat162float(a1));
}

__global__ __launch_bounds__(256) void gate_kernel(
    const float* __restrict__ x, const float* __restrict__ h2,
    const float* __restrict__ gw, const float* __restrict__ gb,
    float* __restrict__ out)
{
    const int r = blockIdx.x;
    const size_t base = (size_t)r * DD;
    const int t = threadIdx.x;
    float x0 = x[base + t], x1 = x[base + t + 256];
    float h0 = h2[base + t], h1 = h2[base + t + 256];
    float s = x0 * gw[t] + x1 * gw[t + 256] + h0 * gw[512 + t] + h1 * gw[768 + t];

    __shared__ float red[8];
    __shared__ float s_c;
#pragma unroll
    for (int o = 16; o; o >>= 1) s += __shfl_xor_sync(0xffffffffu, s, o);
    if ((t & 31) == 0) red[t >> 5] = s;
    __syncthreads();
    if (t == 0) {
        float tot = 0.f;
#pragma unroll
        for (int i = 0; i < 8; i++) tot += red[i];
        s_c = 1.f / (1.f + expf(-(tot + gb[0])));
    }
    __syncthreads();
    const float c = s_c;
    out[base + t]       = c * x0 + (1.f - c) * h0;
    out[base + t + 256] = c * x1 + (1.f - c) * h1;
}

// ---------------- launch ----------------------------------------------------
extern "C" void kernel_launch(void* const* d_in, const int* in_sizes, int n_in,
                              void* d_out, int out_size)
{
    const float* x    = (const float*)d_in[0];
    const float* adj  = (const float*)d_in[1];
    const float* W_w  = (const float*)d_in[2];
    const float* W_b  = (const float*)d_in[3];
    const float* ln_g = (const float*)d_in[4];
    const float* ln_b = (const float*)d_in[5];
    const float* Wq   = (const float*)d_in[6];
    const float* bq   = (const float*)d_in[7];
    const float* Wk   = (const float*)d_in[8];
    const float* bk   = (const float*)d_in[9];
    const float* Wv   = (const float*)d_in[10];
    const float* bv   = (const float*)d_in[11];
    const float* Wo   = (const float*)d_in[12];
    const float* bo   = (const float*)d_in[13];
    const float* gw   = (const float*)d_in[14];
    const float* gb   = (const float*)d_in[15];
    const int*   uadj = (const int*)d_in[16];
    float* out = (float*)d_out;

    float *h, *h2, *bqkv;
    __nv_bfloat16 *xh, *xl, *hh, *hl, *qh, *ql, *kh, *kl, *vth, *vtl, *ch, *cl, *wth, *wtl;
    cudaGetSymbolAddress((void**)&h,  g_h);
    cudaGetSymbolAddress((void**)&h2, g_h2);
    cudaGetSymbolAddress((void**)&bqkv, g_bqkv);
    cudaGetSymbolAddress((void**)&xh, g_xh);
    cudaGetSymbolAddress((void**)&xl, g_xl);
    cudaGetSymbolAddress((void**)&hh, g_hh);
    cudaGetSymbolAddress((void**)&hl, g_hl);
    cudaGetSymbolAddress((void**)&qh, g_qh);
    cudaGetSymbolAddress((void**)&ql, g_ql);
    cudaGetSymbolAddress((void**)&kh, g_kh);
    cudaGetSymbolAddress((void**)&kl, g_kl);
    cudaGetSymbolAddress((void**)&vth, g_vth);
    cudaGetSymbolAddress((void**)&vtl, g_vtl);
    cudaGetSymbolAddress((void**)&ch, g_ch);
    cudaGetSymbolAddress((void**)&cl, g_cl);
    cudaGetSymbolAddress((void**)&wth, g_wth);
    cudaGetSymbolAddress((void**)&wtl, g_wtl);

    cudaFuncSetAttribute(mma_gemm,
                         cudaFuncAttributeMaxDynamicSharedMemorySize, GEMM_SMEM);
    cudaFuncSetAttribute(attn_mma,
                         cudaFuncAttributeMaxDynamicSharedMemorySize, ATT_SMEM);

    const int n4 = MM * DD / 4;
    conv_split<<<(n4 + 255) / 256, 256>>>((const float4*)x,
                                          (__nv_bfloat162*)xh, (__nv_bfloat162*)xl, n4); // 0
    wtrans_all<<<dim3(16, 16, 5), 256>>>(W_w, Wq, Wk, Wv, Wo, wth, wtl);                  // 1
    pack_bias<<<6, 256>>>(bq, bk, bv, bqkv);                                              // 2
    mma_gemm<<<dim3(4, 64), 256, GEMM_SMEM>>>(xh, xl,                                     // 3
        wth + 0 * DD * DD, wtl + 0 * DD * DD, W_b, h,
        nullptr, nullptr, nullptr, nullptr, nullptr, nullptr, 0, 0);
    ln2_kernel<<<MM, 256>>>(h, ln_g, ln_b, hh, hl);                                       // 4
    mma_gemm<<<dim3(12, 64), 256, GEMM_SMEM>>>(hh, hl,                                    // 5: fused QKV
        wth + 1 * DD * DD, wtl + 1 * DD * DD, bqkv, nullptr,
        qh, ql, kh, kl, vth, vtl, 0, 1);
    attn_mma<<<dim3(NN / 64, BB * HH), 128, ATT_SMEM>>>(qh, ql, kh, kl, vth, vtl,         // 6
                                                        adj, uadj, ch, cl);
    mma_gemm<<<dim3(4, 64), 256, GEMM_SMEM>>>(ch, cl,                                     // 7
        wth + 4 * DD * DD, wtl + 4 * DD * DD, bo, h2,
        nullptr, nullptr, nullptr, nullptr, nullptr, nullptr, 1, 0);
    gate_kernel<<<MM, 256>>>(x, h2, gw, gb, out);                                         // 8
}

// round 14
// speedup vs baseline: 2.0683x; 1.0202x over previous
#include <cuda_runtime.h>
#include <cuda_bf16.h>
#include <cstdint>
#include <math.h>

#define BB 16
#define NN 512
#define DD 512
#define HH 8
#define DKK 64
#define MM (BB*NN)          // 8192 rows
#define SCALE 0.125f
#define LN_EPS 1e-5f

// ---------------- scratch (device globals; no allocs allowed) ----------------
__device__ float g_h [MM*DD];
__device__ float g_h2[MM*DD];
__device__ float g_bqkv[3*DD];
__device__ __nv_bfloat16 g_xh[MM*DD], g_xl[MM*DD];
__device__ __nv_bfloat16 g_hh[MM*DD], g_hl[MM*DD];
__device__ __nv_bfloat16 g_qh[MM*DD], g_ql[MM*DD];
__device__ __nv_bfloat16 g_kh[MM*DD], g_kl[MM*DD];
__device__ __nv_bfloat16 g_vth[MM*DD], g_vtl[MM*DD];   // V transposed [b*8+h][64][512]
__device__ __nv_bfloat16 g_ch[MM*DD], g_cl[MM*DD];
__device__ __nv_bfloat16 g_wth[5*DD*DD], g_wtl[5*DD*DD];

__device__ __forceinline__ uint32_t smem_u32(const void* p) {
    uint32_t a;
    asm("{ .reg .u64 t; cvta.to.shared.u64 t, %1; cvt.u32.u64 %0, t; }"
        : "=r"(a) : "l"(p));
    return a;
}

// fast exp on FMA pipe
__device__ __forceinline__ float fexp(float x) {
    x = fmaxf(x, -80.f);
    float y = x * 1.4426950408889634f;
    int   i = __float2int_rd(y);
    float r = y - __int2float_rn(i);
    float q = 1.5403530e-4f;
    q = q * r + 1.3333558e-3f;
    q = q * r + 9.6181291e-3f;
    q = q * r + 5.5504109e-2f;
    q = q * r + 2.4022651e-1f;
    q = q * r + 6.9314718e-1f;
    q = q * r + 1.0f;
    return __int_as_float(__float_as_int(q) + (i << 23));
}

#define MMA_OP(acc, A, B) asm volatile(                                        \
    "mma.sync.aligned.m16n8k16.row.col.f32.bf16.bf16.f32 "                     \
    "{%0,%1,%2,%3}, {%4,%5,%6,%7}, {%8,%9}, {%0,%1,%2,%3};"                    \
    : "+f"((acc)[0]), "+f"((acc)[1]), "+f"((acc)[2]), "+f"((acc)[3])           \
    : "r"((A)[0]), "r"((A)[1]), "r"((A)[2]), "r"((A)[3]),                      \
      "r"((B)[0]), "r"((B)[1]))

#define LDSM4(r0, r1, r2, r3, ad) asm volatile(                                \
    "ldmatrix.sync.aligned.m8n8.x4.shared.b16 {%0,%1,%2,%3}, [%4];"            \
    : "=r"(r0), "=r"(r1), "=r"(r2), "=r"(r3) : "r"(ad))

__device__ __forceinline__ uint32_t pk_bf2(float lo, float hi) {
    uint32_t u;
    asm("cvt.rn.bf16x2.f32 %0, %1, %2;" : "=r"(u) : "f"(hi), "f"(lo));
    return u;
}

// =================== mma.sync bf16-split GEMM ===============================
// CTA 128(M) x 128(N), 256 threads (2x4 warps, warp tile 64x32), K chunks 32.
// All 12 ldmatrix per ks-step hoisted before the 48 MMAs (latency hiding).
// mode 0: fp32 out (+opt relu). mode 1: QKV split out (V stored transposed).
#define PITCHB 80
#define OFF_AL 10240
#define OFF_BH 20480
#define OFF_BL 30720
#define BUFSZ  40960
#define GEMM_SMEM (2*BUFSZ)          // 81920

__global__ __launch_bounds__(256, 2) void mma_gemm(
    const __nv_bfloat16* __restrict__ Ah, const __nv_bfloat16* __restrict__ Al,
    const __nv_bfloat16* __restrict__ Bh, const __nv_bfloat16* __restrict__ Bl,
    const float* __restrict__ bias, float* __restrict__ C,
    __nv_bfloat16* __restrict__ Q0h, __nv_bfloat16* __restrict__ Q0l,
    __nv_bfloat16* __restrict__ Q1h, __nv_bfloat16* __restrict__ Q1l,
    __nv_bfloat16* __restrict__ Q2h, __nv_bfloat16* __restrict__ Q2l,
    int relu, int mode)
{
    extern __shared__ char smx[];
    const uint32_t sbase = smem_u32(smx);
    const int tid = threadIdx.x, wid = tid >> 5, lane = tid & 31;
    const int rowBase = blockIdx.y * 128, nBase = blockIdx.x * 128;
    const int warpM = wid & 1, warpN = wid >> 1;     // 2 x 4

    float acc[4][4][4];
#pragma unroll
    for (int i = 0; i < 4; i++)
#pragma unroll
        for (int j = 0; j < 4; j++)
#pragma unroll
            for (int e = 0; e < 4; e++) acc[i][j][e] = 0.f;

    auto issue_load = [&](int c, int buf) {
        const int kc = c * 32;
#pragma unroll
        for (int s = 0; s < 8; s++) {
            int sid = tid + s * 256;       // 0..2047
            const __nv_bfloat16* g;
            int off;
            if (sid < 512)       { g = Ah; off = 0; }
            else if (sid < 1024) { g = Al; off = OFF_AL; }
            else if (sid < 1536) { g = Bh; off = OFF_BH; }
            else                 { g = Bl; off = OFF_BL; }
            int t = sid & 511;
            int r = t >> 2, seg = t & 3;
            int grow = (off < OFF_BH) ? (rowBase + r) : (nBase + r);
            uint32_t da = sbase + buf * BUFSZ + off + r * PITCHB + seg * 16;
            const char* gp = (const char*)(g + (size_t)grow * 512 + kc) + seg * 16;
            asm volatile("cp.async.cg.shared.global [%0], [%1], 16;"
                         :: "r"(da), "l"(gp) : "memory");
        }
        asm volatile("cp.async.commit_group;" ::: "memory");
    };

    issue_load(0, 0);
    for (int c = 0; c < 16; c++) {
        const int buf = c & 1;
        if (c < 15) issue_load(c + 1, buf ^ 1);
        if (c < 15) asm volatile("cp.async.wait_group 1;" ::: "memory");
        else        asm volatile("cp.async.wait_group 0;" ::: "memory");
        __syncthreads();

        const uint32_t bufb = sbase + buf * BUFSZ;
        const int rq = lane & 7, grp = lane >> 3;
        const int mrow = ((grp & 1) << 3) + rq;
        const int brow = ((grp & 1) << 3) + rq;
#pragma unroll
        for (int ks = 0; ks < 2; ks++) {
            const int kof2 = (ks * 16 + ((grp >> 1) << 3)) * 2;
            uint32_t ah[4][4], al_[4][4], bh_[4][2], bl_[4][2];
            // ---- hoist ALL fragment loads for this ks-step
#pragma unroll
            for (int i = 0; i < 4; i++) {
                uint32_t ad = bufb + (uint32_t)(warpM * 64 + i * 16 + mrow) * PITCHB + kof2;
                LDSM4(ah[i][0], ah[i][1], ah[i][2], ah[i][3], ad);
            }
#pragma unroll
            for (int i = 0; i < 4; i++) {
                uint32_t ad = bufb + OFF_AL +
                    (uint32_t)(warpM * 64 + i * 16 + mrow) * PITCHB + kof2;
                LDSM4(al_[i][0], al_[i][1], al_[i][2], al_[i][3], ad);
            }
#pragma unroll
            for (int jj = 0; jj < 2; jj++) {
                uint32_t ad = bufb + OFF_BH +
                    (uint32_t)(warpN * 32 + jj * 16 + brow) * PITCHB + kof2;
                uint32_t r0, r1, r2, r3;
                LDSM4(r0, r1, r2, r3, ad);
                bh_[2 * jj][0] = r0; bh_[2 * jj + 1][0] = r1;
                bh_[2 * jj][1] = r2; bh_[2 * jj + 1][1] = r3;
            }
#pragma unroll
            for (int jj = 0; jj < 2; jj++) {
                uint32_t ad = bufb + OFF_BL +
                    (uint32_t)(warpN * 32 + jj * 16 + brow) * PITCHB + kof2;
                uint32_t r0, r1, r2, r3;
                LDSM4(r0, r1, r2, r3, ad);
                bl_[2 * jj][0] = r0; bl_[2 * jj + 1][0] = r1;
                bl_[2 * jj][1] = r2; bl_[2 * jj + 1][1] = r3;
            }
            // ---- three passes, each over 16 independent accumulators
#pragma unroll
            for (int i = 0; i < 4; i++)
#pragma unroll
                for (int j = 0; j < 4; j++) MMA_OP(acc[i][j], ah[i], bh_[j]);
#pragma unroll
            for (int i = 0; i < 4; i++)
#pragma unroll
                for (int j = 0; j < 4; j++) MMA_OP(acc[i][j], al_[i], bh_[j]);
#pragma unroll
            for (int i = 0; i < 4; i++)
#pragma unroll
                for (int j = 0; j < 4; j++) MMA_OP(acc[i][j], ah[i], bl_[j]);
        }
        __syncthreads();
    }

    // ---- epilogue
    const int third = nBase >> 9;
    const int ncol0 = nBase & 511;
#pragma unroll
    for (int i = 0; i < 4; i++) {
#pragma unroll
        for (int j = 0; j < 4; j++) {
            int gr = rowBase + warpM * 64 + i * 16 + (lane >> 2);
            int cw = warpN * 32 + j * 8 + (lane & 3) * 2;
            int gc = ncol0 + cw;
            float2 b2 = *(const float2*)&bias[nBase + cw];
            float v0 = acc[i][j][0] + b2.x, v1 = acc[i][j][1] + b2.y;
            float v2 = acc[i][j][2] + b2.x, v3 = acc[i][j][3] + b2.y;
            if (mode == 0) {
                if (relu) {
                    v0 = fmaxf(v0, 0.f); v1 = fmaxf(v1, 0.f);
                    v2 = fmaxf(v2, 0.f); v3 = fmaxf(v3, 0.f);
                }
                float2 o0; o0.x = v0; o0.y = v1;
                float2 o1; o1.x = v2; o1.y = v3;
                *(float2*)&C[(size_t)gr * DD + gc]       = o0;
                *(float2*)&C[(size_t)(gr + 8) * DD + gc] = o1;
            } else if (third < 2) {
                __nv_bfloat16* Ch = (third == 0) ? Q0h : Q1h;
                __nv_bfloat16* Cl = (third == 0) ? Q0l : Q1l;
                float h0 = __bfloat162float(__float2bfloat16(v0));
                float h1 = __bfloat162float(__float2bfloat16(v1));
                float h2 = __bfloat162float(__float2bfloat16(v2));
                float h3 = __bfloat162float(__float2bfloat16(v3));
                *(uint32_t*)&Ch[(size_t)gr * DD + gc]       = pk_bf2(h0, h1);
                *(uint32_t*)&Ch[(size_t)(gr + 8) * DD + gc] = pk_bf2(h2, h3);
                *(uint32_t*)&Cl[(size_t)gr * DD + gc]       = pk_bf2(v0 - h0, v1 - h1);
                *(uint32_t*)&Cl[(size_t)(gr + 8) * DD + gc] = pk_bf2(v2 - h2, v3 - h3);
            } else {
                // V: store transposed Vt[b*8+h][d][n]  (d = head dim, n = token)
                int nr = gr & 511, bb = gr >> 9;
                int hh2 = gc >> 6, d0 = gc & 63;
                size_t rb = ((size_t)(bb * 8 + hh2) * 64 + d0) * 512;
                __nv_bfloat16 t0 = __float2bfloat16(v0);
                __nv_bfloat16 t1 = __float2bfloat16(v1);
                __nv_bfloat16 t2 = __float2bfloat16(v2);
                __nv_bfloat16 t3 = __float2bfloat16(v3);
                Q2h[rb + nr]           = t0;     // (d0,   nr)
                Q2h[rb + 512 + nr]     = t1;     // (d0+1, nr)
                Q2h[rb + nr + 8]       = t2;     // (d0,   nr+8)
                Q2h[rb + 512 + nr + 8] = t3;
                Q2l[rb + nr]           = __float2bfloat16(v0 - __bfloat162float(t0));
                Q2l[rb + 512 + nr]     = __float2bfloat16(v1 - __bfloat162float(t1));
                Q2l[rb + nr + 8]       = __float2bfloat16(v2 - __bfloat162float(t2));
                Q2l[rb + 512 + nr + 8] = __float2bfloat16(v3 - __bfloat162float(t3));
            }
        }
    }
}

// =================== tensor-core flash attention ============================
// K and Vt both cp.async double-buffered; Vt comes pre-transposed from the
// QKV GEMM epilogue, so no in-kernel transpose and only 1 sync per chunk.
#define AP    144
#define OQH   0
#define OQL   9216
#define OK0   18432              // 2 bufs x (hi 9216 + lo 9216)
#define OVT0  55296              // 2 bufs x (hi 9216 + lo 9216)
#define ATT_SMEM 92160

__global__ __launch_bounds__(128) void attn_mma(
    const __nv_bfloat16* __restrict__ qh, const __nv_bfloat16* __restrict__ ql,
    const __nv_bfloat16* __restrict__ kh, const __nv_bfloat16* __restrict__ kl,
    const __nv_bfloat16* __restrict__ vth, const __nv_bfloat16* __restrict__ vtl,
    const float* __restrict__ adj, const int* __restrict__ use_adj_p,
    __nv_bfloat16* __restrict__ ch, __nv_bfloat16* __restrict__ cl)
{
    extern __shared__ char smx[];
    const uint32_t sbase = smem_u32(smx);
    const int tid = threadIdx.x, warp = tid >> 5, lane = tid & 31;
    const int bh = blockIdx.y;
    const int b = bh >> 3, hd = bh & 7;
    const int q0 = blockIdx.x * 64;
    const int use_adj = (*use_adj_p) != 0;

    const int rq = lane & 7, grp = lane >> 3;
    const int mrow = ((grp & 1) << 3) + rq;
    const int kg16 = (grp >> 1) << 4;
    const int lane2 = lane & 3, r0 = lane >> 2;

    // ---- Q tile (hi+lo) once
#pragma unroll
    for (int s = 0; s < 4; s++) {
        int idx = tid + s * 128;
        int r = idx >> 3, seg = idx & 7;
        size_t gb = ((size_t)(b * NN + q0 + r)) * DD + hd * DKK + seg * 8;
        *(uint4*)(smx + OQH + r * AP + seg * 16) = *(const uint4*)(qh + gb);
        *(uint4*)(smx + OQL + r * AP + seg * 16) = *(const uint4*)(ql + gb);
    }

    auto issue_kv = [&](int cc, int buf) {
        const int k0c = cc * 64;
        const uint32_t okb = sbase + OK0  + buf * 18432;
        const uint32_t ovb = sbase + OVT0 + buf * 18432;
#pragma unroll
        for (int s = 0; s < 16; s++) {
            int idx = tid + s * 128;          // 0..2047
            int which = idx >> 9;
            int t = idx & 511;
            int r = t >> 3, seg = t & 7;
            const char* gp;
            uint32_t dst;
            if (which < 2) {                  // K rows = keys
                const __nv_bfloat16* g = which ? kl : kh;
                gp = (const char*)(g + ((size_t)(b * NN + k0c + r)) * DD + hd * DKK) + seg * 16;
                dst = okb + which * 9216 + r * AP + seg * 16;
            } else {                          // Vt rows = d, contiguous keys
                const __nv_bfloat16* g = (which == 2) ? vth : vtl;
                gp = (const char*)(g + ((size_t)bh * 64 + r) * 512 + k0c) + seg * 16;
                dst = ovb + (which - 2) * 9216 + r * AP + seg * 16;
            }
            asm volatile("cp.async.cg.shared.global [%0], [%1], 16;"
                         :: "r"(dst), "l"(gp) : "memory");
        }
        asm volatile("cp.async.commit_group;" ::: "memory");
    };

    float m0 = -1e30f, m1 = -1e30f, l0 = 0.f, l1 = 0.f;
    float ca[8][4];
#pragma unroll
    for (int j = 0; j < 8; j++)
#pragma unroll
        for (int e = 0; e < 4; e++) ca[j][e] = 0.f;

    issue_kv(0, 0);
    for (int cchunk = 0; cchunk < 8; cchunk++) {
        const int buf = cchunk & 1;
        const int k0c = cchunk * 64;
        asm volatile("cp.async.wait_group 0;" ::: "memory");
        __syncthreads();
        // prefetch next chunk into other buffer (safe: its readers synced above)
        if (cchunk < 7) issue_kv(cchunk + 1, buf ^ 1);

        // ---- adj mask bits via direct LDG (hidden under S MMAs)
        uint32_t mk0 = 0xFFFFFFFFu, mk1 = 0xFFFFFFFFu;
        if (use_adj) {
            mk0 = 0; mk1 = 0;
            const float* ab = adj + ((size_t)b * NN + q0 + warp * 16 + r0) * NN + k0c + lane2 * 2;
#pragma unroll
            for (int j = 0; j < 8; j++) {
                float2 a0 = *(const float2*)(ab + j * 8);
                float2 a1 = *(const float2*)(ab + 8 * NN + j * 8);
                mk0 |= (a0.x > 0.f ? 1u : 0u) << (2 * j) | (a0.y > 0.f ? 1u : 0u) << (2 * j + 1);
                mk1 |= (a1.x > 0.f ? 1u : 0u) << (2 * j) | (a1.y > 0.f ? 1u : 0u) << (2 * j + 1);
            }
        }

        // ---- S = Q K^T (3-term split)
        const uint32_t okh = sbase + OK0 + buf * 18432;
        const uint32_t okl = okh + 9216;
        float sa[8][4];
#pragma unroll
        for (int j = 0; j < 8; j++)
#pragma unroll
            for (int e = 0; e < 4; e++) sa[j][e] = 0.f;

#pragma unroll
        for (int ks = 0; ks < 4; ks++) {
            const int kof = ks * 32 + kg16;
            uint32_t aH[4], aL[4];
            uint32_t ad = sbase + OQH + (uint32_t)(warp * 16 + mrow) * AP + kof;
            LDSM4(aH[0], aH[1], aH[2], aH[3], ad);
            ad = sbase + OQL + (uint32_t)(warp * 16 + mrow) * AP + kof;
            LDSM4(aL[0], aL[1], aL[2], aL[3], ad);
#pragma unroll
            for (int jj = 0; jj < 4; jj++) {
                uint32_t bH[2][2], bL[2][2], t0, t1, t2, t3;
                uint32_t bd = okh + (uint32_t)(jj * 16 + mrow) * AP + kof;
                LDSM4(t0, t1, t2, t3, bd);
                bH[0][0] = t0; bH[1][0] = t1; bH[0][1] = t2; bH[1][1] = t3;
                bd = okl + (uint32_t)(jj * 16 + mrow) * AP + kof;
                LDSM4(t0, t1, t2, t3, bd);
                bL[0][0] = t0; bL[1][0] = t1; bL[0][1] = t2; bL[1][1] = t3;
                MMA_OP(sa[2 * jj],     aH, bH[0]); MMA_OP(sa[2 * jj + 1], aH, bH[1]);
                MMA_OP(sa[2 * jj],     aL, bH[0]); MMA_OP(sa[2 * jj + 1], aL, bH[1]);
                MMA_OP(sa[2 * jj],     aH, bL[0]); MMA_OP(sa[2 * jj + 1], aH, bL[1]);
            }
        }

        // ---- mask + scale (masked -> 0.0)
#pragma unroll
        for (int j = 0; j < 8; j++) {
            sa[j][0] = (mk0 >> (2 * j)     & 1u) ? sa[j][0] * SCALE : 0.f;
            sa[j][1] = (mk0 >> (2 * j + 1) & 1u) ? sa[j][1] * SCALE : 0.f;
            sa[j][2] = (mk1 >> (2 * j)     & 1u) ? sa[j][2] * SCALE : 0.f;
            sa[j][3] = (mk1 >> (2 * j + 1) & 1u) ? sa[j][3] * SCALE : 0.f;
        }

        // ---- online softmax
        float cm0 = -1e30f, cm1 = -1e30f;
#pragma unroll
        for (int j = 0; j < 8; j++) {
            cm0 = fmaxf(cm0, fmaxf(sa[j][0], sa[j][1]));
            cm1 = fmaxf(cm1, fmaxf(sa[j][2], sa[j][3]));
        }
        cm0 = fmaxf(cm0, __shfl_xor_sync(0xffffffffu, cm0, 1));
        cm0 = fmaxf(cm0, __shfl_xor_sync(0xffffffffu, cm0, 2));
        cm1 = fmaxf(cm1, __shfl_xor_sync(0xffffffffu, cm1, 1));
        cm1 = fmaxf(cm1, __shfl_xor_sync(0xffffffffu, cm1, 2));
        float mn0 = fmaxf(m0, cm0), mn1 = fmaxf(m1, cm1);
        float sc0 = fexp(m0 - mn0), sc1 = fexp(m1 - mn1);
        float cs0 = 0.f, cs1 = 0.f;
#pragma unroll
        for (int j = 0; j < 8; j++) {
            sa[j][0] = fexp(sa[j][0] - mn0);
            sa[j][1] = fexp(sa[j][1] - mn0);
            sa[j][2] = fexp(sa[j][2] - mn1);
            sa[j][3] = fexp(sa[j][3] - mn1);
            cs0 += sa[j][0] + sa[j][1];
            cs1 += sa[j][2] + sa[j][3];
        }
        cs0 += __shfl_xor_sync(0xffffffffu, cs0, 1);
        cs0 += __shfl_xor_sync(0xffffffffu, cs0, 2);
        cs1 += __shfl_xor_sync(0xffffffffu, cs1, 1);
        cs1 += __shfl_xor_sync(0xffffffffu, cs1, 2);
        l0 = l0 * sc0 + cs0; m0 = mn0;
        l1 = l1 * sc1 + cs1; m1 = mn1;
#pragma unroll
        for (int j = 0; j < 8; j++) {
            ca[j][0] *= sc0; ca[j][1] *= sc0;
            ca[j][2] *= sc1; ca[j][3] *= sc1;
        }

        // ---- ctx += P @ V  (Vt already [d][key] in smem)
        const uint32_t ovh = sbase + OVT0 + buf * 18432;
        const uint32_t ovl = ovh + 9216;
#pragma unroll
        for (int ks = 0; ks < 4; ks++) {
            uint32_t aH[4], aL[4];
            {
                float p0 = sa[2 * ks][0], p1 = sa[2 * ks][1];
                float p2 = sa[2 * ks][2], p3 = sa[2 * ks][3];
                float p4 = sa[2 * ks + 1][0], p5 = sa[2 * ks + 1][1];
                float p6 = sa[2 * ks + 1][2], p7 = sa[2 * ks + 1][3];
                float h0 = __bfloat162float(__float2bfloat16(p0));
                float h1 = __bfloat162float(__float2bfloat16(p1));
                float h2 = __bfloat162float(__float2bfloat16(p2));
                float h3 = __bfloat162float(__float2bfloat16(p3));
                float h4 = __bfloat162float(__float2bfloat16(p4));
                float h5 = __bfloat162float(__float2bfloat16(p5));
                float h6 = __bfloat162float(__float2bfloat16(p6));
                float h7 = __bfloat162float(__float2bfloat16(p7));
                aH[0] = pk_bf2(h0, h1); aH[1] = pk_bf2(h2, h3);
                aH[2] = pk_bf2(h4, h5); aH[3] = pk_bf2(h6, h7);
                aL[0] = pk_bf2(p0 - h0, p1 - h1); aL[1] = pk_bf2(p2 - h2, p3 - h3);
                aL[2] = pk_bf2(p4 - h4, p5 - h5); aL[3] = pk_bf2(p6 - h6, p7 - h7);
            }
            const int kof = ks * 32 + kg16;
#pragma unroll
            for (int jj = 0; jj < 4; jj++) {
                uint32_t bH[2][2], bL[2][2], t0, t1, t2, t3;
                uint32_t bd = ovh + (uint32_t)(jj * 16 + mrow) * AP + kof;
                LDSM4(t0, t1, t2, t3, bd);
                bH[0][0] = t0; bH[1][0] = t1; bH[0][1] = t2; bH[1][1] = t3;
                bd = ovl + (uint32_t)(jj * 16 + mrow) * AP + kof;
                LDSM4(t0, t1, t2, t3, bd);
                bL[0][0] = t0; bL[1][0] = t1; bL[0][1] = t2; bL[1][1] = t3;
                MMA_OP(ca[2 * jj],     aH, bH[0]); MMA_OP(ca[2 * jj + 1], aH, bH[1]);
                MMA_OP(ca[2 * jj],     aL, bH[0]); MMA_OP(ca[2 * jj + 1], aL, bH[1]);
                MMA_OP(ca[2 * jj],     aH, bL[0]); MMA_OP(ca[2 * jj + 1], aH, bL[1]);
            }
        }
    }

    // ---- epilogue
    const float inv0 = 1.f / l0, inv1 = 1.f / l1;
    const int qr0 = q0 + warp * 16 + r0;
#pragma unroll
    for (int j = 0; j < 8; j++) {
        int d = j * 8 + lane2 * 2;
        size_t b0 = ((size_t)(b * NN + qr0)) * DD + hd * DKK + d;
        size_t b1 = b0 + 8 * DD;
        float v0 = ca[j][0] * inv0, v1 = ca[j][1] * inv0;
        float v2 = ca[j][2] * inv1, v3 = ca[j][3] * inv1;
        float h0 = __bfloat162float(__float2bfloat16(v0));
        float h1 = __bfloat162float(__float2bfloat16(v1));
        float h2 = __bfloat162float(__float2bfloat16(v2));
        float h3 = __bfloat162float(__float2bfloat16(v3));
        *(uint32_t*)&ch[b0] = pk_bf2(h0, h1);
        *(uint32_t*)&ch[b1] = pk_bf2(h2, h3);
        *(uint32_t*)&cl[b0] = pk_bf2(v0 - h0, v1 - h1);
        *(uint32_t*)&cl[b1] = pk_bf2(v2 - h2, v3 - h3);
    }
}

// ---------------- helpers ----------------------------------------------------
__global__ __launch_bounds__(256) void conv_split(
    const float4* __restrict__ in, __nv_bfloat162* __restrict__ hi,
    __nv_bfloat162* __restrict__ lo, int n4)
{
    int i = blockIdx.x * 256 + threadIdx.x;
    if (i >= n4) return;
    float4 v = in[i];
    __nv_bfloat16 h0 = __float2bfloat16(v.x), h1 = __float2bfloat16(v.y);
    __nv_bfloat16 h2 = __float2bfloat16(v.z), h3 = __float2bfloat16(v.w);
    __nv_bfloat162 a, b, c, d;
    a.x = h0; a.y = h1; b.x = h2; b.y = h3;
    c.x = __float2bfloat16(v.x - __bfloat162float(h0));
    c.y = __float2bfloat16(v.y - __bfloat162float(h1));
    d.x = __float2bfloat16(v.z - __bfloat162float(h2));
    d.y = __float2bfloat16(v.w - __bfloat162float(h3));
    hi[2 * i] = a; hi[2 * i + 1] = b;
    lo[2 * i] = c; lo[2 * i + 1] = d;
}

// all 5 weight transposes in one launch (blockIdx.z selects the weight)
__global__ __launch_bounds__(256) void wtrans_all(
    const float* __restrict__ W0, const float* __restrict__ W1,
    const float* __restrict__ W2, const float* __restrict__ W3,
    const float* __restrict__ W4,
    __nv_bfloat16* __restrict__ th, __nv_bfloat16* __restrict__ tl)
{
    const int z = blockIdx.z;
    const float* W = (z == 0) ? W0 : (z == 1) ? W1 : (z == 2) ? W2 : (z == 3) ? W3 : W4;
    th += (size_t)z * DD * DD;
    tl += (size_t)z * DD * DD;

    __shared__ float t[32][33];
    const int k0 = blockIdx.y * 32, n0 = blockIdx.x * 32;
    const int tx = threadIdx.x & 31, ty = threadIdx.x >> 5;
#pragma unroll
    for (int i = 0; i < 32; i += 8)
        t[ty + i][tx] = W[(size_t)(k0 + ty + i) * DD + n0 + tx];
    __syncthreads();
#pragma unroll
    for (int i = 0; i < 32; i += 8) {
        float v = t[tx][ty + i];
        __nv_bfloat16 h = __float2bfloat16(v);
        __nv_bfloat16 l = __float2bfloat16(v - __bfloat162float(h));
        size_t o = (size_t)(n0 + ty + i) * DD + k0 + tx;
        th[o] = h; tl[o] = l;
    }
}

__global__ __launch_bounds__(256) void pack_bias(
    const float* __restrict__ bq, const float* __restrict__ bk,
    const float* __restrict__ bv, float* __restrict__ o)
{
    int t = blockIdx.x * 256 + threadIdx.x;
    if (t < 512)       o[t] = bq[t];
    else if (t < 1024) o[t] = bk[t - 512];
    else if (t < 1536) o[t] = bv[t - 1024];
}

__global__ __launch_bounds__(256) void ln2_kernel(
    const float* __restrict__ h, const float* __restrict__ g, const float* __restrict__ b,
    __nv_bfloat16* __restrict__ hh, __nv_bfloat16* __restrict__ hl)
{
    const int r = blockIdx.x;
    const float* row = h + (size_t)r * DD;
    const int t = threadIdx.x;
    float v0 = row[t], v1 = row[t + 256];

    __shared__ float red[8];
    __shared__ float s_mu, s_rs;
    float s = v0 + v1;
#pragma unroll
    for (int o = 16; o; o >>= 1) s += __shfl_xor_sync(0xffffffffu, s, o);
    if ((t & 31) == 0) red[t >> 5] = s;
    __syncthreads();
    if (t == 0) {
        float tot = 0.f;
#pragma unroll
        for (int i = 0; i < 8; i++) tot += red[i];
        s_mu = tot * (1.f / DD);
    }
    __syncthreads();
    const float mu = s_mu;
    float d0 = v0 - mu, d1 = v1 - mu;
    float s2 = d0 * d0 + d1 * d1;
#pragma unroll
    for (int o = 16; o; o >>= 1) s2 += __shfl_xor_sync(0xffffffffu, s2, o);
    if ((t & 31) == 0) red[t >> 5] = s2;
    __syncthreads();
    if (t == 0) {
        float tot = 0.f;
#pragma unroll
        for (int i = 0; i < 8; i++) tot += red[i];
        s_rs = rsqrtf(tot * (1.f / DD) + LN_EPS);
    }
    __syncthreads();
    const float rs = s_rs;
    float y0 = d0 * rs * g[t] + b[t];
    float y1 = d1 * rs * g[t + 256] + b[t + 256];
    size_t base = (size_t)r * DD;
    __nv_bfloat16 a0 = __float2bfloat16(y0);
    __nv_bfloat16 a1 = __float2bfloat16(y1);
    hh[base + t] = a0;       hl[base + t] = __float2bfloat16(y0 - __bfloat162float(a0));
    hh[base + t + 256] = a1; hl[base + t + 256] = __float2bfloat16(y1 - __bfloat162float(a1));
}

__global__ __launch_bounds__(256) void gate_kernel(
    const float* __restrict__ x, const float* __restrict__ h2,
    const float* __restrict__ gw, const float* __restrict__ gb,
    float* __restrict__ out)
{
    const int r = blockIdx.x;
    const size_t base = (size_t)r * DD;
    const int t = threadIdx.x;
    float x0 = x[base + t], x1 = x[base + t + 256];
    float h0 = h2[base + t], h1 = h2[base + t + 256];
    float s = x0 * gw[t] + x1 * gw[t + 256] + h0 * gw[512 + t] + h1 * gw[768 + t];

    __shared__ float red[8];
    __shared__ float s_c;
#pragma unroll
    for (int o = 16; o; o >>= 1) s += __shfl_xor_sync(0xffffffffu, s, o);
    if ((t & 31) == 0) red[t >> 5] = s;
    __syncthreads();
    if (t == 0) {
        float tot = 0.f;
#pragma unroll
        for (int i = 0; i < 8; i++) tot += red[i];
        s_c = 1.f / (1.f + expf(-(tot + gb[0])));
    }
    __syncthreads();
    const float c = s_c;
    out[base + t]       = c * x0 + (1.f - c) * h0;
    out[base + t + 256] = c * x1 + (1.f - c) * h1;
}

// ---------------- launch ----------------------------------------------------
extern "C" void kernel_launch(void* const* d_in, const int* in_sizes, int n_in,
                              void* d_out, int out_size)
{
    const float* x    = (const float*)d_in[0];
    const float* adj  = (const float*)d_in[1];
    const float* W_w  = (const float*)d_in[2];
    const float* W_b  = (const float*)d_in[3];
    const float* ln_g = (const float*)d_in[4];
    const float* ln_b = (const float*)d_in[5];
    const float* Wq   = (const float*)d_in[6];
    const float* bq   = (const float*)d_in[7];
    const float* Wk   = (const float*)d_in[8];
    const float* bk   = (const float*)d_in[9];
    const float* Wv   = (const float*)d_in[10];
    const float* bv   = (const float*)d_in[11];
    const float* Wo   = (const float*)d_in[12];
    const float* bo   = (const float*)d_in[13];
    const float* gw   = (const float*)d_in[14];
    const float* gb   = (const float*)d_in[15];
    const int*   uadj = (const int*)d_in[16];
    float* out = (float*)d_out;

    float *h, *h2, *bqkv;
    __nv_bfloat16 *xh, *xl, *hh, *hl, *qh, *ql, *kh, *kl, *vth, *vtl, *ch, *cl, *wth, *wtl;
    cudaGetSymbolAddress((void**)&h,  g_h);
    cudaGetSymbolAddress((void**)&h2, g_h2);
    cudaGetSymbolAddress((void**)&bqkv, g_bqkv);
    cudaGetSymbolAddress((void**)&xh, g_xh);
    cudaGetSymbolAddress((void**)&xl, g_xl);
    cudaGetSymbolAddress((void**)&hh, g_hh);
    cudaGetSymbolAddress((void**)&hl, g_hl);
    cudaGetSymbolAddress((void**)&qh, g_qh);
    cudaGetSymbolAddress((void**)&ql, g_ql);
    cudaGetSymbolAddress((void**)&kh, g_kh);
    cudaGetSymbolAddress((void**)&kl, g_kl);
    cudaGetSymbolAddress((void**)&vth, g_vth);
    cudaGetSymbolAddress((void**)&vtl, g_vtl);
    cudaGetSymbolAddress((void**)&ch, g_ch);
    cudaGetSymbolAddress((void**)&cl, g_cl);
    cudaGetSymbolAddress((void**)&wth, g_wth);
    cudaGetSymbolAddress((void**)&wtl, g_wtl);

    cudaFuncSetAttribute(mma_gemm,
                         cudaFuncAttributeMaxDynamicSharedMemorySize, GEMM_SMEM);
    cudaFuncSetAttribute(attn_mma,
                         cudaFuncAttributeMaxDynamicSharedMemorySize, ATT_SMEM);

    const int n4 = MM * DD / 4;
    conv_split<<<(n4 + 255) / 256, 256>>>((const float4*)x,
                                          (__nv_bfloat162*)xh, (__nv_bfloat162*)xl, n4); // 0
    wtrans_all<<<dim3(16, 16, 5), 256>>>(W_w, Wq, Wk, Wv, Wo, wth, wtl);                  // 1
    pack_bias<<<6, 256>>>(bq, bk, bv, bqkv);                                              // 2
    mma_gemm<<<dim3(4, 64), 256, GEMM_SMEM>>>(xh, xl,                                     // 3
        wth + 0 * DD * DD, wtl + 0 * DD * DD, W_b, h,
        nullptr, nullptr, nullptr, nullptr, nullptr, nullptr, 0, 0);
    ln2_kernel<<<MM, 256>>>(h, ln_g, ln_b, hh, hl);                                       // 4
    mma_gemm<<<dim3(12, 64), 256, GEMM_SMEM>>>(hh, hl,                                    // 5: fused QKV
        wth + 1 * DD * DD, wtl + 1 * DD * DD, bqkv, nullptr,
        qh, ql, kh, kl, vth, vtl, 0, 1);
    attn_mma<<<dim3(NN / 64, BB * HH), 128, ATT_SMEM>>>(qh, ql, kh, kl, vth, vtl,         // 6
                                                        adj, uadj, ch, cl);
    mma_gemm<<<dim3(4, 64), 256, GEMM_SMEM>>>(ch, cl,                                     // 7
        wth + 4 * DD * DD, wtl + 4 * DD * DD, bo, h2,
        nullptr, nullptr, nullptr, nullptr, nullptr, nullptr, 1, 0);
    gate_kernel<<<MM, 256>>>(x, h2, gw, gb, out);                                         // 8
}

// round 15
// speedup vs baseline: 4.1891x; 2.0254x over previous
#include <cuda_runtime.h>
#include <cuda_fp16.h>
#include <cstdint>
#include <math.h>

#define BB 16
#define NN 512
#define DD 512
#define HH 8
#define DKK 64
#define MM (BB*NN)          // 8192 rows
#define SCALE 0.125f
#define LN_EPS 1e-5f

// ---------------- scratch (device globals; no allocs allowed) ----------------
__device__ float g_h [MM*DD];
__device__ float g_h2[MM*DD];
__device__ float g_bqkv[3*DD];
__device__ __half g_x16[MM*DD];
__device__ __half g_h16[MM*DD];
__device__ __half g_q16[MM*DD];
__device__ __half g_k16[MM*DD];
__device__ __half g_vt16[MM*DD];    // V transposed [b*8+h][64][512]
__device__ __half g_c16[MM*DD];
__device__ __half g_wt16[5*DD*DD];

__device__ __forceinline__ uint32_t smem_u32(const void* p) {
    uint32_t a;
    asm("{ .reg .u64 t; cvta.to.shared.u64 t, %1; cvt.u32.u64 %0, t; }"
        : "=r"(a) : "l"(p));
    return a;
}

// fast exp on FMA pipe
__device__ __forceinline__ float fexp(float x) {
    x = fmaxf(x, -80.f);
    float y = x * 1.4426950408889634f;
    int   i = __float2int_rd(y);
    float r = y - __int2float_rn(i);
    float q = 1.5403530e-4f;
    q = q * r + 1.3333558e-3f;
    q = q * r + 9.6181291e-3f;
    q = q * r + 5.5504109e-2f;
    q = q * r + 2.4022651e-1f;
    q = q * r + 6.9314718e-1f;
    q = q * r + 1.0f;
    return __int_as_float(__float_as_int(q) + (i << 23));
}

#define MMA_OP(acc, A, B) asm volatile(                                        \
    "mma.sync.aligned.m16n8k16.row.col.f32.f16.f16.f32 "                       \
    "{%0,%1,%2,%3}, {%4,%5,%6,%7}, {%8,%9}, {%0,%1,%2,%3};"                    \
    : "+f"((acc)[0]), "+f"((acc)[1]), "+f"((acc)[2]), "+f"((acc)[3])           \
    : "r"((A)[0]), "r"((A)[1]), "r"((A)[2]), "r"((A)[3]),                      \
      "r"((B)[0]), "r"((B)[1]))

#define LDSM4(r0, r1, r2, r3, ad) asm volatile(                                \
    "ldmatrix.sync.aligned.m8n8.x4.shared.b16 {%0,%1,%2,%3}, [%4];"            \
    : "=r"(r0), "=r"(r1), "=r"(r2), "=r"(r3) : "r"(ad))

__device__ __forceinline__ uint32_t pk_hf2(float lo, float hi) {
    __half2 h = __floats2half2_rn(lo, hi);
    return *(uint32_t*)&h;
}

// =================== mma.sync fp16 GEMM =====================================
// CTA 128(M) x 128(N), 256 threads (2x4 warps, warp tile 64x32), K chunks 32,
// cp.async double buffer, hoisted fragment loads.
// mode 0: fp32 out (+opt relu). mode 1: QKV fp16 out (V stored transposed).
#define PITCHB 80
#define OFF_B  10240
#define BUFSZ  20480
#define GEMM_SMEM (2*BUFSZ)          // 40960

__global__ __launch_bounds__(256, 2) void mma_gemm(
    const __half* __restrict__ A, const __half* __restrict__ B,
    const float* __restrict__ bias, float* __restrict__ C,
    __half* __restrict__ Q0, __half* __restrict__ Q1, __half* __restrict__ Q2,
    int relu, int mode)
{
    extern __shared__ char smx[];
    const uint32_t sbase = smem_u32(smx);
    const int tid = threadIdx.x, wid = tid >> 5, lane = tid & 31;
    const int rowBase = blockIdx.y * 128, nBase = blockIdx.x * 128;
    const int warpM = wid & 1, warpN = wid >> 1;     // 2 x 4

    float acc[4][4][4];
#pragma unroll
    for (int i = 0; i < 4; i++)
#pragma unroll
        for (int j = 0; j < 4; j++)
#pragma unroll
            for (int e = 0; e < 4; e++) acc[i][j][e] = 0.f;

    auto issue_load = [&](int c, int buf) {
        const int kc = c * 32;
#pragma unroll
        for (int s = 0; s < 4; s++) {
            int sid = tid + s * 256;       // 0..1023
            const __half* g = (sid < 512) ? A : B;
            int off = (sid < 512) ? 0 : OFF_B;
            int t = sid & 511;
            int r = t >> 2, seg = t & 3;   // 128 rows x 4 segs of 16B
            int grow = (sid < 512) ? (rowBase + r) : (nBase + r);
            uint32_t da = sbase + buf * BUFSZ + off + r * PITCHB + seg * 16;
            const char* gp = (const char*)(g + (size_t)grow * 512 + kc) + seg * 16;
            asm volatile("cp.async.cg.shared.global [%0], [%1], 16;"
                         :: "r"(da), "l"(gp) : "memory");
        }
        asm volatile("cp.async.commit_group;" ::: "memory");
    };

    issue_load(0, 0);
    for (int c = 0; c < 16; c++) {
        const int buf = c & 1;
        if (c < 15) issue_load(c + 1, buf ^ 1);
        if (c < 15) asm volatile("cp.async.wait_group 1;" ::: "memory");
        else        asm volatile("cp.async.wait_group 0;" ::: "memory");
        __syncthreads();

        const uint32_t bufb = sbase + buf * BUFSZ;
        const int rq = lane & 7, grp = lane >> 3;
        const int mrow = ((grp & 1) << 3) + rq;
#pragma unroll
        for (int ks = 0; ks < 2; ks++) {
            const int kof2 = ks * 32 + ((grp >> 1) << 4);   // byte offset
            uint32_t ah[4][4], bh_[4][2];
            // hoist all fragment loads for this ks-step
#pragma unroll
            for (int i = 0; i < 4; i++) {
                uint32_t ad = bufb + (uint32_t)(warpM * 64 + i * 16 + mrow) * PITCHB + kof2;
                LDSM4(ah[i][0], ah[i][1], ah[i][2], ah[i][3], ad);
            }
#pragma unroll
            for (int jj = 0; jj < 2; jj++) {
                uint32_t ad = bufb + OFF_B +
                    (uint32_t)(warpN * 32 + jj * 16 + mrow) * PITCHB + kof2;
                uint32_t r0, r1, r2, r3;
                LDSM4(r0, r1, r2, r3, ad);
                bh_[2 * jj][0] = r0; bh_[2 * jj + 1][0] = r1;
                bh_[2 * jj][1] = r2; bh_[2 * jj + 1][1] = r3;
            }
#pragma unroll
            for (int i = 0; i < 4; i++)
#pragma unroll
                for (int j = 0; j < 4; j++) MMA_OP(acc[i][j], ah[i], bh_[j]);
        }
        __syncthreads();
    }

    // ---- epilogue
    const int third = nBase >> 9;
    const int ncol0 = nBase & 511;
#pragma unroll
    for (int i = 0; i < 4; i++) {
#pragma unroll
        for (int j = 0; j < 4; j++) {
            int gr = rowBase + warpM * 64 + i * 16 + (lane >> 2);
            int cw = warpN * 32 + j * 8 + (lane & 3) * 2;
            int gc = ncol0 + cw;
            float2 b2 = *(const float2*)&bias[nBase + cw];
            float v0 = acc[i][j][0] + b2.x, v1 = acc[i][j][1] + b2.y;
            float v2 = acc[i][j][2] + b2.x, v3 = acc[i][j][3] + b2.y;
            if (mode == 0) {
                if (relu) {
                    v0 = fmaxf(v0, 0.f); v1 = fmaxf(v1, 0.f);
                    v2 = fmaxf(v2, 0.f); v3 = fmaxf(v3, 0.f);
                }
                float2 o0; o0.x = v0; o0.y = v1;
                float2 o1; o1.x = v2; o1.y = v3;
                *(float2*)&C[(size_t)gr * DD + gc]       = o0;
                *(float2*)&C[(size_t)(gr + 8) * DD + gc] = o1;
            } else if (third < 2) {
                __half* Ch = (third == 0) ? Q0 : Q1;
                *(uint32_t*)&Ch[(size_t)gr * DD + gc]       = pk_hf2(v0, v1);
                *(uint32_t*)&Ch[(size_t)(gr + 8) * DD + gc] = pk_hf2(v2, v3);
            } else {
                // V: store transposed Vt[b*8+h][d][n]
                int nr = gr & 511, bb = gr >> 9;
                int hh2 = gc >> 6, d0 = gc & 63;
                size_t rb = ((size_t)(bb * 8 + hh2) * 64 + d0) * 512;
                Q2[rb + nr]           = __float2half_rn(v0);   // (d0,   nr)
                Q2[rb + 512 + nr]     = __float2half_rn(v1);   // (d0+1, nr)
                Q2[rb + nr + 8]       = __float2half_rn(v2);   // (d0,   nr+8)
                Q2[rb + 512 + nr + 8] = __float2half_rn(v3);
            }
        }
    }
}

// =================== tensor-core flash attention (fp16) =====================
// K and Vt cp.async double-buffered; Vt pre-transposed by QKV GEMM epilogue.
#define AP    144
#define OQ    0                  // 64 x 144 = 9216
#define OK0   9216               // 2 bufs x 9216
#define OVT0  27648              // 2 bufs x 9216
#define ATT_SMEM 46080

__global__ __launch_bounds__(128) void attn_mma(
    const __half* __restrict__ q16, const __half* __restrict__ k16,
    const __half* __restrict__ vt16,
    const float* __restrict__ adj, const int* __restrict__ use_adj_p,
    __half* __restrict__ c16)
{
    extern __shared__ char smx[];
    const uint32_t sbase = smem_u32(smx);
    const int tid = threadIdx.x, warp = tid >> 5, lane = tid & 31;
    const int bh = blockIdx.y;
    const int b = bh >> 3, hd = bh & 7;
    const int q0 = blockIdx.x * 64;
    const int use_adj = (*use_adj_p) != 0;

    const int rq = lane & 7, grp = lane >> 3;
    const int mrow = ((grp & 1) << 3) + rq;
    const int kg16 = (grp >> 1) << 4;
    const int lane2 = lane & 3, r0 = lane >> 2;

    // ---- Q tile once
#pragma unroll
    for (int s = 0; s < 4; s++) {
        int idx = tid + s * 128;            // 0..511
        int r = idx >> 3, seg = idx & 7;
        size_t gb = ((size_t)(b * NN + q0 + r)) * DD + hd * DKK + seg * 8;
        *(uint4*)(smx + OQ + r * AP + seg * 16) = *(const uint4*)(q16 + gb);
    }

    auto issue_kv = [&](int cc, int buf) {
        const int k0c = cc * 64;
        const uint32_t okb = sbase + OK0  + buf * 9216;
        const uint32_t ovb = sbase + OVT0 + buf * 9216;
#pragma unroll
        for (int s = 0; s < 8; s++) {
            int idx = tid + s * 128;        // 0..1023
            int which = idx >> 9;
            int t = idx & 511;
            int r = t >> 3, seg = t & 7;
            const char* gp;
            uint32_t dst;
            if (which == 0) {               // K rows = keys
                gp = (const char*)(k16 + ((size_t)(b * NN + k0c + r)) * DD + hd * DKK) + seg * 16;
                dst = okb + r * AP + seg * 16;
            } else {                        // Vt rows = d, contiguous keys
                gp = (const char*)(vt16 + ((size_t)bh * 64 + r) * 512 + k0c) + seg * 16;
                dst = ovb + r * AP + seg * 16;
            }
            asm volatile("cp.async.cg.shared.global [%0], [%1], 16;"
                         :: "r"(dst), "l"(gp) : "memory");
        }
        asm volatile("cp.async.commit_group;" ::: "memory");
    };

    float m0 = -1e30f, m1 = -1e30f, l0 = 0.f, l1 = 0.f;
    float ca[8][4];
#pragma unroll
    for (int j = 0; j < 8; j++)
#pragma unroll
        for (int e = 0; e < 4; e++) ca[j][e] = 0.f;

    issue_kv(0, 0);
    for (int cchunk = 0; cchunk < 8; cchunk++) {
        const int buf = cchunk & 1;
        const int k0c = cchunk * 64;
        asm volatile("cp.async.wait_group 0;" ::: "memory");
        __syncthreads();
        if (cchunk < 7) issue_kv(cchunk + 1, buf ^ 1);

        // ---- adj mask bits via direct LDG
        uint32_t mk0 = 0xFFFFFFFFu, mk1 = 0xFFFFFFFFu;
        if (use_adj) {
            mk0 = 0; mk1 = 0;
            const float* ab = adj + ((size_t)b * NN + q0 + warp * 16 + r0) * NN + k0c + lane2 * 2;
#pragma unroll
            for (int j = 0; j < 8; j++) {
                float2 a0 = *(const float2*)(ab + j * 8);
                float2 a1 = *(const float2*)(ab + 8 * NN + j * 8);
                mk0 |= (a0.x > 0.f ? 1u : 0u) << (2 * j) | (a0.y > 0.f ? 1u : 0u) << (2 * j + 1);
                mk1 |= (a1.x > 0.f ? 1u : 0u) << (2 * j) | (a1.y > 0.f ? 1u : 0u) << (2 * j + 1);
            }
        }

        // ---- S = Q K^T
        const uint32_t okh = sbase + OK0 + buf * 9216;
        float sa[8][4];
#pragma unroll
        for (int j = 0; j < 8; j++)
#pragma unroll
            for (int e = 0; e < 4; e++) sa[j][e] = 0.f;

#pragma unroll
        for (int ks = 0; ks < 4; ks++) {
            const int kof = ks * 32 + kg16;
            uint32_t aH[4];
            uint32_t ad = sbase + OQ + (uint32_t)(warp * 16 + mrow) * AP + kof;
            LDSM4(aH[0], aH[1], aH[2], aH[3], ad);
#pragma unroll
            for (int jj = 0; jj < 4; jj++) {
                uint32_t bH[2][2], t0, t1, t2, t3;
                uint32_t bd = okh + (uint32_t)(jj * 16 + mrow) * AP + kof;
                LDSM4(t0, t1, t2, t3, bd);
                bH[0][0] = t0; bH[1][0] = t1; bH[0][1] = t2; bH[1][1] = t3;
                MMA_OP(sa[2 * jj], aH, bH[0]); MMA_OP(sa[2 * jj + 1], aH, bH[1]);
            }
        }

        // ---- mask + scale (masked -> 0.0)
#pragma unroll
        for (int j = 0; j < 8; j++) {
            sa[j][0] = (mk0 >> (2 * j)     & 1u) ? sa[j][0] * SCALE : 0.f;
            sa[j][1] = (mk0 >> (2 * j + 1) & 1u) ? sa[j][1] * SCALE : 0.f;
            sa[j][2] = (mk1 >> (2 * j)     & 1u) ? sa[j][2] * SCALE : 0.f;
            sa[j][3] = (mk1 >> (2 * j + 1) & 1u) ? sa[j][3] * SCALE : 0.f;
        }

        // ---- online softmax
        float cm0 = -1e30f, cm1 = -1e30f;
#pragma unroll
        for (int j = 0; j < 8; j++) {
            cm0 = fmaxf(cm0, fmaxf(sa[j][0], sa[j][1]));
            cm1 = fmaxf(cm1, fmaxf(sa[j][2], sa[j][3]));
        }
        cm0 = fmaxf(cm0, __shfl_xor_sync(0xffffffffu, cm0, 1));
        cm0 = fmaxf(cm0, __shfl_xor_sync(0xffffffffu, cm0, 2));
        cm1 = fmaxf(cm1, __shfl_xor_sync(0xffffffffu, cm1, 1));
        cm1 = fmaxf(cm1, __shfl_xor_sync(0xffffffffu, cm1, 2));
        float mn0 = fmaxf(m0, cm0), mn1 = fmaxf(m1, cm1);
        float sc0 = fexp(m0 - mn0), sc1 = fexp(m1 - mn1);
        float cs0 = 0.f, cs1 = 0.f;
#pragma unroll
        for (int j = 0; j < 8; j++) {
            sa[j][0] = fexp(sa[j][0] - mn0);
            sa[j][1] = fexp(sa[j][1] - mn0);
            sa[j][2] = fexp(sa[j][2] - mn1);
            sa[j][3] = fexp(sa[j][3] - mn1);
            cs0 += sa[j][0] + sa[j][1];
            cs1 += sa[j][2] + sa[j][3];
        }
        cs0 += __shfl_xor_sync(0xffffffffu, cs0, 1);
        cs0 += __shfl_xor_sync(0xffffffffu, cs0, 2);
        cs1 += __shfl_xor_sync(0xffffffffu, cs1, 1);
        cs1 += __shfl_xor_sync(0xffffffffu, cs1, 2);
        l0 = l0 * sc0 + cs0; m0 = mn0;
        l1 = l1 * sc1 + cs1; m1 = mn1;
#pragma unroll
        for (int j = 0; j < 8; j++) {
            ca[j][0] *= sc0; ca[j][1] *= sc0;
            ca[j][2] *= sc1; ca[j][3] *= sc1;
        }

        // ---- ctx += P @ V  (Vt [d][key] in smem)
        const uint32_t ovh = sbase + OVT0 + buf * 9216;
#pragma unroll
        for (int ks = 0; ks < 4; ks++) {
            uint32_t aH[4];
            aH[0] = pk_hf2(sa[2 * ks][0],     sa[2 * ks][1]);
            aH[1] = pk_hf2(sa[2 * ks][2],     sa[2 * ks][3]);
            aH[2] = pk_hf2(sa[2 * ks + 1][0], sa[2 * ks + 1][1]);
            aH[3] = pk_hf2(sa[2 * ks + 1][2], sa[2 * ks + 1][3]);
            const int kof = ks * 32 + kg16;
#pragma unroll
            for (int jj = 0; jj < 4; jj++) {
                uint32_t bH[2][2], t0, t1, t2, t3;
                uint32_t bd = ovh + (uint32_t)(jj * 16 + mrow) * AP + kof;
                LDSM4(t0, t1, t2, t3, bd);
                bH[0][0] = t0; bH[1][0] = t1; bH[0][1] = t2; bH[1][1] = t3;
                MMA_OP(ca[2 * jj], aH, bH[0]); MMA_OP(ca[2 * jj + 1], aH, bH[1]);
            }
        }
    }

    // ---- epilogue: normalize + write ctx (fp16)
    const float inv0 = 1.f / l0, inv1 = 1.f / l1;
    const int qr0 = q0 + warp * 16 + r0;
#pragma unroll
    for (int j = 0; j < 8; j++) {
        int d = j * 8 + lane2 * 2;
        size_t b0 = ((size_t)(b * NN + qr0)) * DD + hd * DKK + d;
        size_t b1 = b0 + 8 * DD;
        *(uint32_t*)&c16[b0] = pk_hf2(ca[j][0] * inv0, ca[j][1] * inv0);
        *(uint32_t*)&c16[b1] = pk_hf2(ca[j][2] * inv1, ca[j][3] * inv1);
    }
}

// ---------------- helpers ----------------------------------------------------
__global__ __launch_bounds__(256) void conv_half(
    const float4* __restrict__ in, __half2* __restrict__ o, int n4)
{
    int i = blockIdx.x * 256 + threadIdx.x;
    if (i >= n4) return;
    float4 v = in[i];
    o[2 * i]     = __floats2half2_rn(v.x, v.y);
    o[2 * i + 1] = __floats2half2_rn(v.z, v.w);
}

// all 5 weight transposes in one launch (blockIdx.z selects the weight)
__global__ __launch_bounds__(256) void wtrans_all(
    const float* __restrict__ W0, const float* __restrict__ W1,
    const float* __restrict__ W2, const float* __restrict__ W3,
    const float* __restrict__ W4, __half* __restrict__ th)
{
    const int z = blockIdx.z;
    const float* W = (z == 0) ? W0 : (z == 1) ? W1 : (z == 2) ? W2 : (z == 3) ? W3 : W4;
    th += (size_t)z * DD * DD;

    __shared__ float t[32][33];
    const int k0 = blockIdx.y * 32, n0 = blockIdx.x * 32;
    const int tx = threadIdx.x & 31, ty = threadIdx.x >> 5;
#pragma unroll
    for (int i = 0; i < 32; i += 8)
        t[ty + i][tx] = W[(size_t)(k0 + ty + i) * DD + n0 + tx];
    __syncthreads();
#pragma unroll
    for (int i = 0; i < 32; i += 8) {
        float v = t[tx][ty + i];
        th[(size_t)(n0 + ty + i) * DD + k0 + tx] = __float2half_rn(v);
    }
}

__global__ __launch_bounds__(256) void pack_bias(
    const float* __restrict__ bq, const float* __restrict__ bk,
    const float* __restrict__ bv, float* __restrict__ o)
{
    int t = blockIdx.x * 256 + threadIdx.x;
    if (t < 512)       o[t] = bq[t];
    else if (t < 1024) o[t] = bk[t - 512];
    else if (t < 1536) o[t] = bv[t - 1024];
}

__global__ __launch_bounds__(256) void ln2_kernel(
    const float* __restrict__ h, const float* __restrict__ g, const float* __restrict__ b,
    __half* __restrict__ h16)
{
    const int r = blockIdx.x;
    const float* row = h + (size_t)r * DD;
    const int t = threadIdx.x;
    float v0 = row[t], v1 = row[t + 256];

    __shared__ float red[8];
    __shared__ float s_mu, s_rs;
    float s = v0 + v1;
#pragma unroll
    for (int o = 16; o; o >>= 1) s += __shfl_xor_sync(0xffffffffu, s, o);
    if ((t & 31) == 0) red[t >> 5] = s;
    __syncthreads();
    if (t == 0) {
        float tot = 0.f;
#pragma unroll
        for (int i = 0; i < 8; i++) tot += red[i];
        s_mu = tot * (1.f / DD);
    }
    __syncthreads();
    const float mu = s_mu;
    float d0 = v0 - mu, d1 = v1 - mu;
    float s2 = d0 * d0 + d1 * d1;
#pragma unroll
    for (int o = 16; o; o >>= 1) s2 += __shfl_xor_sync(0xffffffffu, s2, o);
    if ((t & 31) == 0) red[t >> 5] = s2;
    __syncthreads();
    if (t == 0) {
        float tot = 0.f;
#pragma unroll
        for (int i = 0; i < 8; i++) tot += red[i];
        s_rs = rsqrtf(tot * (1.f / DD) + LN_EPS);
    }
    __syncthreads();
    const float rs = s_rs;
    float y0 = d0 * rs * g[t] + b[t];
    float y1 = d1 * rs * g[t + 256] + b[t + 256];
    size_t base = (size_t)r * DD;
    h16[base + t]       = __float2half_rn(y0);
    h16[base + t + 256] = __float2half_rn(y1);
}

__global__ __launch_bounds__(256) void gate_kernel(
    const float* __restrict__ x, const float* __restrict__ h2,
    const float* __restrict__ gw, const float* __restrict__ gb,
    float* __restrict__ out)
{
    const int r = blockIdx.x;
    const size_t base = (size_t)r * DD;
    const int t = threadIdx.x;
    float x0 = x[base + t], x1 = x[base + t + 256];
    float h0 = h2[base + t], h1 = h2[base + t + 256];
    float s = x0 * gw[t] + x1 * gw[t + 256] + h0 * gw[512 + t] + h1 * gw[768 + t];

    __shared__ float red[8];
    __shared__ float s_c;
#pragma unroll
    for (int o = 16; o; o >>= 1) s += __shfl_xor_sync(0xffffffffu, s, o);
    if ((t & 31) == 0) red[t >> 5] = s;
    __syncthreads();
    if (t == 0) {
        float tot = 0.f;
#pragma unroll
        for (int i = 0; i < 8; i++) tot += red[i];
        s_c = 1.f / (1.f + expf(-(tot + gb[0])));
    }
    __syncthreads();
    const float c = s_c;
    out[base + t]       = c * x0 + (1.f - c) * h0;
    out[base + t + 256] = c * x1 + (1.f - c) * h1;
}

// ---------------- launch ----------------------------------------------------
extern "C" void kernel_launch(void* const* d_in, const int* in_sizes, int n_in,
                              void* d_out, int out_size)
{
    const float* x    = (const float*)d_in[0];
    const float* adj  = (const float*)d_in[1];
    const float* W_w  = (const float*)d_in[2];
    const float* W_b  = (const float*)d_in[3];
    const float* ln_g = (const float*)d_in[4];
    const float* ln_b = (const float*)d_in[5];
    const float* Wq   = (const float*)d_in[6];
    const float* bq   = (const float*)d_in[7];
    const float* Wk   = (const float*)d_in[8];
    const float* bk   = (const float*)d_in[9];
    const float* Wv   = (const float*)d_in[10];
    const float* bv   = (const float*)d_in[11];
    const float* Wo   = (const float*)d_in[12];
    const float* bo   = (const float*)d_in[13];
    const float* gw   = (const float*)d_in[14];
    const float* gb   = (const float*)d_in[15];
    const int*   uadj = (const int*)d_in[16];
    float* out = (float*)d_out;

    float *h, *h2, *bqkv;
    __half *x16, *h16, *q16, *k16, *vt16, *c16, *wt16;
    cudaGetSymbolAddress((void**)&h,    g_h);
    cudaGetSymbolAddress((void**)&h2,   g_h2);
    cudaGetSymbolAddress((void**)&bqkv, g_bqkv);
    cudaGetSymbolAddress((void**)&x16,  g_x16);
    cudaGetSymbolAddress((void**)&h16,  g_h16);
    cudaGetSymbolAddress((void**)&q16,  g_q16);
    cudaGetSymbolAddress((void**)&k16,  g_k16);
    cudaGetSymbolAddress((void**)&vt16, g_vt16);
    cudaGetSymbolAddress((void**)&c16,  g_c16);
    cudaGetSymbolAddress((void**)&wt16, g_wt16);

    cudaFuncSetAttribute(mma_gemm,
                         cudaFuncAttributeMaxDynamicSharedMemorySize, GEMM_SMEM);
    cudaFuncSetAttribute(attn_mma,
                         cudaFuncAttributeMaxDynamicSharedMemorySize, ATT_SMEM);

    const int n4 = MM * DD / 4;
    conv_half<<<(n4 + 255) / 256, 256>>>((const float4*)x, (__half2*)x16, n4);           // 0
    wtrans_all<<<dim3(16, 16, 5), 256>>>(W_w, Wq, Wk, Wv, Wo, wt16);                      // 1
    pack_bias<<<6, 256>>>(bq, bk, bv, bqkv);                                              // 2
    mma_gemm<<<dim3(4, 64), 256, GEMM_SMEM>>>(x16,                                        // 3
        wt16 + 0 * DD * DD, W_b, h, nullptr, nullptr, nullptr, 0, 0);
    ln2_kernel<<<MM, 256>>>(h, ln_g, ln_b, h16);                                          // 4
    mma_gemm<<<dim3(12, 64), 256, GEMM_SMEM>>>(h16,                                       // 5: fused QKV
        wt16 + 1 * DD * DD, bqkv, nullptr, q16, k16, vt16, 0, 1);
    attn_mma<<<dim3(NN / 64, BB * HH), 128, ATT_SMEM>>>(q16, k16, vt16,                   // 6
                                                        adj, uadj, c16);
    mma_gemm<<<dim3(4, 64), 256, GEMM_SMEM>>>(c16,                                        // 7
        wt16 + 4 * DD * DD, bo, h2, nullptr, nullptr, nullptr, 1, 0);
    gate_kernel<<<MM, 256>>>(x, h2, gw, gb, out);                                         // 8
}